// round 1
// baseline (speedup 1.0000x reference)
#include <cuda_runtime.h>
#include <cuda_bf16.h>

// Problem constants
#define B_  2
#define S_  4096
#define D_  768
#define H_  12
#define HD_ 64
#define W_  256
#define NC_ 16
#define G_  32
#define SCALE_ 0.125f

#define BHSD (B_*H_*S_*HD_)   // 6291456

// Scratch (device globals; no allocations allowed)
// bufs: 0=Q(scaled) 1=K 2=V 3=Kg 4=Vg
__device__ float d_bufs[5][BHSD];
__device__ float d_qg[B_*G_*D_];                 // (b, g, n=h*64+d)
__device__ float d_lpart[B_*H_*8*G_];            // split-K partial exp-sums
__device__ float d_accpart[B_*H_*8*G_*HD_];      // split-K partial weighted V

// ---------------------------------------------------------------------------
// Projection GEMM: out[b,h,s,d] = (hidden[m,:] @ W[:,n] + bias[n]) * scale
// M=8192, K=768, N=768.  BM=BN=128, BK=8, 256 threads, 8x8 microtile.
// ---------------------------------------------------------------------------
__global__ __launch_bounds__(256) void proj_kernel(
    const float* __restrict__ A,    // [8192,768]
    const float* __restrict__ Wt,   // [768,768]
    const float* __restrict__ bias, // [768]
    int which, float scale)
{
    __shared__ float As[8][128];
    __shared__ float Ws[8][128];
    float* __restrict__ out = d_bufs[which];

    const int tid = threadIdx.x;
    const int tx = tid & 15, ty = tid >> 4;
    const int m0 = blockIdx.y * 128, n0 = blockIdx.x * 128;

    const int arow = tid >> 1, acol = (tid & 1) * 4;
    const int wrow = tid >> 5, wcol = (tid & 31) * 4;

    float acc[8][8];
    #pragma unroll
    for (int i = 0; i < 8; i++)
        #pragma unroll
        for (int j = 0; j < 8; j++) acc[i][j] = 0.f;

    for (int k0 = 0; k0 < D_; k0 += 8) {
        float4 a4 = *(const float4*)&A[(m0 + arow) * D_ + k0 + acol];
        As[acol + 0][arow] = a4.x;
        As[acol + 1][arow] = a4.y;
        As[acol + 2][arow] = a4.z;
        As[acol + 3][arow] = a4.w;
        *(float4*)&Ws[wrow][wcol] = *(const float4*)&Wt[(k0 + wrow) * D_ + n0 + wcol];
        __syncthreads();
        #pragma unroll
        for (int kk = 0; kk < 8; kk++) {
            float af[8], bf[8];
            *(float4*)&af[0] = *(float4*)&As[kk][ty * 8];
            *(float4*)&af[4] = *(float4*)&As[kk][ty * 8 + 4];
            *(float4*)&bf[0] = *(float4*)&Ws[kk][tx * 8];
            *(float4*)&bf[4] = *(float4*)&Ws[kk][tx * 8 + 4];
            #pragma unroll
            for (int i = 0; i < 8; i++)
                #pragma unroll
                for (int j = 0; j < 8; j++)
                    acc[i][j] += af[i] * bf[j];
        }
        __syncthreads();
    }

    #pragma unroll
    for (int i = 0; i < 8; i++) {
        int m = m0 + ty * 8 + i;
        int b = m >> 12, s = m & 4095;
        #pragma unroll
        for (int j = 0; j < 8; j++) {
            int n = n0 + tx * 8 + j;
            float val = (acc[i][j] + bias[n]) * scale;
            int h = n >> 6, hd = n & 63;
            out[(((b * H_ + h) * S_) + s) * HD_ + hd] = val;
        }
    }
}

// ---------------------------------------------------------------------------
// qg projection: only first G rows per batch. grid=64 (b*32+g), 256 threads.
// qg[(b*G+g)*768 + n] = (hidden[b,g,:] @ Wqg[:,n] + bqg[n]) * SCALE
// ---------------------------------------------------------------------------
__global__ __launch_bounds__(256) void qg_proj_kernel(
    const float* __restrict__ hidden,
    const float* __restrict__ Wqg,
    const float* __restrict__ bqg)
{
    __shared__ float hrow[D_];
    const int blk = blockIdx.x;
    const int b = blk >> 5, g = blk & 31;
    const int t = threadIdx.x;
    if (t < 192)
        *(float4*)&hrow[t * 4] = *(const float4*)&hidden[(b * S_ + g) * D_ + t * 4];
    __syncthreads();
    for (int n = t; n < D_; n += 256) {
        float s0 = 0.f, s1 = 0.f, s2 = 0.f, s3 = 0.f;
        for (int k = 0; k < D_; k += 4) {
            s0 += hrow[k + 0] * Wqg[(k + 0) * D_ + n];
            s1 += hrow[k + 1] * Wqg[(k + 1) * D_ + n];
            s2 += hrow[k + 2] * Wqg[(k + 2) * D_ + n];
            s3 += hrow[k + 3] * Wqg[(k + 3) * D_ + n];
        }
        d_qg[(b * G_ + g) * D_ + n] = ((s0 + s1) + (s2 + s3) + bqg[n]) * SCALE_;
    }
}

// ---------------------------------------------------------------------------
// Band + global-key attention. grid=(nc,H,B), 256 threads (1 per query).
// softmax over 32 global keys + 768 band keys (masked). max fixed at 0 —
// scores are O(1), exp never overflows, matches shift-invariant softmax.
// ---------------------------------------------------------------------------
__global__ __launch_bounds__(256) void band_attn_kernel(float* __restrict__ out)
{
    const int c = blockIdx.x, h = blockIdx.y, b = blockIdx.z;
    const int pq = threadIdx.x;

    const float* __restrict__ Q  = d_bufs[0];
    const float* __restrict__ K  = d_bufs[1];
    const float* __restrict__ V  = d_bufs[2];

    const float* qptr = &Q[(((b * H_ + h) * S_) + c * W_ + pq) * HD_];
    float qr[64];
    #pragma unroll
    for (int i = 0; i < 16; i++)
        *(float4*)&qr[i * 4] = *(const float4*)&qptr[i * 4];

    float acc[64];
    #pragma unroll
    for (int i = 0; i < 64; i++) acc[i] = 0.f;
    float lsum = 0.f;

    __shared__ float ks[32][64];
    __shared__ float vs[32][64];

    const float* Kb = &K[((b * H_ + h) * S_) * HD_];
    const float* Vb = &V[((b * H_ + h) * S_) * HD_];

    // chunk 0: 32 global keys (unmasked). chunks 1..24: band e = (ch-1)*32 .. +31
    for (int ch = 0; ch < 25; ch++) {
        __syncthreads();
        #pragma unroll
        for (int r = 0; r < 2; r++) {
            int idx = threadIdx.x + r * 256;      // 0..511
            int key = idx >> 4;
            int c4  = (idx & 15) * 4;
            int kabs;
            if (ch == 0) kabs = key;
            else        kabs = c * W_ + ((ch - 1) * 32 + key) - W_;
            int row = min(max(kabs, 0), S_ - 1);
            *(float4*)&ks[key][c4] = *(const float4*)&Kb[row * HD_ + c4];
            *(float4*)&vs[key][c4] = *(const float4*)&Vb[row * HD_ + c4];
        }
        __syncthreads();

        for (int j = 0; j < 32; j++) {
            bool valid;
            if (ch == 0) {
                valid = true;
            } else {
                int e = (ch - 1) * 32 + j;
                int kabs = c * W_ + e - W_;
                valid = (kabs >= 0) && (kabs < S_) && (e >= pq) && (e <= pq + 2 * W_);
            }
            if (!valid) continue;

            float s0 = 0.f, s1 = 0.f, s2 = 0.f, s3 = 0.f;
            #pragma unroll
            for (int d4 = 0; d4 < 16; d4++) {
                float4 kv = *(float4*)&ks[j][d4 * 4];
                s0 += qr[d4 * 4 + 0] * kv.x;
                s1 += qr[d4 * 4 + 1] * kv.y;
                s2 += qr[d4 * 4 + 2] * kv.z;
                s3 += qr[d4 * 4 + 3] * kv.w;
            }
            float p = __expf((s0 + s1) + (s2 + s3));
            lsum += p;
            #pragma unroll
            for (int d4 = 0; d4 < 16; d4++) {
                float4 vv = *(float4*)&vs[j][d4 * 4];
                acc[d4 * 4 + 0] += p * vv.x;
                acc[d4 * 4 + 1] += p * vv.y;
                acc[d4 * 4 + 2] += p * vv.z;
                acc[d4 * 4 + 3] += p * vv.w;
            }
        }
    }

    float inv = 1.f / lsum;
    float* op = &out[(b * S_ + c * W_ + pq) * D_ + h * HD_];
    #pragma unroll
    for (int i = 0; i < 16; i++) {
        float4 o;
        o.x = acc[i * 4 + 0] * inv;
        o.y = acc[i * 4 + 1] * inv;
        o.z = acc[i * 4 + 2] * inv;
        o.w = acc[i * 4 + 3] * inv;
        *(float4*)&op[i * 4] = o;
    }
}

// ---------------------------------------------------------------------------
// Global attention, split-K over 8 partitions of 512 keys.
// grid=(8,H,B), 256 threads = 32 query-groups x 8 lanes (8 dims each).
// ---------------------------------------------------------------------------
__global__ __launch_bounds__(256) void gattn_part_kernel()
{
    const int sp = blockIdx.x, h = blockIdx.y, b = blockIdx.z;
    const int t = threadIdx.x;
    const int g = t >> 3;
    const int li = t & 7;
    const int bh = b * H_ + h;

    const float* __restrict__ Kg = d_bufs[3];
    const float* __restrict__ Vg = d_bufs[4];

    float q_r[8];
    const float* qp = &d_qg[(b * G_ + g) * D_ + h * HD_ + li * 8];
    *(float4*)&q_r[0] = *(const float4*)&qp[0];
    *(float4*)&q_r[4] = *(const float4*)&qp[4];

    float acc[8];
    #pragma unroll
    for (int i = 0; i < 8; i++) acc[i] = 0.f;
    float lsum = 0.f;

    __shared__ float ks[64][64];
    __shared__ float vs[64][64];

    const float* Kb = &Kg[(bh * S_ + sp * 512) * HD_];
    const float* Vb = &Vg[(bh * S_ + sp * 512) * HD_];

    for (int ch = 0; ch < 8; ch++) {
        __syncthreads();
        #pragma unroll
        for (int r = 0; r < 4; r++) {
            int idx = t + r * 256;        // 0..1023
            int key = idx >> 4;
            int c4  = (idx & 15) * 4;
            *(float4*)&ks[key][c4] = *(const float4*)&Kb[(ch * 64 + key) * HD_ + c4];
            *(float4*)&vs[key][c4] = *(const float4*)&Vb[(ch * 64 + key) * HD_ + c4];
        }
        __syncthreads();

        for (int j = 0; j < 64; j++) {
            float4 k0 = *(float4*)&ks[j][li * 8];
            float4 k1 = *(float4*)&ks[j][li * 8 + 4];
            float partial = q_r[0] * k0.x + q_r[1] * k0.y + q_r[2] * k0.z + q_r[3] * k0.w
                          + q_r[4] * k1.x + q_r[5] * k1.y + q_r[6] * k1.z + q_r[7] * k1.w;
            partial += __shfl_xor_sync(0xffffffffu, partial, 1);
            partial += __shfl_xor_sync(0xffffffffu, partial, 2);
            partial += __shfl_xor_sync(0xffffffffu, partial, 4);
            float p = __expf(partial);
            lsum += p;
            float4 v0 = *(float4*)&vs[j][li * 8];
            float4 v1 = *(float4*)&vs[j][li * 8 + 4];
            acc[0] += p * v0.x; acc[1] += p * v0.y; acc[2] += p * v0.z; acc[3] += p * v0.w;
            acc[4] += p * v1.x; acc[5] += p * v1.y; acc[6] += p * v1.z; acc[7] += p * v1.w;
        }
    }

    if (li == 0)
        d_lpart[(bh * 8 + sp) * G_ + g] = lsum;
    float* ap = &d_accpart[((bh * 8 + sp) * G_ + g) * HD_ + li * 8];
    float4 a0, a1;
    a0.x = acc[0]; a0.y = acc[1]; a0.z = acc[2]; a0.w = acc[3];
    a1.x = acc[4]; a1.y = acc[5]; a1.z = acc[6]; a1.w = acc[7];
    *(float4*)&ap[0] = a0;
    *(float4*)&ap[4] = a1;
}

// Combine 8 split-K partials; overwrite out rows s < G.
__global__ __launch_bounds__(64) void gattn_combine_kernel(float* __restrict__ out)
{
    const int idx = blockIdx.x;       // 0..767 = bh*32 + g
    const int bh = idx >> 5;
    const int g = idx & 31;
    const int b = bh / H_, h = bh % H_;
    const int d = threadIdx.x;
    float l = 0.f, a = 0.f;
    #pragma unroll
    for (int sp = 0; sp < 8; sp++) {
        l += d_lpart[(bh * 8 + sp) * G_ + g];
        a += d_accpart[((bh * 8 + sp) * G_ + g) * HD_ + d];
    }
    out[(b * S_ + g) * D_ + h * HD_ + d] = a / l;
}

// ---------------------------------------------------------------------------
extern "C" void kernel_launch(void* const* d_in, const int* in_sizes, int n_in,
                              void* d_out, int out_size)
{
    const float* hidden = (const float*)d_in[0];
    const float* Wq  = (const float*)d_in[1];
    const float* bq  = (const float*)d_in[2];
    const float* Wk  = (const float*)d_in[3];
    const float* bk  = (const float*)d_in[4];
    const float* Wv  = (const float*)d_in[5];
    const float* bv  = (const float*)d_in[6];
    const float* Wqg = (const float*)d_in[7];
    const float* bqg = (const float*)d_in[8];
    const float* Wkg = (const float*)d_in[9];
    const float* bkg = (const float*)d_in[10];
    const float* Wvg = (const float*)d_in[11];
    const float* bvg = (const float*)d_in[12];
    float* out = (float*)d_out;

    dim3 pgrid(D_ / 128, (B_ * S_) / 128);
    proj_kernel<<<pgrid, 256>>>(hidden, Wq,  bq,  0, SCALE_);
    proj_kernel<<<pgrid, 256>>>(hidden, Wk,  bk,  1, 1.0f);
    proj_kernel<<<pgrid, 256>>>(hidden, Wv,  bv,  2, 1.0f);
    proj_kernel<<<pgrid, 256>>>(hidden, Wkg, bkg, 3, 1.0f);
    proj_kernel<<<pgrid, 256>>>(hidden, Wvg, bvg, 4, 1.0f);
    qg_proj_kernel<<<B_ * G_, 256>>>(hidden, Wqg, bqg);

    band_attn_kernel<<<dim3(NC_, H_, B_), 256>>>(out);

    gattn_part_kernel<<<dim3(8, H_, B_), 256>>>();
    gattn_combine_kernel<<<B_ * H_ * G_, 64>>>(out);
}

// round 4
// speedup vs baseline: 1.5751x; 1.5751x over previous
#include <cuda_runtime.h>
#include <cuda_bf16.h>
#include <cstdint>

// Problem constants
#define B_  2
#define S_  4096
#define D_  768
#define H_  12
#define HD_ 64
#define W_  256
#define NC_ 16
#define G_  32
#define SCALE_ 0.125f

#define BHSD (B_*H_*S_*HD_)   // 6291456

// ---------------------------------------------------------------------------
__device__ __forceinline__ uint32_t smem_u32(const void* p) {
    uint32_t a;
    asm("{ .reg .u64 t; cvta.to.shared.u64 t, %1; cvt.u32.u64 %0, t; }" : "=r"(a) : "l"(p));
    return a;
}
#define CPA16(sa, g) asm volatile("cp.async.cg.shared.global [%0], [%1], 16;" :: "r"(sa), "l"(g))
#define CPA_COMMIT() asm volatile("cp.async.commit_group;" ::: "memory")
#define CPA_WAIT1()  asm volatile("cp.async.wait_group 1;" ::: "memory")
#define CPA_WAIT0()  asm volatile("cp.async.wait_group 0;" ::: "memory")
#define LDM4(r, addr) \
  asm volatile("ldmatrix.sync.aligned.m8n8.x4.shared.b16 {%0,%1,%2,%3}, [%4];" \
    : "=r"((r)[0]), "=r"((r)[1]), "=r"((r)[2]), "=r"((r)[3]) : "r"(addr))
#define MMA16816(d, a, b0, b1) \
  asm volatile("mma.sync.aligned.m16n8k16.row.col.f32.bf16.bf16.f32 " \
    "{%0,%1,%2,%3}, {%4,%5,%6,%7}, {%8,%9}, {%0,%1,%2,%3};" \
    : "+f"((d)[0]), "+f"((d)[1]), "+f"((d)[2]), "+f"((d)[3]) \
    : "r"((a)[0]), "r"((a)[1]), "r"((a)[2]), "r"((a)[3]), "r"(b0), "r"(b1))

// ---------------------------------------------------------------------------
// Device scratch. bufs: 0=Q(scaled) 1=K 2=V 3=Kg 4=Vg
__device__ float d_bufs[5][BHSD];
__device__ __nv_bfloat16 d_Ahi[B_*S_*D_];
__device__ __nv_bfloat16 d_Alo[B_*S_*D_];
__device__ __nv_bfloat16 d_Whi[5][D_*D_];   // transposed [n][k]
__device__ __nv_bfloat16 d_Wlo[5][D_*D_];
__device__ float d_qg[B_*G_*D_];
__device__ float d_lpart[B_*H_*8*G_];
__device__ float d_accpart[B_*H_*8*G_*HD_];

// ---------------------------------------------------------------------------
// Prepass: hidden -> bf16 hi/lo
__global__ __launch_bounds__(256) void convA_kernel(const float* __restrict__ A)
{
    int i = (blockIdx.x * 256 + threadIdx.x) * 4;
    float4 a = *(const float4*)&A[i];
    float av[4] = {a.x, a.y, a.z, a.w};
    __nv_bfloat16 h[4], l[4];
    #pragma unroll
    for (int j = 0; j < 4; j++) {
        h[j] = __float2bfloat16(av[j]);
        l[j] = __float2bfloat16(av[j] - __bfloat162float(h[j]));
    }
    *(uint2*)&d_Ahi[i] = *(uint2*)h;
    *(uint2*)&d_Alo[i] = *(uint2*)l;
}

// Prepass: W[k][n] -> Wt_hi/lo[n][k] bf16 (transpose via smem)
__global__ __launch_bounds__(256) void convW_kernel(const float* __restrict__ W, int which)
{
    __shared__ float t[32][33];
    const int n0 = blockIdx.x * 32, k0 = blockIdx.y * 32;
    const int tx = threadIdx.x, ty = threadIdx.y;   // (32, 8)
    #pragma unroll
    for (int r = 0; r < 32; r += 8)
        t[ty + r][tx] = W[(k0 + ty + r) * D_ + n0 + tx];
    __syncthreads();
    #pragma unroll
    for (int r = 0; r < 32; r += 8) {
        float v = t[tx][ty + r];
        __nv_bfloat16 hh = __float2bfloat16(v);
        __nv_bfloat16 ll = __float2bfloat16(v - __bfloat162float(hh));
        d_Whi[which][(n0 + ty + r) * D_ + k0 + tx] = hh;
        d_Wlo[which][(n0 + ty + r) * D_ + k0 + tx] = ll;
    }
}

// ---------------------------------------------------------------------------
// Fused projection GEMMs on mma.sync (HMMA bf16, fp32 acc), hi/lo 3-term.
// grid = (N/128=6, M/128=64, 5). 256 threads, warp grid 4(m) x 2(n),
// warp tile 32x64. K-chunk 32, cp.async double buffer.
// smem tile: 128 rows x 80B (32 bf16 padded) = 10240B; 4 tiles x 2 bufs.
// ---------------------------------------------------------------------------
#define TILE_B 10240
#define GEMM_DYN (2*4*TILE_B)   // 81920

__global__ __launch_bounds__(256, 2) void gemm_kernel(
    const float* __restrict__ bq,  const float* __restrict__ bk,
    const float* __restrict__ bv,  const float* __restrict__ bkg,
    const float* __restrict__ bvg)
{
    extern __shared__ char smraw[];
    const uint32_t sb = smem_u32(smraw);
    const int tid = threadIdx.x, wid = tid >> 5, lane = tid & 31;
    const int mw = wid & 3, nw = wid >> 2;
    const int n0 = blockIdx.x * 128, m0 = blockIdx.y * 128;
    const int which = blockIdx.z;
    const float* bias = (which == 0) ? bq : (which == 1) ? bk : (which == 2) ? bv
                       : (which == 3) ? bkg : bvg;
    const float scale = (which == 0) ? SCALE_ : 1.0f;
    float* __restrict__ out = d_bufs[which];
    const __nv_bfloat16* __restrict__ Ahi = d_Ahi;
    const __nv_bfloat16* __restrict__ Alo = d_Alo;
    const __nv_bfloat16* __restrict__ Whi = d_Whi[which];
    const __nv_bfloat16* __restrict__ Wlo = d_Wlo[which];

    float acc[2][8][4];
    #pragma unroll
    for (int mt = 0; mt < 2; mt++)
        #pragma unroll
        for (int nt = 0; nt < 8; nt++)
            #pragma unroll
            for (int r = 0; r < 4; r++) acc[mt][nt][r] = 0.f;

    // per-thread load slots: idx = tid + j*256 -> row = idx>>2, ch = idx&3
    const int lrow = tid >> 2, lch = tid & 3;
    const int lrow2 = (tid + 256) >> 2;   // lch identical for j=1

    auto load_chunk = [&](int buf, int k0) {
        uint32_t base = sb + buf * 4 * TILE_B;
        const __nv_bfloat16* gA0 = &Ahi[(m0 + lrow) * D_ + k0 + lch * 8];
        const __nv_bfloat16* gA1 = &Ahi[(m0 + lrow2) * D_ + k0 + lch * 8];
        CPA16(base + lrow * 80 + lch * 16, gA0);
        CPA16(base + lrow2 * 80 + lch * 16, gA1);
        base += TILE_B;
        const __nv_bfloat16* gL0 = &Alo[(m0 + lrow) * D_ + k0 + lch * 8];
        const __nv_bfloat16* gL1 = &Alo[(m0 + lrow2) * D_ + k0 + lch * 8];
        CPA16(base + lrow * 80 + lch * 16, gL0);
        CPA16(base + lrow2 * 80 + lch * 16, gL1);
        base += TILE_B;
        const __nv_bfloat16* gB0 = &Whi[(n0 + lrow) * D_ + k0 + lch * 8];
        const __nv_bfloat16* gB1 = &Whi[(n0 + lrow2) * D_ + k0 + lch * 8];
        CPA16(base + lrow * 80 + lch * 16, gB0);
        CPA16(base + lrow2 * 80 + lch * 16, gB1);
        base += TILE_B;
        const __nv_bfloat16* gC0 = &Wlo[(n0 + lrow) * D_ + k0 + lch * 8];
        const __nv_bfloat16* gC1 = &Wlo[(n0 + lrow2) * D_ + k0 + lch * 8];
        CPA16(base + lrow * 80 + lch * 16, gC0);
        CPA16(base + lrow2 * 80 + lch * 16, gC1);
        CPA_COMMIT();
    };

    load_chunk(0, 0);

    #pragma unroll 1
    for (int c = 0; c < 24; c++) {
        if (c + 1 < 24) { load_chunk((c + 1) & 1, (c + 1) * 32); CPA_WAIT1(); }
        else CPA_WAIT0();
        __syncthreads();

        const uint32_t aBase  = sb + ((c & 1) * 4 + 0) * TILE_B;
        const uint32_t alBase = sb + ((c & 1) * 4 + 1) * TILE_B;
        const uint32_t bBase  = sb + ((c & 1) * 4 + 2) * TILE_B;
        const uint32_t blBase = sb + ((c & 1) * 4 + 3) * TILE_B;

        #pragma unroll
        for (int ks = 0; ks < 2; ks++) {
            uint32_t ahi[2][4], alo[2][4];
            const uint32_t acoff = ks * 32 + ((lane >> 4) & 1) * 16;
            #pragma unroll
            for (int mt = 0; mt < 2; mt++) {
                int row = mw * 32 + mt * 16 + (lane & 15);
                LDM4(ahi[mt], aBase + row * 80 + acoff);
                LDM4(alo[mt], alBase + row * 80 + acoff);
            }
            const uint32_t bcoff = ks * 32 + ((lane >> 3) & 1) * 16;
            #pragma unroll
            for (int nh = 0; nh < 2; nh++) {
                uint32_t bhi[2][4], blo[2][4];
                #pragma unroll
                for (int q = 0; q < 2; q++) {
                    int row = nw * 64 + nh * 32 + q * 16 + (lane & 7) + ((lane >> 4) << 3);
                    LDM4(bhi[q], bBase + row * 80 + bcoff);
                    LDM4(blo[q], blBase + row * 80 + bcoff);
                }
                #pragma unroll
                for (int mt = 0; mt < 2; mt++)
                    #pragma unroll
                    for (int q = 0; q < 2; q++)
                        #pragma unroll
                        for (int p = 0; p < 2; p++) {
                            int nt = nh * 4 + q * 2 + p;
                            MMA16816(acc[mt][nt], ahi[mt], bhi[q][p*2], bhi[q][p*2+1]);
                            MMA16816(acc[mt][nt], ahi[mt], blo[q][p*2], blo[q][p*2+1]);
                            MMA16816(acc[mt][nt], alo[mt], bhi[q][p*2], bhi[q][p*2+1]);
                        }
            }
        }
        __syncthreads();
    }

    // Epilogue: direct stores (b,h,s,hd layout), bias + scale
    const int g = lane >> 2, tg = lane & 3;
    #pragma unroll
    for (int mt = 0; mt < 2; mt++)
        #pragma unroll
        for (int half = 0; half < 2; half++) {
            int m = m0 + mw * 32 + mt * 16 + g + half * 8;
            int b = m >> 12, s = m & 4095;
            #pragma unroll
            for (int nt = 0; nt < 8; nt++) {
                int n = n0 + nw * 64 + nt * 8 + tg * 2;
                int h = n >> 6, hd = n & 63;
                float2 o;
                o.x = (acc[mt][nt][half * 2 + 0] + bias[n]) * scale;
                o.y = (acc[mt][nt][half * 2 + 1] + bias[n + 1]) * scale;
                *(float2*)&out[(((b * H_ + h) * S_) + s) * HD_ + hd] = o;
            }
        }
}

// ---------------------------------------------------------------------------
// qg projection: only first G rows per batch.
// ---------------------------------------------------------------------------
__global__ __launch_bounds__(256) void qg_proj_kernel(
    const float* __restrict__ hidden,
    const float* __restrict__ Wqg,
    const float* __restrict__ bqg)
{
    __shared__ float hrow[D_];
    const int blk = blockIdx.x;
    const int b = blk >> 5, g = blk & 31;
    const int t = threadIdx.x;
    if (t < 192)
        *(float4*)&hrow[t * 4] = *(const float4*)&hidden[(b * S_ + g) * D_ + t * 4];
    __syncthreads();
    for (int n = t; n < D_; n += 256) {
        float s0 = 0.f, s1 = 0.f, s2 = 0.f, s3 = 0.f;
        for (int k = 0; k < D_; k += 4) {
            s0 += hrow[k + 0] * Wqg[(k + 0) * D_ + n];
            s1 += hrow[k + 1] * Wqg[(k + 1) * D_ + n];
            s2 += hrow[k + 2] * Wqg[(k + 2) * D_ + n];
            s3 += hrow[k + 3] * Wqg[(k + 3) * D_ + n];
        }
        d_qg[(b * G_ + g) * D_ + n] = ((s0 + s1) + (s2 + s3) + bqg[n]) * SCALE_;
    }
}

// ---------------------------------------------------------------------------
// Band + global-key attention, lane-pair split over HD.
// grid=(nc*2, H, B), 256 threads: query pq = qh*128 + tid/2, half = tid&1.
// ---------------------------------------------------------------------------
__global__ __launch_bounds__(256) void band_attn_kernel(float* __restrict__ out)
{
    const int c = blockIdx.x >> 1, qh = blockIdx.x & 1;
    const int h = blockIdx.y, b = blockIdx.z;
    const int pq0 = qh * 128;
    const int pq = pq0 + (threadIdx.x >> 1);
    const int half = threadIdx.x & 1;

    const float* __restrict__ Q = d_bufs[0];
    const float* __restrict__ K = d_bufs[1];
    const float* __restrict__ V = d_bufs[2];

    const float* qptr = &Q[(((b * H_ + h) * S_) + c * W_ + pq) * HD_ + half * 32];
    float qr[32];
    #pragma unroll
    for (int i = 0; i < 8; i++)
        *(float4*)&qr[i * 4] = *(const float4*)&qptr[i * 4];

    float acc[32];
    #pragma unroll
    for (int i = 0; i < 32; i++) acc[i] = 0.f;
    float lsum = 0.f;

    __shared__ float ks[32][64];
    __shared__ float vs[32][64];

    const float* Kb = &K[((b * H_ + h) * S_) * HD_];
    const float* Vb = &V[((b * H_ + h) * S_) * HD_];

    for (int ch = 0; ch < 25; ch++) {
        if (ch > 0) {   // block-uniform chunk skip
            int e_lo = (ch - 1) * 32;
            int kabs_lo = c * W_ + e_lo - W_;
            if (kabs_lo + 31 < 0 || kabs_lo >= S_) continue;
            if (e_lo + 31 < pq0 || e_lo > pq0 + 127 + 2 * W_) continue;
        }
        __syncthreads();
        #pragma unroll
        for (int r = 0; r < 2; r++) {
            int idx = threadIdx.x + r * 256;
            int key = idx >> 4;
            int c4  = (idx & 15) * 4;
            int kabs;
            if (ch == 0) kabs = key;
            else         kabs = c * W_ + ((ch - 1) * 32 + key) - W_;
            int row = min(max(kabs, 0), S_ - 1);
            *(float4*)&ks[key][c4] = *(const float4*)&Kb[row * HD_ + c4];
            *(float4*)&vs[key][c4] = *(const float4*)&Vb[row * HD_ + c4];
        }
        __syncthreads();

        for (int j = 0; j < 32; j++) {
            bool valid;
            if (ch == 0) {
                valid = true;
            } else {
                int e = (ch - 1) * 32 + j;
                int kabs = c * W_ + e - W_;
                valid = (kabs >= 0) && (kabs < S_) && (e >= pq) && (e <= pq + 2 * W_);
            }
            float s0 = 0.f, s1 = 0.f, s2 = 0.f, s3 = 0.f;
            #pragma unroll
            for (int d4 = 0; d4 < 8; d4++) {
                float4 kv = *(float4*)&ks[j][half * 32 + d4 * 4];
                s0 += qr[d4 * 4 + 0] * kv.x;
                s1 += qr[d4 * 4 + 1] * kv.y;
                s2 += qr[d4 * 4 + 2] * kv.z;
                s3 += qr[d4 * 4 + 3] * kv.w;
            }
            float part = (s0 + s1) + (s2 + s3);
            part += __shfl_xor_sync(0xffffffffu, part, 1);
            if (valid) {
                float p = __expf(part);
                lsum += p;
                #pragma unroll
                for (int d4 = 0; d4 < 8; d4++) {
                    float4 vv = *(float4*)&vs[j][half * 32 + d4 * 4];
                    acc[d4 * 4 + 0] += p * vv.x;
                    acc[d4 * 4 + 1] += p * vv.y;
                    acc[d4 * 4 + 2] += p * vv.z;
                    acc[d4 * 4 + 3] += p * vv.w;
                }
            }
        }
    }

    float inv = 1.f / lsum;
    float* op = &out[(b * S_ + c * W_ + pq) * D_ + h * HD_ + half * 32];
    #pragma unroll
    for (int i = 0; i < 8; i++) {
        float4 o;
        o.x = acc[i * 4 + 0] * inv;
        o.y = acc[i * 4 + 1] * inv;
        o.z = acc[i * 4 + 2] * inv;
        o.w = acc[i * 4 + 3] * inv;
        *(float4*)&op[i * 4] = o;
    }
}

// ---------------------------------------------------------------------------
// Global attention, split-K over 8 partitions of 512 keys.
// ---------------------------------------------------------------------------
__global__ __launch_bounds__(256) void gattn_part_kernel()
{
    const int sp = blockIdx.x, h = blockIdx.y, b = blockIdx.z;
    const int t = threadIdx.x;
    const int g = t >> 3;
    const int li = t & 7;
    const int bh = b * H_ + h;

    const float* __restrict__ Kg = d_bufs[3];
    const float* __restrict__ Vg = d_bufs[4];

    float q_r[8];
    const float* qp = &d_qg[(b * G_ + g) * D_ + h * HD_ + li * 8];
    *(float4*)&q_r[0] = *(const float4*)&qp[0];
    *(float4*)&q_r[4] = *(const float4*)&qp[4];

    float acc[8];
    #pragma unroll
    for (int i = 0; i < 8; i++) acc[i] = 0.f;
    float lsum = 0.f;

    __shared__ float ks[64][64];
    __shared__ float vs[64][64];

    const float* Kb = &Kg[(bh * S_ + sp * 512) * HD_];
    const float* Vb = &Vg[(bh * S_ + sp * 512) * HD_];

    for (int ch = 0; ch < 8; ch++) {
        __syncthreads();
        #pragma unroll
        for (int r = 0; r < 4; r++) {
            int idx = t + r * 256;
            int key = idx >> 4;
            int c4  = (idx & 15) * 4;
            *(float4*)&ks[key][c4] = *(const float4*)&Kb[(ch * 64 + key) * HD_ + c4];
            *(float4*)&vs[key][c4] = *(const float4*)&Vb[(ch * 64 + key) * HD_ + c4];
        }
        __syncthreads();

        for (int j = 0; j < 64; j++) {
            float4 k0 = *(float4*)&ks[j][li * 8];
            float4 k1 = *(float4*)&ks[j][li * 8 + 4];
            float partial = q_r[0] * k0.x + q_r[1] * k0.y + q_r[2] * k0.z + q_r[3] * k0.w
                          + q_r[4] * k1.x + q_r[5] * k1.y + q_r[6] * k1.z + q_r[7] * k1.w;
            partial += __shfl_xor_sync(0xffffffffu, partial, 1);
            partial += __shfl_xor_sync(0xffffffffu, partial, 2);
            partial += __shfl_xor_sync(0xffffffffu, partial, 4);
            float p = __expf(partial);
            lsum += p;
            float4 v0 = *(float4*)&vs[j][li * 8];
            float4 v1 = *(float4*)&vs[j][li * 8 + 4];
            acc[0] += p * v0.x; acc[1] += p * v0.y; acc[2] += p * v0.z; acc[3] += p * v0.w;
            acc[4] += p * v1.x; acc[5] += p * v1.y; acc[6] += p * v1.z; acc[7] += p * v1.w;
        }
    }

    if (li == 0)
        d_lpart[(bh * 8 + sp) * G_ + g] = lsum;
    float* ap = &d_accpart[((bh * 8 + sp) * G_ + g) * HD_ + li * 8];
    float4 a0, a1;
    a0.x = acc[0]; a0.y = acc[1]; a0.z = acc[2]; a0.w = acc[3];
    a1.x = acc[4]; a1.y = acc[5]; a1.z = acc[6]; a1.w = acc[7];
    *(float4*)&ap[0] = a0;
    *(float4*)&ap[4] = a1;
}

__global__ __launch_bounds__(64) void gattn_combine_kernel(float* __restrict__ out)
{
    const int idx = blockIdx.x;
    const int bh = idx >> 5;
    const int g = idx & 31;
    const int b = bh / H_, h = bh % H_;
    const int d = threadIdx.x;
    float l = 0.f, a = 0.f;
    #pragma unroll
    for (int sp = 0; sp < 8; sp++) {
        l += d_lpart[(bh * 8 + sp) * G_ + g];
        a += d_accpart[((bh * 8 + sp) * G_ + g) * HD_ + d];
    }
    out[(b * S_ + g) * D_ + h * HD_ + d] = a / l;
}

// ---------------------------------------------------------------------------
extern "C" void kernel_launch(void* const* d_in, const int* in_sizes, int n_in,
                              void* d_out, int out_size)
{
    const float* hidden = (const float*)d_in[0];
    const float* Wq  = (const float*)d_in[1];
    const float* bq  = (const float*)d_in[2];
    const float* Wk  = (const float*)d_in[3];
    const float* bk  = (const float*)d_in[4];
    const float* Wv  = (const float*)d_in[5];
    const float* bv  = (const float*)d_in[6];
    const float* Wqg = (const float*)d_in[7];
    const float* bqg = (const float*)d_in[8];
    const float* Wkg = (const float*)d_in[9];
    const float* bkg = (const float*)d_in[10];
    const float* Wvg = (const float*)d_in[11];
    const float* bvg = (const float*)d_in[12];
    float* out = (float*)d_out;

    static int configured = 0;
    if (!configured) {
        cudaFuncSetAttribute(gemm_kernel, cudaFuncAttributeMaxDynamicSharedMemorySize, GEMM_DYN);
        configured = 1;
    }

    // Prepass: bf16 hi/lo split
    convA_kernel<<<(B_*S_*D_)/1024, 256>>>(hidden);
    dim3 wgrid(24, 24);
    convW_kernel<<<wgrid, dim3(32, 8)>>>(Wq,  0);
    convW_kernel<<<wgrid, dim3(32, 8)>>>(Wk,  1);
    convW_kernel<<<wgrid, dim3(32, 8)>>>(Wv,  2);
    convW_kernel<<<wgrid, dim3(32, 8)>>>(Wkg, 3);
    convW_kernel<<<wgrid, dim3(32, 8)>>>(Wvg, 4);

    // All 5 projections in one fused launch (grid.z = which)
    dim3 ggrid(D_ / 128, (B_ * S_) / 128, 5);
    gemm_kernel<<<ggrid, 256, GEMM_DYN>>>(bq, bk, bv, bkg, bvg);

    qg_proj_kernel<<<B_ * G_, 256>>>(hidden, Wqg, bqg);

    band_attn_kernel<<<dim3(NC_ * 2, H_, B_), 256>>>(out);

    gattn_part_kernel<<<dim3(8, H_, B_), 256>>>();
    gattn_combine_kernel<<<B_ * H_ * G_, 64>>>(out);
}

// round 5
// speedup vs baseline: 1.6106x; 1.0225x over previous
#include <cuda_runtime.h>
#include <cuda_bf16.h>
#include <cstdint>

// Problem constants
#define B_  2
#define S_  4096
#define D_  768
#define H_  12
#define HD_ 64
#define W_  256
#define NC_ 16
#define G_  32
#define SCALE_ 0.125f

#define BHSD (B_*H_*S_*HD_)   // 6291456

typedef unsigned long long ull;

// ---------------------------------------------------------------------------
__device__ __forceinline__ uint32_t smem_u32(const void* p) {
    uint32_t a;
    asm("{ .reg .u64 t; cvta.to.shared.u64 t, %1; cvt.u32.u64 %0, t; }" : "=r"(a) : "l"(p));
    return a;
}
#define CPA16(sa, g) asm volatile("cp.async.cg.shared.global [%0], [%1], 16;" :: "r"(sa), "l"(g))
#define CPA_COMMIT() asm volatile("cp.async.commit_group;" ::: "memory")
#define CPA_WAIT1()  asm volatile("cp.async.wait_group 1;" ::: "memory")
#define CPA_WAIT0()  asm volatile("cp.async.wait_group 0;" ::: "memory")
#define LDM4(r, addr) \
  asm volatile("ldmatrix.sync.aligned.m8n8.x4.shared.b16 {%0,%1,%2,%3}, [%4];" \
    : "=r"((r)[0]), "=r"((r)[1]), "=r"((r)[2]), "=r"((r)[3]) : "r"(addr))
#define MMA16816(d, a, b0, b1) \
  asm volatile("mma.sync.aligned.m16n8k16.row.col.f32.bf16.bf16.f32 " \
    "{%0,%1,%2,%3}, {%4,%5,%6,%7}, {%8,%9}, {%0,%1,%2,%3};" \
    : "+f"((d)[0]), "+f"((d)[1]), "+f"((d)[2]), "+f"((d)[3]) \
    : "r"((a)[0]), "r"((a)[1]), "r"((a)[2]), "r"((a)[3]), "r"(b0), "r"(b1))

// Packed f32x2 (sm_100+ base-target PTX)
#define FMA2(d, a, b) \
  asm("fma.rn.f32x2 %0, %1, %2, %3;" : "=l"(d) : "l"(a), "l"(b), "l"(d))
#define PACK2(d, f) \
  asm("mov.b64 %0, {%1, %1};" : "=l"(d) : "f"(f))
#define UNPACK2(lo, hi, v) \
  asm("mov.b64 {%0, %1}, %2;" : "=f"(lo), "=f"(hi) : "l"(v))

// ---------------------------------------------------------------------------
// Device scratch. bufs: 0=Q(scaled) 1=K 2=V 3=Kg 4=Vg
__device__ float d_bufs[5][BHSD];
__device__ __nv_bfloat16 d_Ahi[B_*S_*D_];
__device__ __nv_bfloat16 d_Alo[B_*S_*D_];
__device__ __nv_bfloat16 d_Whi[5][D_*D_];   // transposed [n][k]
__device__ __nv_bfloat16 d_Wlo[5][D_*D_];
__device__ float d_qg[B_*G_*D_];
__device__ float d_lpart[B_*H_*8*G_];
__device__ float d_accpart[B_*H_*8*G_*HD_];

// ---------------------------------------------------------------------------
// Prepass: hidden -> bf16 hi/lo
__global__ __launch_bounds__(256) void convA_kernel(const float* __restrict__ A)
{
    int i = (blockIdx.x * 256 + threadIdx.x) * 4;
    float4 a = *(const float4*)&A[i];
    float av[4] = {a.x, a.y, a.z, a.w};
    __nv_bfloat16 h[4], l[4];
    #pragma unroll
    for (int j = 0; j < 4; j++) {
        h[j] = __float2bfloat16(av[j]);
        l[j] = __float2bfloat16(av[j] - __bfloat162float(h[j]));
    }
    *(uint2*)&d_Ahi[i] = *(uint2*)h;
    *(uint2*)&d_Alo[i] = *(uint2*)l;
}

// Prepass (fused over 5 weights): W[k][n] -> Wt_hi/lo[n][k] bf16
__global__ __launch_bounds__(256) void convW_kernel(
    const float* __restrict__ W0, const float* __restrict__ W1,
    const float* __restrict__ W2, const float* __restrict__ W3,
    const float* __restrict__ W4)
{
    __shared__ float t[32][33];
    const int which = blockIdx.z;
    const float* __restrict__ W = (which == 0) ? W0 : (which == 1) ? W1
                                : (which == 2) ? W2 : (which == 3) ? W3 : W4;
    const int n0 = blockIdx.x * 32, k0 = blockIdx.y * 32;
    const int tx = threadIdx.x, ty = threadIdx.y;   // (32, 8)
    #pragma unroll
    for (int r = 0; r < 32; r += 8)
        t[ty + r][tx] = W[(k0 + ty + r) * D_ + n0 + tx];
    __syncthreads();
    #pragma unroll
    for (int r = 0; r < 32; r += 8) {
        float v = t[tx][ty + r];
        __nv_bfloat16 hh = __float2bfloat16(v);
        __nv_bfloat16 ll = __float2bfloat16(v - __bfloat162float(hh));
        d_Whi[which][(n0 + ty + r) * D_ + k0 + tx] = hh;
        d_Wlo[which][(n0 + ty + r) * D_ + k0 + tx] = ll;
    }
}

// ---------------------------------------------------------------------------
// Fused projection GEMMs on mma.sync (HMMA bf16, fp32 acc), hi/lo 3-term.
// ---------------------------------------------------------------------------
#define TILE_B 10240
#define GEMM_DYN (2*4*TILE_B)   // 81920

__global__ __launch_bounds__(256, 2) void gemm_kernel(
    const float* __restrict__ bq,  const float* __restrict__ bk,
    const float* __restrict__ bv,  const float* __restrict__ bkg,
    const float* __restrict__ bvg)
{
    extern __shared__ char smraw[];
    const uint32_t sb = smem_u32(smraw);
    const int tid = threadIdx.x, wid = tid >> 5, lane = tid & 31;
    const int mw = wid & 3, nw = wid >> 2;
    const int n0 = blockIdx.x * 128, m0 = blockIdx.y * 128;
    const int which = blockIdx.z;
    const float* bias = (which == 0) ? bq : (which == 1) ? bk : (which == 2) ? bv
                       : (which == 3) ? bkg : bvg;
    const float scale = (which == 0) ? SCALE_ : 1.0f;
    float* __restrict__ out = d_bufs[which];
    const __nv_bfloat16* __restrict__ Ahi = d_Ahi;
    const __nv_bfloat16* __restrict__ Alo = d_Alo;
    const __nv_bfloat16* __restrict__ Whi = d_Whi[which];
    const __nv_bfloat16* __restrict__ Wlo = d_Wlo[which];

    float acc[2][8][4];
    #pragma unroll
    for (int mt = 0; mt < 2; mt++)
        #pragma unroll
        for (int nt = 0; nt < 8; nt++)
            #pragma unroll
            for (int r = 0; r < 4; r++) acc[mt][nt][r] = 0.f;

    const int lrow = tid >> 2, lch = tid & 3;
    const int lrow2 = (tid + 256) >> 2;

    auto load_chunk = [&](int buf, int k0) {
        uint32_t base = sb + buf * 4 * TILE_B;
        CPA16(base + lrow * 80 + lch * 16, &Ahi[(m0 + lrow) * D_ + k0 + lch * 8]);
        CPA16(base + lrow2 * 80 + lch * 16, &Ahi[(m0 + lrow2) * D_ + k0 + lch * 8]);
        base += TILE_B;
        CPA16(base + lrow * 80 + lch * 16, &Alo[(m0 + lrow) * D_ + k0 + lch * 8]);
        CPA16(base + lrow2 * 80 + lch * 16, &Alo[(m0 + lrow2) * D_ + k0 + lch * 8]);
        base += TILE_B;
        CPA16(base + lrow * 80 + lch * 16, &Whi[(n0 + lrow) * D_ + k0 + lch * 8]);
        CPA16(base + lrow2 * 80 + lch * 16, &Whi[(n0 + lrow2) * D_ + k0 + lch * 8]);
        base += TILE_B;
        CPA16(base + lrow * 80 + lch * 16, &Wlo[(n0 + lrow) * D_ + k0 + lch * 8]);
        CPA16(base + lrow2 * 80 + lch * 16, &Wlo[(n0 + lrow2) * D_ + k0 + lch * 8]);
        CPA_COMMIT();
    };

    load_chunk(0, 0);

    #pragma unroll 1
    for (int c = 0; c < 24; c++) {
        if (c + 1 < 24) { load_chunk((c + 1) & 1, (c + 1) * 32); CPA_WAIT1(); }
        else CPA_WAIT0();
        __syncthreads();

        const uint32_t aBase  = sb + ((c & 1) * 4 + 0) * TILE_B;
        const uint32_t alBase = sb + ((c & 1) * 4 + 1) * TILE_B;
        const uint32_t bBase  = sb + ((c & 1) * 4 + 2) * TILE_B;
        const uint32_t blBase = sb + ((c & 1) * 4 + 3) * TILE_B;

        #pragma unroll
        for (int ks = 0; ks < 2; ks++) {
            uint32_t ahi[2][4], alo[2][4];
            const uint32_t acoff = ks * 32 + ((lane >> 4) & 1) * 16;
            #pragma unroll
            for (int mt = 0; mt < 2; mt++) {
                int row = mw * 32 + mt * 16 + (lane & 15);
                LDM4(ahi[mt], aBase + row * 80 + acoff);
                LDM4(alo[mt], alBase + row * 80 + acoff);
            }
            const uint32_t bcoff = ks * 32 + ((lane >> 3) & 1) * 16;
            #pragma unroll
            for (int nh = 0; nh < 2; nh++) {
                uint32_t bhi[2][4], blo[2][4];
                #pragma unroll
                for (int q = 0; q < 2; q++) {
                    int row = nw * 64 + nh * 32 + q * 16 + (lane & 7) + ((lane >> 4) << 3);
                    LDM4(bhi[q], bBase + row * 80 + bcoff);
                    LDM4(blo[q], blBase + row * 80 + bcoff);
                }
                #pragma unroll
                for (int mt = 0; mt < 2; mt++)
                    #pragma unroll
                    for (int q = 0; q < 2; q++)
                        #pragma unroll
                        for (int p = 0; p < 2; p++) {
                            int nt = nh * 4 + q * 2 + p;
                            MMA16816(acc[mt][nt], ahi[mt], bhi[q][p*2], bhi[q][p*2+1]);
                            MMA16816(acc[mt][nt], ahi[mt], blo[q][p*2], blo[q][p*2+1]);
                            MMA16816(acc[mt][nt], alo[mt], bhi[q][p*2], bhi[q][p*2+1]);
                        }
            }
        }
        __syncthreads();
    }

    const int g = lane >> 2, tg = lane & 3;
    #pragma unroll
    for (int mt = 0; mt < 2; mt++)
        #pragma unroll
        for (int half = 0; half < 2; half++) {
            int m = m0 + mw * 32 + mt * 16 + g + half * 8;
            int b = m >> 12, s = m & 4095;
            #pragma unroll
            for (int nt = 0; nt < 8; nt++) {
                int n = n0 + nw * 64 + nt * 8 + tg * 2;
                int h = n >> 6, hd = n & 63;
                float2 o;
                o.x = (acc[mt][nt][half * 2 + 0] + bias[n]) * scale;
                o.y = (acc[mt][nt][half * 2 + 1] + bias[n + 1]) * scale;
                *(float2*)&out[(((b * H_ + h) * S_) + s) * HD_ + hd] = o;
            }
        }
}

// ---------------------------------------------------------------------------
// qg projection: only first G rows per batch.
// ---------------------------------------------------------------------------
__global__ __launch_bounds__(256) void qg_proj_kernel(
    const float* __restrict__ hidden,
    const float* __restrict__ Wqg,
    const float* __restrict__ bqg)
{
    __shared__ float hrow[D_];
    const int blk = blockIdx.x;
    const int b = blk >> 5, g = blk & 31;
    const int t = threadIdx.x;
    if (t < 192)
        *(float4*)&hrow[t * 4] = *(const float4*)&hidden[(b * S_ + g) * D_ + t * 4];
    __syncthreads();
    for (int n = t; n < D_; n += 256) {
        float s0 = 0.f, s1 = 0.f, s2 = 0.f, s3 = 0.f;
        for (int k = 0; k < D_; k += 4) {
            s0 += hrow[k + 0] * Wqg[(k + 0) * D_ + n];
            s1 += hrow[k + 1] * Wqg[(k + 1) * D_ + n];
            s2 += hrow[k + 2] * Wqg[(k + 2) * D_ + n];
            s3 += hrow[k + 3] * Wqg[(k + 3) * D_ + n];
        }
        d_qg[(b * G_ + g) * D_ + n] = ((s0 + s1) + (s2 + s3) + bqg[n]) * SCALE_;
    }
}

// ---------------------------------------------------------------------------
// Band + global-key attention, lane-pair split over HD, f32x2 math.
// grid=(nc*2, H, B), 256 threads: query pq = qh*128 + tid/2, half = tid&1.
// ---------------------------------------------------------------------------
__global__ __launch_bounds__(256) void band_attn_kernel(float* __restrict__ out)
{
    const int c = blockIdx.x >> 1, qh = blockIdx.x & 1;
    const int h = blockIdx.y, b = blockIdx.z;
    const int pq0 = qh * 128;
    const int pq = pq0 + (threadIdx.x >> 1);
    const int half = threadIdx.x & 1;

    const float* __restrict__ Q = d_bufs[0];
    const float* __restrict__ K = d_bufs[1];
    const float* __restrict__ V = d_bufs[2];

    // q as 16 packed f32x2
    ull q2[16];
    {
        const ulonglong2* qp = (const ulonglong2*)
            &Q[(((b * H_ + h) * S_) + c * W_ + pq) * HD_ + half * 32];
        #pragma unroll
        for (int i = 0; i < 8; i++) {
            ulonglong2 t = qp[i];
            q2[2 * i] = t.x; q2[2 * i + 1] = t.y;
        }
    }

    ull vacc[16];
    #pragma unroll
    for (int i = 0; i < 16; i++) vacc[i] = 0ull;
    float lsum = 0.f;

    __shared__ float ks[32][64];
    __shared__ float vs[32][64];

    const float* Kb = &K[((b * H_ + h) * S_) * HD_];
    const float* Vb = &V[((b * H_ + h) * S_) * HD_];

    for (int ch = 0; ch < 25; ch++) {
        if (ch > 0) {   // block-uniform chunk skip
            int e_lo = (ch - 1) * 32;
            int kabs_lo = c * W_ + e_lo - W_;
            if (kabs_lo + 31 < 0 || kabs_lo >= S_) continue;
            if (e_lo + 31 < pq0 || e_lo > pq0 + 127 + 2 * W_) continue;
        }
        __syncthreads();
        #pragma unroll
        for (int r = 0; r < 2; r++) {
            int idx = threadIdx.x + r * 256;
            int key = idx >> 4;
            int c4  = (idx & 15) * 4;
            int kabs;
            if (ch == 0) kabs = key;
            else         kabs = c * W_ + ((ch - 1) * 32 + key) - W_;
            int row = min(max(kabs, 0), S_ - 1);
            *(float4*)&ks[key][c4] = *(const float4*)&Kb[row * HD_ + c4];
            *(float4*)&vs[key][c4] = *(const float4*)&Vb[row * HD_ + c4];
        }
        __syncthreads();

        // per-thread valid j range for this chunk
        int jlo, jhi;
        if (ch == 0) { jlo = 0; jhi = 31; }
        else {
            int e_base = (ch - 1) * 32;
            jlo = max(0,  max(W_ - c * W_ - e_base, pq - e_base));
            jhi = min(31, min(S_ + W_ - c * W_ - e_base - 1, pq + 2 * W_ - e_base));
        }

        for (int j = 0; j < 32; j++) {
            const ulonglong2* kp = (const ulonglong2*)&ks[j][half * 32];
            ull d2a = 0ull, d2b = 0ull, d2c = 0ull, d2d = 0ull;
            #pragma unroll
            for (int i = 0; i < 4; i++) {
                ulonglong2 kk0 = kp[2 * i];
                ulonglong2 kk1 = kp[2 * i + 1];
                FMA2(d2a, q2[4 * i + 0], kk0.x);
                FMA2(d2b, q2[4 * i + 1], kk0.y);
                FMA2(d2c, q2[4 * i + 2], kk1.x);
                FMA2(d2d, q2[4 * i + 3], kk1.y);
            }
            float xa, ya, xb, yb, xc, yc, xd, yd;
            UNPACK2(xa, ya, d2a); UNPACK2(xb, yb, d2b);
            UNPACK2(xc, yc, d2c); UNPACK2(xd, yd, d2d);
            float part = ((xa + ya) + (xb + yb)) + ((xc + yc) + (xd + yd));
            part += __shfl_xor_sync(0xffffffffu, part, 1);
            if (j >= jlo && j <= jhi) {
                float p = __expf(part);
                lsum += p;
                ull p2; PACK2(p2, p);
                const ulonglong2* vp = (const ulonglong2*)&vs[j][half * 32];
                #pragma unroll
                for (int i = 0; i < 8; i++) {
                    ulonglong2 vv = vp[i];
                    FMA2(vacc[2 * i + 0], p2, vv.x);
                    FMA2(vacc[2 * i + 1], p2, vv.y);
                }
            }
        }
    }

    float inv = 1.f / lsum;
    float* op = &out[(b * S_ + c * W_ + pq) * D_ + h * HD_ + half * 32];
    #pragma unroll
    for (int i = 0; i < 8; i++) {
        float x0, y0, x1, y1;
        UNPACK2(x0, y0, vacc[2 * i]);
        UNPACK2(x1, y1, vacc[2 * i + 1]);
        float4 o;
        o.x = x0 * inv; o.y = y0 * inv; o.z = x1 * inv; o.w = y1 * inv;
        *(float4*)&op[i * 4] = o;
    }
}

// ---------------------------------------------------------------------------
// Global attention, split-K over 8 partitions of 512 keys.
// ---------------------------------------------------------------------------
__global__ __launch_bounds__(256) void gattn_part_kernel()
{
    const int sp = blockIdx.x, h = blockIdx.y, b = blockIdx.z;
    const int t = threadIdx.x;
    const int g = t >> 3;
    const int li = t & 7;
    const int bh = b * H_ + h;

    const float* __restrict__ Kg = d_bufs[3];
    const float* __restrict__ Vg = d_bufs[4];

    float q_r[8];
    const float* qp = &d_qg[(b * G_ + g) * D_ + h * HD_ + li * 8];
    *(float4*)&q_r[0] = *(const float4*)&qp[0];
    *(float4*)&q_r[4] = *(const float4*)&qp[4];

    float acc[8];
    #pragma unroll
    for (int i = 0; i < 8; i++) acc[i] = 0.f;
    float lsum = 0.f;

    __shared__ float ks[64][64];
    __shared__ float vs[64][64];

    const float* Kb = &Kg[(bh * S_ + sp * 512) * HD_];
    const float* Vb = &Vg[(bh * S_ + sp * 512) * HD_];

    for (int ch = 0; ch < 8; ch++) {
        __syncthreads();
        #pragma unroll
        for (int r = 0; r < 4; r++) {
            int idx = t + r * 256;
            int key = idx >> 4;
            int c4  = (idx & 15) * 4;
            *(float4*)&ks[key][c4] = *(const float4*)&Kb[(ch * 64 + key) * HD_ + c4];
            *(float4*)&vs[key][c4] = *(const float4*)&Vb[(ch * 64 + key) * HD_ + c4];
        }
        __syncthreads();

        for (int j = 0; j < 64; j++) {
            float4 k0 = *(float4*)&ks[j][li * 8];
            float4 k1 = *(float4*)&ks[j][li * 8 + 4];
            float partial = q_r[0] * k0.x + q_r[1] * k0.y + q_r[2] * k0.z + q_r[3] * k0.w
                          + q_r[4] * k1.x + q_r[5] * k1.y + q_r[6] * k1.z + q_r[7] * k1.w;
            partial += __shfl_xor_sync(0xffffffffu, partial, 1);
            partial += __shfl_xor_sync(0xffffffffu, partial, 2);
            partial += __shfl_xor_sync(0xffffffffu, partial, 4);
            float p = __expf(partial);
            lsum += p;
            float4 v0 = *(float4*)&vs[j][li * 8];
            float4 v1 = *(float4*)&vs[j][li * 8 + 4];
            acc[0] += p * v0.x; acc[1] += p * v0.y; acc[2] += p * v0.z; acc[3] += p * v0.w;
            acc[4] += p * v1.x; acc[5] += p * v1.y; acc[6] += p * v1.z; acc[7] += p * v1.w;
        }
    }

    if (li == 0)
        d_lpart[(bh * 8 + sp) * G_ + g] = lsum;
    float* ap = &d_accpart[((bh * 8 + sp) * G_ + g) * HD_ + li * 8];
    float4 a0, a1;
    a0.x = acc[0]; a0.y = acc[1]; a0.z = acc[2]; a0.w = acc[3];
    a1.x = acc[4]; a1.y = acc[5]; a1.z = acc[6]; a1.w = acc[7];
    *(float4*)&ap[0] = a0;
    *(float4*)&ap[4] = a1;
}

__global__ __launch_bounds__(64) void gattn_combine_kernel(float* __restrict__ out)
{
    const int idx = blockIdx.x;
    const int bh = idx >> 5;
    const int g = idx & 31;
    const int b = bh / H_, h = bh % H_;
    const int d = threadIdx.x;
    float l = 0.f, a = 0.f;
    #pragma unroll
    for (int sp = 0; sp < 8; sp++) {
        l += d_lpart[(bh * 8 + sp) * G_ + g];
        a += d_accpart[((bh * 8 + sp) * G_ + g) * HD_ + d];
    }
    out[(b * S_ + g) * D_ + h * HD_ + d] = a / l;
}

// ---------------------------------------------------------------------------
extern "C" void kernel_launch(void* const* d_in, const int* in_sizes, int n_in,
                              void* d_out, int out_size)
{
    const float* hidden = (const float*)d_in[0];
    const float* Wq  = (const float*)d_in[1];
    const float* bq  = (const float*)d_in[2];
    const float* Wk  = (const float*)d_in[3];
    const float* bk  = (const float*)d_in[4];
    const float* Wv  = (const float*)d_in[5];
    const float* bv  = (const float*)d_in[6];
    const float* Wqg = (const float*)d_in[7];
    const float* bqg = (const float*)d_in[8];
    const float* Wkg = (const float*)d_in[9];
    const float* bkg = (const float*)d_in[10];
    const float* Wvg = (const float*)d_in[11];
    const float* bvg = (const float*)d_in[12];
    float* out = (float*)d_out;

    static int configured = 0;
    if (!configured) {
        cudaFuncSetAttribute(gemm_kernel, cudaFuncAttributeMaxDynamicSharedMemorySize, GEMM_DYN);
        configured = 1;
    }

    // Launch order chosen so the 6th launch (ncu -s 5 -c 1) is band_attn.
    convA_kernel<<<(B_*S_*D_)/1024, 256>>>(hidden);                 // 1
    convW_kernel<<<dim3(24, 24, 5), dim3(32, 8)>>>(Wq, Wk, Wv, Wkg, Wvg); // 2
    qg_proj_kernel<<<B_ * G_, 256>>>(hidden, Wqg, bqg);             // 3

    dim3 ggrid(D_ / 128, (B_ * S_) / 128, 5);
    gemm_kernel<<<ggrid, 256, GEMM_DYN>>>(bq, bk, bv, bkg, bvg);    // 4

    gattn_part_kernel<<<dim3(8, H_, B_), 256>>>();                  // 5
    band_attn_kernel<<<dim3(NC_ * 2, H_, B_), 256>>>(out);          // 6  <- profiled
    gattn_combine_kernel<<<B_ * H_ * G_, 64>>>(out);                // 7
}

// round 8
// speedup vs baseline: 2.3815x; 1.4787x over previous
#include <cuda_runtime.h>
#include <cuda_bf16.h>
#include <cstdint>

// Problem constants
#define B_  2
#define S_  4096
#define D_  768
#define H_  12
#define HD_ 64
#define W_  256
#define NC_ 16
#define G_  32
#define SCALE_ 0.125f

#define BHSD (B_*H_*S_*HD_)   // 6291456
#define NSPLIT 16

// ---------------------------------------------------------------------------
__device__ __forceinline__ uint32_t smem_u32(const void* p) {
    uint32_t a;
    asm("{ .reg .u64 t; cvta.to.shared.u64 t, %1; cvt.u32.u64 %0, t; }" : "=r"(a) : "l"(p));
    return a;
}
#define CPA16(sa, g) asm volatile("cp.async.cg.shared.global [%0], [%1], 16;" :: "r"(sa), "l"(g))
#define CPA_COMMIT() asm volatile("cp.async.commit_group;" ::: "memory")
#define CPA_WAIT1()  asm volatile("cp.async.wait_group 1;" ::: "memory")
#define CPA_WAIT0()  asm volatile("cp.async.wait_group 0;" ::: "memory")
#define LDM4(r, addr) \
  asm volatile("ldmatrix.sync.aligned.m8n8.x4.shared.b16 {%0,%1,%2,%3}, [%4];" \
    : "=r"((r)[0]), "=r"((r)[1]), "=r"((r)[2]), "=r"((r)[3]) : "r"(addr))
#define LDM4T(r, addr) \
  asm volatile("ldmatrix.sync.aligned.m8n8.x4.trans.shared.b16 {%0,%1,%2,%3}, [%4];" \
    : "=r"((r)[0]), "=r"((r)[1]), "=r"((r)[2]), "=r"((r)[3]) : "r"(addr))
#define MMA16816(d, a, b0, b1) \
  asm volatile("mma.sync.aligned.m16n8k16.row.col.f32.bf16.bf16.f32 " \
    "{%0,%1,%2,%3}, {%4,%5,%6,%7}, {%8,%9}, {%0,%1,%2,%3};" \
    : "+f"((d)[0]), "+f"((d)[1]), "+f"((d)[2]), "+f"((d)[3]) \
    : "r"((a)[0]), "r"((a)[1]), "r"((a)[2]), "r"((a)[3]), "r"(b0), "r"(b1))

// ---------------------------------------------------------------------------
// Device scratch. bufs: 3=Kg 4=Vg (fp32)
__device__ float d_bufs[5][BHSD];
__device__ __nv_bfloat16 d_Qhi[BHSD], d_Qlo[BHSD];
__device__ __nv_bfloat16 d_Khi[BHSD], d_Klo[BHSD];
__device__ __nv_bfloat16 d_Vhi[BHSD], d_Vlo[BHSD];
__device__ __nv_bfloat16 d_Ahi[B_*S_*D_];
__device__ __nv_bfloat16 d_Alo[B_*S_*D_];
__device__ __nv_bfloat16 d_Whi[6][D_*D_];   // transposed [n][k]
__device__ __nv_bfloat16 d_Wlo[6][D_*D_];
__device__ float d_qg[B_*G_*D_];
__device__ float d_lpart[B_*H_*NSPLIT*G_];
__device__ float d_accpart[B_*H_*NSPLIT*G_*HD_];

// ---------------------------------------------------------------------------
// Prepass: hidden -> bf16 hi/lo
__global__ __launch_bounds__(256) void convA_kernel(const float* __restrict__ A)
{
    int i = (blockIdx.x * 256 + threadIdx.x) * 4;
    float4 a = *(const float4*)&A[i];
    float av[4] = {a.x, a.y, a.z, a.w};
    __nv_bfloat16 h[4], l[4];
    #pragma unroll
    for (int j = 0; j < 4; j++) {
        h[j] = __float2bfloat16(av[j]);
        l[j] = __float2bfloat16(av[j] - __bfloat162float(h[j]));
    }
    *(uint2*)&d_Ahi[i] = *(uint2*)h;
    *(uint2*)&d_Alo[i] = *(uint2*)l;
}

// Prepass (fused over 6 weights): W[k][n] -> Wt_hi/lo[n][k] bf16
__global__ __launch_bounds__(256) void convW_kernel(
    const float* __restrict__ W0, const float* __restrict__ W1,
    const float* __restrict__ W2, const float* __restrict__ W3,
    const float* __restrict__ W4, const float* __restrict__ W5)
{
    __shared__ float t[32][33];
    const int which = blockIdx.z;
    const float* __restrict__ W = (which == 0) ? W0 : (which == 1) ? W1
                                : (which == 2) ? W2 : (which == 3) ? W3
                                : (which == 4) ? W4 : W5;
    const int n0 = blockIdx.x * 32, k0 = blockIdx.y * 32;
    const int tx = threadIdx.x, ty = threadIdx.y;   // (32, 8)
    #pragma unroll
    for (int r = 0; r < 32; r += 8)
        t[ty + r][tx] = W[(k0 + ty + r) * D_ + n0 + tx];
    __syncthreads();
    #pragma unroll
    for (int r = 0; r < 32; r += 8) {
        float v = t[tx][ty + r];
        __nv_bfloat16 hh = __float2bfloat16(v);
        __nv_bfloat16 ll = __float2bfloat16(v - __bfloat162float(hh));
        d_Whi[which][(n0 + ty + r) * D_ + k0 + tx] = hh;
        d_Wlo[which][(n0 + ty + r) * D_ + k0 + tx] = ll;
    }
}

// ---------------------------------------------------------------------------
// Fused projection GEMMs on mma.sync (HMMA bf16, fp32 acc), hi/lo 3-term.
// qg=0: which = blockIdx.z in 0..4.  qg=1: which=5, m-tiles {0, 4096}.
// Epilogue: which 0/1/2 -> bf16 hi/lo (Q scaled), 3/4 -> fp32, 5 -> d_qg s<G.
// ---------------------------------------------------------------------------
#define TILE_B 10240
#define GEMM_DYN (2*4*TILE_B)   // 81920

__global__ __launch_bounds__(256, 2) void gemm_kernel(
    const float* __restrict__ bq,  const float* __restrict__ bk,
    const float* __restrict__ bv,  const float* __restrict__ bkg,
    const float* __restrict__ bvg, const float* __restrict__ bqg,
    int qg)
{
    extern __shared__ char smraw[];
    const uint32_t sb = smem_u32(smraw);
    const int tid = threadIdx.x, wid = tid >> 5, lane = tid & 31;
    const int mw = wid & 3, nw = wid >> 2;
    const int n0 = blockIdx.x * 128;
    const int m0 = qg ? blockIdx.y * 4096 : blockIdx.y * 128;
    const int which = qg ? 5 : blockIdx.z;
    const float* bias = (which == 0) ? bq : (which == 1) ? bk : (which == 2) ? bv
                       : (which == 3) ? bkg : (which == 4) ? bvg : bqg;
    const __nv_bfloat16* __restrict__ Ahi = d_Ahi;
    const __nv_bfloat16* __restrict__ Alo = d_Alo;
    const __nv_bfloat16* __restrict__ Whi = d_Whi[which];
    const __nv_bfloat16* __restrict__ Wlo = d_Wlo[which];

    float acc[2][8][4];
    #pragma unroll
    for (int mt = 0; mt < 2; mt++)
        #pragma unroll
        for (int nt = 0; nt < 8; nt++)
            #pragma unroll
            for (int r = 0; r < 4; r++) acc[mt][nt][r] = 0.f;

    const int lrow = tid >> 2, lch = tid & 3;
    const int lrow2 = (tid + 256) >> 2;

    auto load_chunk = [&](int buf, int k0) {
        uint32_t base = sb + buf * 4 * TILE_B;
        CPA16(base + lrow * 80 + lch * 16, &Ahi[(m0 + lrow) * D_ + k0 + lch * 8]);
        CPA16(base + lrow2 * 80 + lch * 16, &Ahi[(m0 + lrow2) * D_ + k0 + lch * 8]);
        base += TILE_B;
        CPA16(base + lrow * 80 + lch * 16, &Alo[(m0 + lrow) * D_ + k0 + lch * 8]);
        CPA16(base + lrow2 * 80 + lch * 16, &Alo[(m0 + lrow2) * D_ + k0 + lch * 8]);
        base += TILE_B;
        CPA16(base + lrow * 80 + lch * 16, &Whi[(n0 + lrow) * D_ + k0 + lch * 8]);
        CPA16(base + lrow2 * 80 + lch * 16, &Whi[(n0 + lrow2) * D_ + k0 + lch * 8]);
        base += TILE_B;
        CPA16(base + lrow * 80 + lch * 16, &Wlo[(n0 + lrow) * D_ + k0 + lch * 8]);
        CPA16(base + lrow2 * 80 + lch * 16, &Wlo[(n0 + lrow2) * D_ + k0 + lch * 8]);
        CPA_COMMIT();
    };

    load_chunk(0, 0);

    #pragma unroll 1
    for (int c = 0; c < 24; c++) {
        if (c + 1 < 24) { load_chunk((c + 1) & 1, (c + 1) * 32); CPA_WAIT1(); }
        else CPA_WAIT0();
        __syncthreads();

        const uint32_t aBase  = sb + ((c & 1) * 4 + 0) * TILE_B;
        const uint32_t alBase = sb + ((c & 1) * 4 + 1) * TILE_B;
        const uint32_t bBase  = sb + ((c & 1) * 4 + 2) * TILE_B;
        const uint32_t blBase = sb + ((c & 1) * 4 + 3) * TILE_B;

        #pragma unroll
        for (int ks = 0; ks < 2; ks++) {
            uint32_t ahi[2][4], alo[2][4];
            const uint32_t acoff = ks * 32 + ((lane >> 4) & 1) * 16;
            #pragma unroll
            for (int mt = 0; mt < 2; mt++) {
                int row = mw * 32 + mt * 16 + (lane & 15);
                LDM4(ahi[mt], aBase + row * 80 + acoff);
                LDM4(alo[mt], alBase + row * 80 + acoff);
            }
            const uint32_t bcoff = ks * 32 + ((lane >> 3) & 1) * 16;
            #pragma unroll
            for (int nh = 0; nh < 2; nh++) {
                uint32_t bhi[2][4], blo[2][4];
                #pragma unroll
                for (int q = 0; q < 2; q++) {
                    int row = nw * 64 + nh * 32 + q * 16 + (lane & 7) + ((lane >> 4) << 3);
                    LDM4(bhi[q], bBase + row * 80 + bcoff);
                    LDM4(blo[q], blBase + row * 80 + bcoff);
                }
                #pragma unroll
                for (int mt = 0; mt < 2; mt++)
                    #pragma unroll
                    for (int q = 0; q < 2; q++)
                        #pragma unroll
                        for (int p = 0; p < 2; p++) {
                            int nt = nh * 4 + q * 2 + p;
                            MMA16816(acc[mt][nt], ahi[mt], bhi[q][p*2], bhi[q][p*2+1]);
                            MMA16816(acc[mt][nt], ahi[mt], blo[q][p*2], blo[q][p*2+1]);
                            MMA16816(acc[mt][nt], alo[mt], bhi[q][p*2], bhi[q][p*2+1]);
                        }
            }
        }
        __syncthreads();
    }

    // Epilogue
    const int g = lane >> 2, tg = lane & 3;
    #pragma unroll
    for (int mt = 0; mt < 2; mt++)
        #pragma unroll
        for (int half = 0; half < 2; half++) {
            int m = m0 + mw * 32 + mt * 16 + g + half * 8;
            int b = m >> 12, s = m & 4095;
            #pragma unroll
            for (int nt = 0; nt < 8; nt++) {
                int n = n0 + nw * 64 + nt * 8 + tg * 2;
                float v0 = acc[mt][nt][half * 2 + 0] + bias[n];
                float v1 = acc[mt][nt][half * 2 + 1] + bias[n + 1];
                int h = n >> 6, hd = n & 63;
                size_t bidx = ((size_t)(b * H_ + h) * S_ + s) * HD_ + hd;
                if (which <= 2) {
                    if (which == 0) { v0 *= SCALE_; v1 *= SCALE_; }
                    __nv_bfloat16 h0 = __float2bfloat16(v0);
                    __nv_bfloat16 h1 = __float2bfloat16(v1);
                    __nv_bfloat16 l0 = __float2bfloat16(v0 - __bfloat162float(h0));
                    __nv_bfloat16 l1 = __float2bfloat16(v1 - __bfloat162float(h1));
                    __nv_bfloat162 hp; hp.x = h0; hp.y = h1;
                    __nv_bfloat162 lp; lp.x = l0; lp.y = l1;
                    if (which == 0) {
                        *(__nv_bfloat162*)&d_Qhi[bidx] = hp;
                        *(__nv_bfloat162*)&d_Qlo[bidx] = lp;
                    } else if (which == 1) {
                        *(__nv_bfloat162*)&d_Khi[bidx] = hp;
                        *(__nv_bfloat162*)&d_Klo[bidx] = lp;
                    } else {
                        *(__nv_bfloat162*)&d_Vhi[bidx] = hp;
                        *(__nv_bfloat162*)&d_Vlo[bidx] = lp;
                    }
                } else if (which <= 4) {
                    float2 o; o.x = v0; o.y = v1;
                    *(float2*)&d_bufs[which][bidx] = o;
                } else {
                    if (s < G_) {
                        float2 o; o.x = v0 * SCALE_; o.y = v1 * SCALE_;
                        *(float2*)&d_qg[(b * G_ + s) * D_ + n] = o;
                    }
                }
            }
        }
}

// ---------------------------------------------------------------------------
// Band + global-key attention on mma.sync, flash-style, hi/lo in QK AND PV.
// grid = (NC*2, H, B); CTA = 128 q-rows; 8 warps x 16 rows.
// Key tiles: t=0 -> 32 global keys; t=1..10 -> band e in [qh*128+(t-1)*64, +63].
// ---------------------------------------------------------------------------
__global__ __launch_bounds__(256, 2) void band_mma_kernel(float* __restrict__ out)
{
    __shared__ __align__(16) char ksm_hi[8192];
    __shared__ __align__(16) char ksm_lo[8192];
    __shared__ __align__(16) char vsm_hi[8192];
    __shared__ __align__(16) char vsm_lo[8192];
    const uint32_t sKhi = smem_u32(ksm_hi), sKlo = smem_u32(ksm_lo);
    const uint32_t sVhi = smem_u32(vsm_hi), sVlo = smem_u32(vsm_lo);
    const int tid = threadIdx.x, wid = tid >> 5, lane = tid & 31;
    const int c = blockIdx.x >> 1, qh = blockIdx.x & 1;
    const int h = blockIdx.y, b = blockIdx.z;
    const int bh = b * H_ + h;
    const int row0 = c * W_ + qh * 128;
    const int wr = wid * 16;
    const int g = lane >> 2, tg = lane & 3;
    const int pqr0 = qh * 128 + wr + g;

    // ---- Q fragments (persistent, direct from gmem) ----
    uint32_t qhi[4][4], qlo[4][4];
    {
        const __nv_bfloat16* Qh = &d_Qhi[((size_t)bh * S_ + row0 + wr) * 64];
        const __nv_bfloat16* Ql = &d_Qlo[((size_t)bh * S_ + row0 + wr) * 64];
        #pragma unroll
        for (int ks = 0; ks < 4; ks++) {
            int c0 = ks * 16 + tg * 2;
            qhi[ks][0] = *(const uint32_t*)&Qh[g * 64 + c0];
            qhi[ks][1] = *(const uint32_t*)&Qh[(g + 8) * 64 + c0];
            qhi[ks][2] = *(const uint32_t*)&Qh[g * 64 + c0 + 8];
            qhi[ks][3] = *(const uint32_t*)&Qh[(g + 8) * 64 + c0 + 8];
            qlo[ks][0] = *(const uint32_t*)&Ql[g * 64 + c0];
            qlo[ks][1] = *(const uint32_t*)&Ql[(g + 8) * 64 + c0];
            qlo[ks][2] = *(const uint32_t*)&Ql[g * 64 + c0 + 8];
            qlo[ks][3] = *(const uint32_t*)&Ql[(g + 8) * 64 + c0 + 8];
        }
    }

    float oacc[8][4];
    #pragma unroll
    for (int i = 0; i < 8; i++)
        #pragma unroll
        for (int r = 0; r < 4; r++) oacc[i][r] = 0.f;
    float lsum0 = 0.f, lsum1 = 0.f;

    const int lrowA = tid >> 3, lseg = tid & 7;
    const int lrowB = lrowA + 32;

    #pragma unroll 1
    for (int t = 0; t < 11; t++) {
        const int ebase = qh * 128 + (t - 1) * 64;
        if (t > 0) {
            int kl = c * W_ + ebase - W_;
            if (kl + 63 < 0 || kl >= S_) continue;
        }
        __syncthreads();
        #pragma unroll
        for (int r = 0; r < 2; r++) {
            int row = r ? lrowB : lrowA;
            int ka = (t == 0) ? row : (c * W_ + ebase + row - W_);
            int kr = min(max(ka, 0), S_ - 1);
            uint32_t off = row * 128 + ((lseg ^ (row & 7)) * 16);
            size_t src = ((size_t)bh * S_ + kr) * 64 + lseg * 8;
            CPA16(sKhi + off, &d_Khi[src]);
            CPA16(sKlo + off, &d_Klo[src]);
            CPA16(sVhi + off, &d_Vhi[src]);
            CPA16(sVlo + off, &d_Vlo[src]);
        }
        CPA_COMMIT(); CPA_WAIT0();
        __syncthreads();

        const int nhalf = (t == 0) ? 1 : 2;
        for (int hf = 0; hf < nhalf; hf++) {
            const int kb = hf * 32;
            float sc[4][4];
            #pragma unroll
            for (int i = 0; i < 4; i++)
                #pragma unroll
                for (int r = 0; r < 4; r++) sc[i][r] = 0.f;

            // ---- QK^T (3-term hi/lo) ----
            #pragma unroll
            for (int ks = 0; ks < 4; ks++) {
                uint32_t kh[2][4], kl[2][4];
                #pragma unroll
                for (int q2 = 0; q2 < 2; q2++) {
                    int row = kb + q2 * 16 + (lane & 7) + ((lane >> 4) << 3);
                    int seg = ks * 2 + ((lane >> 3) & 1);
                    uint32_t addr = row * 128 + ((seg ^ (row & 7)) * 16);
                    LDM4(kh[q2], sKhi + addr);
                    LDM4(kl[q2], sKlo + addr);
                }
                #pragma unroll
                for (int q2 = 0; q2 < 2; q2++)
                    #pragma unroll
                    for (int p = 0; p < 2; p++) {
                        int nt = q2 * 2 + p;
                        MMA16816(sc[nt], qhi[ks], kh[q2][p*2], kh[q2][p*2+1]);
                        MMA16816(sc[nt], qhi[ks], kl[q2][p*2], kl[q2][p*2+1]);
                        MMA16816(sc[nt], qlo[ks], kh[q2][p*2], kh[q2][p*2+1]);
                    }
            }

            // ---- mask + exp + pack P hi/lo (bf16 A-frags) ----
            uint32_t pah[2][4], pal[2][4];
            #pragma unroll
            for (int nt = 0; nt < 4; nt++) {
                float p00, p01, p10, p11;
                if (t == 0) {
                    p00 = __expf(sc[nt][0]); p01 = __expf(sc[nt][1]);
                    p10 = __expf(sc[nt][2]); p11 = __expf(sc[nt][3]);
                } else {
                    int e0 = ebase + kb + nt * 8 + tg * 2;
                    int e1 = e0 + 1;
                    int ka0 = c * W_ + e0 - W_;
                    int ka1 = ka0 + 1;
                    int pr1 = pqr0 + 8;
                    bool in0 = (ka0 >= 0) && (ka0 < S_);
                    bool in1 = (ka1 >= 0) && (ka1 < S_);
                    p00 = (in0 && e0 >= pqr0 && e0 <= pqr0 + 2*W_) ? __expf(sc[nt][0]) : 0.f;
                    p01 = (in1 && e1 >= pqr0 && e1 <= pqr0 + 2*W_) ? __expf(sc[nt][1]) : 0.f;
                    p10 = (in0 && e0 >= pr1  && e0 <= pr1  + 2*W_) ? __expf(sc[nt][2]) : 0.f;
                    p11 = (in1 && e1 >= pr1  && e1 <= pr1  + 2*W_) ? __expf(sc[nt][3]) : 0.f;
                }
                lsum0 += p00 + p01;
                lsum1 += p10 + p11;
                __nv_bfloat16 h00 = __float2bfloat16(p00);
                __nv_bfloat16 h01 = __float2bfloat16(p01);
                __nv_bfloat16 h10 = __float2bfloat16(p10);
                __nv_bfloat16 h11 = __float2bfloat16(p11);
                float r00 = p00 - __bfloat162float(h00);
                float r01 = p01 - __bfloat162float(h01);
                float r10 = p10 - __bfloat162float(h10);
                float r11 = p11 - __bfloat162float(h11);
                __nv_bfloat162 hp0; hp0.x = h00; hp0.y = h01;
                __nv_bfloat162 hp1; hp1.x = h10; hp1.y = h11;
                __nv_bfloat162 lp0; lp0.x = __float2bfloat16(r00); lp0.y = __float2bfloat16(r01);
                __nv_bfloat162 lp1; lp1.x = __float2bfloat16(r10); lp1.y = __float2bfloat16(r11);
                pah[nt >> 1][(nt & 1) * 2 + 0] = *(uint32_t*)&hp0;
                pah[nt >> 1][(nt & 1) * 2 + 1] = *(uint32_t*)&hp1;
                pal[nt >> 1][(nt & 1) * 2 + 0] = *(uint32_t*)&lp0;
                pal[nt >> 1][(nt & 1) * 2 + 1] = *(uint32_t*)&lp1;
            }

            // ---- P @ V (3-term hi/lo) ----
            #pragma unroll
            for (int ksp = 0; ksp < 2; ksp++) {
                #pragma unroll
                for (int dg = 0; dg < 4; dg++) {
                    uint32_t vh[4], vl[4];
                    int row = kb + ksp * 16 + (lane & 15);
                    int seg = dg * 2 + (lane >> 4);
                    uint32_t addr = row * 128 + ((seg ^ (row & 7)) * 16);
                    LDM4T(vh, sVhi + addr);
                    LDM4T(vl, sVlo + addr);
                    MMA16816(oacc[dg * 2 + 0], pah[ksp], vh[0], vh[1]);
                    MMA16816(oacc[dg * 2 + 0], pal[ksp], vh[0], vh[1]);
                    MMA16816(oacc[dg * 2 + 0], pah[ksp], vl[0], vl[1]);
                    MMA16816(oacc[dg * 2 + 1], pah[ksp], vh[2], vh[3]);
                    MMA16816(oacc[dg * 2 + 1], pal[ksp], vh[2], vh[3]);
                    MMA16816(oacc[dg * 2 + 1], pah[ksp], vl[2], vl[3]);
                }
            }
        }
    }

    // ---- normalize + store ----
    lsum0 += __shfl_xor_sync(0xffffffffu, lsum0, 1);
    lsum0 += __shfl_xor_sync(0xffffffffu, lsum0, 2);
    lsum1 += __shfl_xor_sync(0xffffffffu, lsum1, 1);
    lsum1 += __shfl_xor_sync(0xffffffffu, lsum1, 2);
    float inv0 = 1.f / lsum0, inv1 = 1.f / lsum1;
    float* o0 = &out[(size_t)(b * S_ + row0 + wr + g) * D_ + h * 64];
    float* o1 = o0 + 8 * D_;
    #pragma unroll
    for (int nt = 0; nt < 8; nt++) {
        float2 w0; w0.x = oacc[nt][0] * inv0; w0.y = oacc[nt][1] * inv0;
        float2 w1; w1.x = oacc[nt][2] * inv1; w1.y = oacc[nt][3] * inv1;
        *(float2*)&o0[nt * 8 + tg * 2] = w0;
        *(float2*)&o1[nt * 8 + tg * 2] = w1;
    }
}

// ---------------------------------------------------------------------------
// Global attention, split-K over NSPLIT partitions of 256 keys.
// ---------------------------------------------------------------------------
__global__ __launch_bounds__(256) void gattn_part_kernel()
{
    const int sp = blockIdx.x, h = blockIdx.y, b = blockIdx.z;
    const int t = threadIdx.x;
    const int g = t >> 3;
    const int li = t & 7;
    const int bh = b * H_ + h;

    const float* __restrict__ Kg = d_bufs[3];
    const float* __restrict__ Vg = d_bufs[4];

    float q_r[8];
    const float* qp = &d_qg[(b * G_ + g) * D_ + h * HD_ + li * 8];
    *(float4*)&q_r[0] = *(const float4*)&qp[0];
    *(float4*)&q_r[4] = *(const float4*)&qp[4];

    float acc[8];
    #pragma unroll
    for (int i = 0; i < 8; i++) acc[i] = 0.f;
    float lsum = 0.f;

    __shared__ float ks[64][64];
    __shared__ float vs[64][64];

    const float* Kb = &Kg[((size_t)bh * S_ + sp * 256) * HD_];
    const float* Vb = &Vg[((size_t)bh * S_ + sp * 256) * HD_];

    for (int ch = 0; ch < 4; ch++) {
        __syncthreads();
        #pragma unroll
        for (int r = 0; r < 4; r++) {
            int idx = t + r * 256;
            int key = idx >> 4;
            int c4  = (idx & 15) * 4;
            *(float4*)&ks[key][c4] = *(const float4*)&Kb[(ch * 64 + key) * HD_ + c4];
            *(float4*)&vs[key][c4] = *(const float4*)&Vb[(ch * 64 + key) * HD_ + c4];
        }
        __syncthreads();

        #pragma unroll 2
        for (int j = 0; j < 64; j++) {
            float4 k0 = *(float4*)&ks[j][li * 8];
            float4 k1 = *(float4*)&ks[j][li * 8 + 4];
            float partial = q_r[0] * k0.x + q_r[1] * k0.y + q_r[2] * k0.z + q_r[3] * k0.w
                          + q_r[4] * k1.x + q_r[5] * k1.y + q_r[6] * k1.z + q_r[7] * k1.w;
            partial += __shfl_xor_sync(0xffffffffu, partial, 1);
            partial += __shfl_xor_sync(0xffffffffu, partial, 2);
            partial += __shfl_xor_sync(0xffffffffu, partial, 4);
            float p = __expf(partial);
            lsum += p;
            float4 v0 = *(float4*)&vs[j][li * 8];
            float4 v1 = *(float4*)&vs[j][li * 8 + 4];
            acc[0] += p * v0.x; acc[1] += p * v0.y; acc[2] += p * v0.z; acc[3] += p * v0.w;
            acc[4] += p * v1.x; acc[5] += p * v1.y; acc[6] += p * v1.z; acc[7] += p * v1.w;
        }
    }

    if (li == 0)
        d_lpart[(bh * NSPLIT + sp) * G_ + g] = lsum;
    float* ap = &d_accpart[((bh * NSPLIT + sp) * G_ + g) * HD_ + li * 8];
    float4 a0, a1;
    a0.x = acc[0]; a0.y = acc[1]; a0.z = acc[2]; a0.w = acc[3];
    a1.x = acc[4]; a1.y = acc[5]; a1.z = acc[6]; a1.w = acc[7];
    *(float4*)&ap[0] = a0;
    *(float4*)&ap[4] = a1;
}

__global__ __launch_bounds__(64) void gattn_combine_kernel(float* __restrict__ out)
{
    const int idx = blockIdx.x;
    const int bh = idx >> 5;
    const int g = idx & 31;
    const int b = bh / H_, h = bh % H_;
    const int d = threadIdx.x;
    float l = 0.f, a = 0.f;
    #pragma unroll
    for (int sp = 0; sp < NSPLIT; sp++) {
        l += d_lpart[(bh * NSPLIT + sp) * G_ + g];
        a += d_accpart[((bh * NSPLIT + sp) * G_ + g) * HD_ + d];
    }
    out[(b * S_ + g) * D_ + h * HD_ + d] = a / l;
}

// ---------------------------------------------------------------------------
extern "C" void kernel_launch(void* const* d_in, const int* in_sizes, int n_in,
                              void* d_out, int out_size)
{
    const float* hidden = (const float*)d_in[0];
    const float* Wq  = (const float*)d_in[1];
    const float* bq  = (const float*)d_in[2];
    const float* Wk  = (const float*)d_in[3];
    const float* bk  = (const float*)d_in[4];
    const float* Wv  = (const float*)d_in[5];
    const float* bv  = (const float*)d_in[6];
    const float* Wqg = (const float*)d_in[7];
    const float* bqg = (const float*)d_in[8];
    const float* Wkg = (const float*)d_in[9];
    const float* bkg = (const float*)d_in[10];
    const float* Wvg = (const float*)d_in[11];
    const float* bvg = (const float*)d_in[12];
    float* out = (float*)d_out;

    static int configured = 0;
    if (!configured) {
        cudaFuncSetAttribute(gemm_kernel, cudaFuncAttributeMaxDynamicSharedMemorySize, GEMM_DYN);
        configured = 1;
    }

    convA_kernel<<<(B_*S_*D_)/1024, 256>>>(hidden);                               // 1
    convW_kernel<<<dim3(24, 24, 6), dim3(32, 8)>>>(Wq, Wk, Wv, Wkg, Wvg, Wqg);    // 2

    dim3 ggrid(D_ / 128, (B_ * S_) / 128, 5);
    gemm_kernel<<<ggrid, 256, GEMM_DYN>>>(bq, bk, bv, bkg, bvg, bqg, 0);          // 3
    gemm_kernel<<<dim3(6, 2, 1), 256, GEMM_DYN>>>(bq, bk, bv, bkg, bvg, bqg, 1);  // 4 (qg)

    gattn_part_kernel<<<dim3(NSPLIT, H_, B_), 256>>>();                           // 5
    band_mma_kernel<<<dim3(NC_ * 2, H_, B_), 256>>>(out);                         // 6 <- profiled
    gattn_combine_kernel<<<B_ * H_ * G_, 64>>>(out);                              // 7
}

// round 9
// speedup vs baseline: 3.8666x; 1.6236x over previous
#include <cuda_runtime.h>
#include <cuda_bf16.h>
#include <cstdint>

// Problem constants
#define B_  2
#define S_  4096
#define D_  768
#define H_  12
#define HD_ 64
#define W_  256
#define NC_ 16
#define G_  32
#define SCALE_ 0.125f

#define BHSD (B_*H_*S_*HD_)   // 6291456
#define NSPLIT 16

// ---------------------------------------------------------------------------
__device__ __forceinline__ uint32_t smem_u32(const void* p) {
    uint32_t a;
    asm("{ .reg .u64 t; cvta.to.shared.u64 t, %1; cvt.u32.u64 %0, t; }" : "=r"(a) : "l"(p));
    return a;
}
#define CPA16(sa, g) asm volatile("cp.async.cg.shared.global [%0], [%1], 16;" :: "r"(sa), "l"(g))
#define CPA_COMMIT() asm volatile("cp.async.commit_group;" ::: "memory")
#define CPA_WAIT1()  asm volatile("cp.async.wait_group 1;" ::: "memory")
#define CPA_WAIT0()  asm volatile("cp.async.wait_group 0;" ::: "memory")
#define LDM4(r, addr) \
  asm volatile("ldmatrix.sync.aligned.m8n8.x4.shared.b16 {%0,%1,%2,%3}, [%4];" \
    : "=r"((r)[0]), "=r"((r)[1]), "=r"((r)[2]), "=r"((r)[3]) : "r"(addr))
#define LDM4T(r, addr) \
  asm volatile("ldmatrix.sync.aligned.m8n8.x4.trans.shared.b16 {%0,%1,%2,%3}, [%4];" \
    : "=r"((r)[0]), "=r"((r)[1]), "=r"((r)[2]), "=r"((r)[3]) : "r"(addr))
#define MMA16816(d, a, b0, b1) \
  asm volatile("mma.sync.aligned.m16n8k16.row.col.f32.bf16.bf16.f32 " \
    "{%0,%1,%2,%3}, {%4,%5,%6,%7}, {%8,%9}, {%0,%1,%2,%3};" \
    : "+f"((d)[0]), "+f"((d)[1]), "+f"((d)[2]), "+f"((d)[3]) \
    : "r"((a)[0]), "r"((a)[1]), "r"((a)[2]), "r"((a)[3]), "r"(b0), "r"(b1))

// ---------------------------------------------------------------------------
// Device scratch. bufs: 3=Kg 4=Vg (fp32)
__device__ float d_bufs[5][BHSD];
__device__ __nv_bfloat16 d_Qhi[BHSD], d_Qlo[BHSD];
__device__ __nv_bfloat16 d_Khi[BHSD], d_Klo[BHSD];
__device__ __nv_bfloat16 d_Vhi[BHSD], d_Vlo[BHSD];
__device__ __nv_bfloat16 d_Ahi[B_*S_*D_];
__device__ __nv_bfloat16 d_Alo[B_*S_*D_];
__device__ __nv_bfloat16 d_Whi[6][D_*D_];   // transposed [n][k]
__device__ __nv_bfloat16 d_Wlo[6][D_*D_];
__device__ float d_qg[B_*G_*D_];
__device__ float d_lpart[B_*H_*NSPLIT*G_];
__device__ float d_accpart[B_*H_*NSPLIT*G_*HD_];

// ---------------------------------------------------------------------------
// Prepass: hidden -> bf16 hi/lo
__global__ __launch_bounds__(256) void convA_kernel(const float* __restrict__ A)
{
    int i = (blockIdx.x * 256 + threadIdx.x) * 4;
    float4 a = *(const float4*)&A[i];
    float av[4] = {a.x, a.y, a.z, a.w};
    __nv_bfloat16 h[4], l[4];
    #pragma unroll
    for (int j = 0; j < 4; j++) {
        h[j] = __float2bfloat16(av[j]);
        l[j] = __float2bfloat16(av[j] - __bfloat162float(h[j]));
    }
    *(uint2*)&d_Ahi[i] = *(uint2*)h;
    *(uint2*)&d_Alo[i] = *(uint2*)l;
}

// Prepass (fused over 6 weights): W[k][n] -> Wt_hi/lo[n][k] bf16
__global__ __launch_bounds__(256) void convW_kernel(
    const float* __restrict__ W0, const float* __restrict__ W1,
    const float* __restrict__ W2, const float* __restrict__ W3,
    const float* __restrict__ W4, const float* __restrict__ W5)
{
    __shared__ float t[32][33];
    const int which = blockIdx.z;
    const float* __restrict__ W = (which == 0) ? W0 : (which == 1) ? W1
                                : (which == 2) ? W2 : (which == 3) ? W3
                                : (which == 4) ? W4 : W5;
    const int n0 = blockIdx.x * 32, k0 = blockIdx.y * 32;
    const int tx = threadIdx.x, ty = threadIdx.y;   // (32, 8)
    #pragma unroll
    for (int r = 0; r < 32; r += 8)
        t[ty + r][tx] = W[(k0 + ty + r) * D_ + n0 + tx];
    __syncthreads();
    #pragma unroll
    for (int r = 0; r < 32; r += 8) {
        float v = t[tx][ty + r];
        __nv_bfloat16 hh = __float2bfloat16(v);
        __nv_bfloat16 ll = __float2bfloat16(v - __bfloat162float(hh));
        d_Whi[which][(n0 + ty + r) * D_ + k0 + tx] = hh;
        d_Wlo[which][(n0 + ty + r) * D_ + k0 + tx] = ll;
    }
}

// ---------------------------------------------------------------------------
// Fused projection GEMMs on mma.sync (HMMA bf16, fp32 acc), hi/lo 3-term.
// grid = (6, 64, 6). z = which; z==5 (qg) only runs y==0 / y==32.
// Epilogue: which 0/1/2 -> bf16 hi/lo (Q scaled), 3/4 -> fp32, 5 -> d_qg s<G.
// ---------------------------------------------------------------------------
#define TILE_B 10240
#define GEMM_DYN (2*4*TILE_B)   // 81920

__global__ __launch_bounds__(256, 2) void gemm_kernel(
    const float* __restrict__ bq,  const float* __restrict__ bk,
    const float* __restrict__ bv,  const float* __restrict__ bkg,
    const float* __restrict__ bvg, const float* __restrict__ bqg)
{
    const int which = blockIdx.z;
    if (which == 5 && blockIdx.y != 0 && blockIdx.y != 32) return;
    extern __shared__ char smraw[];
    const uint32_t sb = smem_u32(smraw);
    const int tid = threadIdx.x, wid = tid >> 5, lane = tid & 31;
    const int mw = wid & 3, nw = wid >> 2;
    const int n0 = blockIdx.x * 128;
    const int m0 = blockIdx.y * 128;
    const float* bias = (which == 0) ? bq : (which == 1) ? bk : (which == 2) ? bv
                       : (which == 3) ? bkg : (which == 4) ? bvg : bqg;
    const __nv_bfloat16* __restrict__ Ahi = d_Ahi;
    const __nv_bfloat16* __restrict__ Alo = d_Alo;
    const __nv_bfloat16* __restrict__ Whi = d_Whi[which];
    const __nv_bfloat16* __restrict__ Wlo = d_Wlo[which];

    float acc[2][8][4];
    #pragma unroll
    for (int mt = 0; mt < 2; mt++)
        #pragma unroll
        for (int nt = 0; nt < 8; nt++)
            #pragma unroll
            for (int r = 0; r < 4; r++) acc[mt][nt][r] = 0.f;

    const int lrow = tid >> 2, lch = tid & 3;
    const int lrow2 = (tid + 256) >> 2;

    auto load_chunk = [&](int buf, int k0) {
        uint32_t base = sb + buf * 4 * TILE_B;
        CPA16(base + lrow * 80 + lch * 16, &Ahi[(m0 + lrow) * D_ + k0 + lch * 8]);
        CPA16(base + lrow2 * 80 + lch * 16, &Ahi[(m0 + lrow2) * D_ + k0 + lch * 8]);
        base += TILE_B;
        CPA16(base + lrow * 80 + lch * 16, &Alo[(m0 + lrow) * D_ + k0 + lch * 8]);
        CPA16(base + lrow2 * 80 + lch * 16, &Alo[(m0 + lrow2) * D_ + k0 + lch * 8]);
        base += TILE_B;
        CPA16(base + lrow * 80 + lch * 16, &Whi[(n0 + lrow) * D_ + k0 + lch * 8]);
        CPA16(base + lrow2 * 80 + lch * 16, &Whi[(n0 + lrow2) * D_ + k0 + lch * 8]);
        base += TILE_B;
        CPA16(base + lrow * 80 + lch * 16, &Wlo[(n0 + lrow) * D_ + k0 + lch * 8]);
        CPA16(base + lrow2 * 80 + lch * 16, &Wlo[(n0 + lrow2) * D_ + k0 + lch * 8]);
        CPA_COMMIT();
    };

    load_chunk(0, 0);

    #pragma unroll 1
    for (int c = 0; c < 24; c++) {
        if (c + 1 < 24) { load_chunk((c + 1) & 1, (c + 1) * 32); CPA_WAIT1(); }
        else CPA_WAIT0();
        __syncthreads();

        const uint32_t aBase  = sb + ((c & 1) * 4 + 0) * TILE_B;
        const uint32_t alBase = sb + ((c & 1) * 4 + 1) * TILE_B;
        const uint32_t bBase  = sb + ((c & 1) * 4 + 2) * TILE_B;
        const uint32_t blBase = sb + ((c & 1) * 4 + 3) * TILE_B;

        #pragma unroll
        for (int ks = 0; ks < 2; ks++) {
            uint32_t ahi[2][4], alo[2][4];
            const uint32_t acoff = ks * 32 + ((lane >> 4) & 1) * 16;
            #pragma unroll
            for (int mt = 0; mt < 2; mt++) {
                int row = mw * 32 + mt * 16 + (lane & 15);
                LDM4(ahi[mt], aBase + row * 80 + acoff);
                LDM4(alo[mt], alBase + row * 80 + acoff);
            }
            const uint32_t bcoff = ks * 32 + ((lane >> 3) & 1) * 16;
            #pragma unroll
            for (int nh = 0; nh < 2; nh++) {
                uint32_t bhi[2][4], blo[2][4];
                #pragma unroll
                for (int q = 0; q < 2; q++) {
                    int row = nw * 64 + nh * 32 + q * 16 + (lane & 7) + ((lane >> 4) << 3);
                    LDM4(bhi[q], bBase + row * 80 + bcoff);
                    LDM4(blo[q], blBase + row * 80 + bcoff);
                }
                #pragma unroll
                for (int mt = 0; mt < 2; mt++)
                    #pragma unroll
                    for (int q = 0; q < 2; q++)
                        #pragma unroll
                        for (int p = 0; p < 2; p++) {
                            int nt = nh * 4 + q * 2 + p;
                            MMA16816(acc[mt][nt], ahi[mt], bhi[q][p*2], bhi[q][p*2+1]);
                            MMA16816(acc[mt][nt], ahi[mt], blo[q][p*2], blo[q][p*2+1]);
                            MMA16816(acc[mt][nt], alo[mt], bhi[q][p*2], bhi[q][p*2+1]);
                        }
            }
        }
        __syncthreads();
    }

    // Epilogue
    const int g = lane >> 2, tg = lane & 3;
    #pragma unroll
    for (int mt = 0; mt < 2; mt++)
        #pragma unroll
        for (int half = 0; half < 2; half++) {
            int m = m0 + mw * 32 + mt * 16 + g + half * 8;
            int b = m >> 12, s = m & 4095;
            #pragma unroll
            for (int nt = 0; nt < 8; nt++) {
                int n = n0 + nw * 64 + nt * 8 + tg * 2;
                float v0 = acc[mt][nt][half * 2 + 0] + bias[n];
                float v1 = acc[mt][nt][half * 2 + 1] + bias[n + 1];
                int h = n >> 6, hd = n & 63;
                size_t bidx = ((size_t)(b * H_ + h) * S_ + s) * HD_ + hd;
                if (which <= 2) {
                    if (which == 0) { v0 *= SCALE_; v1 *= SCALE_; }
                    __nv_bfloat16 h0 = __float2bfloat16(v0);
                    __nv_bfloat16 h1 = __float2bfloat16(v1);
                    __nv_bfloat16 l0 = __float2bfloat16(v0 - __bfloat162float(h0));
                    __nv_bfloat16 l1 = __float2bfloat16(v1 - __bfloat162float(h1));
                    __nv_bfloat162 hp; hp.x = h0; hp.y = h1;
                    __nv_bfloat162 lp; lp.x = l0; lp.y = l1;
                    if (which == 0) {
                        *(__nv_bfloat162*)&d_Qhi[bidx] = hp;
                        *(__nv_bfloat162*)&d_Qlo[bidx] = lp;
                    } else if (which == 1) {
                        *(__nv_bfloat162*)&d_Khi[bidx] = hp;
                        *(__nv_bfloat162*)&d_Klo[bidx] = lp;
                    } else {
                        *(__nv_bfloat162*)&d_Vhi[bidx] = hp;
                        *(__nv_bfloat162*)&d_Vlo[bidx] = lp;
                    }
                } else if (which <= 4) {
                    float2 o; o.x = v0; o.y = v1;
                    *(float2*)&d_bufs[which][bidx] = o;
                } else {
                    if (s < G_) {
                        float2 o; o.x = v0 * SCALE_; o.y = v1 * SCALE_;
                        *(float2*)&d_qg[(b * G_ + s) * D_ + n] = o;
                    }
                }
            }
        }
}

// ---------------------------------------------------------------------------
// Band + global-key attention on mma.sync, flash-style, hi/lo QK and PV,
// double-buffered cp.async pipeline over the active key-tile list.
// grid = (NC*2, H, B); CTA = 128 q-rows; 8 warps x 16 rows.
// ---------------------------------------------------------------------------
__global__ __launch_bounds__(256, 2) void band_mma_kernel(float* __restrict__ out)
{
    __shared__ __align__(16) char ksm_hi[2][8192];
    __shared__ __align__(16) char ksm_lo[2][8192];
    __shared__ __align__(16) char vsm_hi[2][8192];
    __shared__ __align__(16) char vsm_lo[2][8192];
    const int tid = threadIdx.x, wid = tid >> 5, lane = tid & 31;
    const int c = blockIdx.x >> 1, qh = blockIdx.x & 1;
    const int h = blockIdx.y, b = blockIdx.z;
    const int bh = b * H_ + h;
    const int row0 = c * W_ + qh * 128;
    const int wr = wid * 16;
    const int g = lane >> 2, tg = lane & 3;
    const int pqr0 = qh * 128 + wr + g;

    // ---- active tile list (uniform across CTA) ----
    int tlist[11], ntl = 0;
    tlist[ntl++] = 0;
    #pragma unroll
    for (int t = 1; t < 11; t++) {
        int ebase = qh * 128 + (t - 1) * 64;
        int kl = c * W_ + ebase - W_;
        if (kl + 63 >= 0 && kl < S_) tlist[ntl++] = t;
    }

    // ---- Q fragments (persistent, direct from gmem) ----
    uint32_t qhi[4][4], qlo[4][4];
    {
        const __nv_bfloat16* Qh = &d_Qhi[((size_t)bh * S_ + row0 + wr) * 64];
        const __nv_bfloat16* Ql = &d_Qlo[((size_t)bh * S_ + row0 + wr) * 64];
        #pragma unroll
        for (int ks = 0; ks < 4; ks++) {
            int c0 = ks * 16 + tg * 2;
            qhi[ks][0] = *(const uint32_t*)&Qh[g * 64 + c0];
            qhi[ks][1] = *(const uint32_t*)&Qh[(g + 8) * 64 + c0];
            qhi[ks][2] = *(const uint32_t*)&Qh[g * 64 + c0 + 8];
            qhi[ks][3] = *(const uint32_t*)&Qh[(g + 8) * 64 + c0 + 8];
            qlo[ks][0] = *(const uint32_t*)&Ql[g * 64 + c0];
            qlo[ks][1] = *(const uint32_t*)&Ql[(g + 8) * 64 + c0];
            qlo[ks][2] = *(const uint32_t*)&Ql[g * 64 + c0 + 8];
            qlo[ks][3] = *(const uint32_t*)&Ql[(g + 8) * 64 + c0 + 8];
        }
    }

    float oacc[8][4];
    #pragma unroll
    for (int i = 0; i < 8; i++)
        #pragma unroll
        for (int r = 0; r < 4; r++) oacc[i][r] = 0.f;
    float lsum0 = 0.f, lsum1 = 0.f;

    const int lrowA = tid >> 3, lseg = tid & 7;
    const int lrowB = lrowA + 32;

    auto load_tile = [&](int stg, int t) {
        #pragma unroll
        for (int r = 0; r < 2; r++) {
            int row = r ? lrowB : lrowA;
            int ka = (t == 0) ? row
                              : (c * W_ + qh * 128 + (t - 1) * 64 + row - W_);
            int kr = min(max(ka, 0), S_ - 1);
            uint32_t off = row * 128 + ((lseg ^ (row & 7)) * 16);
            size_t src = ((size_t)bh * S_ + kr) * 64 + lseg * 8;
            CPA16(smem_u32(&ksm_hi[stg][0]) + off, &d_Khi[src]);
            CPA16(smem_u32(&ksm_lo[stg][0]) + off, &d_Klo[src]);
            CPA16(smem_u32(&vsm_hi[stg][0]) + off, &d_Vhi[src]);
            CPA16(smem_u32(&vsm_lo[stg][0]) + off, &d_Vlo[src]);
        }
        CPA_COMMIT();
    };

    load_tile(0, tlist[0]);

    #pragma unroll 1
    for (int it = 0; it < ntl; it++) {
        const int t = tlist[it];
        const int stg = it & 1;
        if (it + 1 < ntl) { load_tile((it + 1) & 1, tlist[it + 1]); CPA_WAIT1(); }
        else CPA_WAIT0();
        __syncthreads();

        const uint32_t sKhi = smem_u32(&ksm_hi[stg][0]);
        const uint32_t sKlo = smem_u32(&ksm_lo[stg][0]);
        const uint32_t sVhi = smem_u32(&vsm_hi[stg][0]);
        const uint32_t sVlo = smem_u32(&vsm_lo[stg][0]);
        const int ebase = qh * 128 + (t - 1) * 64;

        const int nhalf = (t == 0) ? 1 : 2;
        for (int hf = 0; hf < nhalf; hf++) {
            const int kb = hf * 32;
            float sc[4][4];
            #pragma unroll
            for (int i = 0; i < 4; i++)
                #pragma unroll
                for (int r = 0; r < 4; r++) sc[i][r] = 0.f;

            // ---- QK^T (3-term hi/lo) ----
            #pragma unroll
            for (int ks = 0; ks < 4; ks++) {
                uint32_t kh[2][4], kl[2][4];
                #pragma unroll
                for (int q2 = 0; q2 < 2; q2++) {
                    int row = kb + q2 * 16 + (lane & 7) + ((lane >> 4) << 3);
                    int seg = ks * 2 + ((lane >> 3) & 1);
                    uint32_t addr = row * 128 + ((seg ^ (row & 7)) * 16);
                    LDM4(kh[q2], sKhi + addr);
                    LDM4(kl[q2], sKlo + addr);
                }
                #pragma unroll
                for (int q2 = 0; q2 < 2; q2++)
                    #pragma unroll
                    for (int p = 0; p < 2; p++) {
                        int nt = q2 * 2 + p;
                        MMA16816(sc[nt], qhi[ks], kh[q2][p*2], kh[q2][p*2+1]);
                        MMA16816(sc[nt], qhi[ks], kl[q2][p*2], kl[q2][p*2+1]);
                        MMA16816(sc[nt], qlo[ks], kh[q2][p*2], kh[q2][p*2+1]);
                    }
            }

            // ---- mask + exp + pack P hi/lo ----
            uint32_t pah[2][4], pal[2][4];
            #pragma unroll
            for (int nt = 0; nt < 4; nt++) {
                float p00, p01, p10, p11;
                if (t == 0) {
                    p00 = __expf(sc[nt][0]); p01 = __expf(sc[nt][1]);
                    p10 = __expf(sc[nt][2]); p11 = __expf(sc[nt][3]);
                } else {
                    int e0 = ebase + kb + nt * 8 + tg * 2;
                    int e1 = e0 + 1;
                    int ka0 = c * W_ + e0 - W_;
                    int ka1 = ka0 + 1;
                    int pr1 = pqr0 + 8;
                    bool in0 = (ka0 >= 0) && (ka0 < S_);
                    bool in1 = (ka1 >= 0) && (ka1 < S_);
                    p00 = (in0 && e0 >= pqr0 && e0 <= pqr0 + 2*W_) ? __expf(sc[nt][0]) : 0.f;
                    p01 = (in1 && e1 >= pqr0 && e1 <= pqr0 + 2*W_) ? __expf(sc[nt][1]) : 0.f;
                    p10 = (in0 && e0 >= pr1  && e0 <= pr1  + 2*W_) ? __expf(sc[nt][2]) : 0.f;
                    p11 = (in1 && e1 >= pr1  && e1 <= pr1  + 2*W_) ? __expf(sc[nt][3]) : 0.f;
                }
                lsum0 += p00 + p01;
                lsum1 += p10 + p11;
                __nv_bfloat16 h00 = __float2bfloat16(p00);
                __nv_bfloat16 h01 = __float2bfloat16(p01);
                __nv_bfloat16 h10 = __float2bfloat16(p10);
                __nv_bfloat16 h11 = __float2bfloat16(p11);
                float r00 = p00 - __bfloat162float(h00);
                float r01 = p01 - __bfloat162float(h01);
                float r10 = p10 - __bfloat162float(h10);
                float r11 = p11 - __bfloat162float(h11);
                __nv_bfloat162 hp0; hp0.x = h00; hp0.y = h01;
                __nv_bfloat162 hp1; hp1.x = h10; hp1.y = h11;
                __nv_bfloat162 lp0; lp0.x = __float2bfloat16(r00); lp0.y = __float2bfloat16(r01);
                __nv_bfloat162 lp1; lp1.x = __float2bfloat16(r10); lp1.y = __float2bfloat16(r11);
                pah[nt >> 1][(nt & 1) * 2 + 0] = *(uint32_t*)&hp0;
                pah[nt >> 1][(nt & 1) * 2 + 1] = *(uint32_t*)&hp1;
                pal[nt >> 1][(nt & 1) * 2 + 0] = *(uint32_t*)&lp0;
                pal[nt >> 1][(nt & 1) * 2 + 1] = *(uint32_t*)&lp1;
            }

            // ---- P @ V (3-term hi/lo) ----
            #pragma unroll
            for (int ksp = 0; ksp < 2; ksp++) {
                #pragma unroll
                for (int dg = 0; dg < 4; dg++) {
                    uint32_t vh[4], vl[4];
                    int row = kb + ksp * 16 + (lane & 15);
                    int seg = dg * 2 + (lane >> 4);
                    uint32_t addr = row * 128 + ((seg ^ (row & 7)) * 16);
                    LDM4T(vh, sVhi + addr);
                    LDM4T(vl, sVlo + addr);
                    MMA16816(oacc[dg * 2 + 0], pah[ksp], vh[0], vh[1]);
                    MMA16816(oacc[dg * 2 + 0], pal[ksp], vh[0], vh[1]);
                    MMA16816(oacc[dg * 2 + 0], pah[ksp], vl[0], vl[1]);
                    MMA16816(oacc[dg * 2 + 1], pah[ksp], vh[2], vh[3]);
                    MMA16816(oacc[dg * 2 + 1], pal[ksp], vh[2], vh[3]);
                    MMA16816(oacc[dg * 2 + 1], pah[ksp], vl[2], vl[3]);
                }
            }
        }
        __syncthreads();
    }

    // ---- normalize + store ----
    lsum0 += __shfl_xor_sync(0xffffffffu, lsum0, 1);
    lsum0 += __shfl_xor_sync(0xffffffffu, lsum0, 2);
    lsum1 += __shfl_xor_sync(0xffffffffu, lsum1, 1);
    lsum1 += __shfl_xor_sync(0xffffffffu, lsum1, 2);
    float inv0 = 1.f / lsum0, inv1 = 1.f / lsum1;
    float* o0 = &out[(size_t)(b * S_ + row0 + wr + g) * D_ + h * 64];
    float* o1 = o0 + 8 * D_;
    #pragma unroll
    for (int nt = 0; nt < 8; nt++) {
        float2 w0; w0.x = oacc[nt][0] * inv0; w0.y = oacc[nt][1] * inv0;
        float2 w1; w1.x = oacc[nt][2] * inv1; w1.y = oacc[nt][3] * inv1;
        *(float2*)&o0[nt * 8 + tg * 2] = w0;
        *(float2*)&o1[nt * 8 + tg * 2] = w1;
    }
}

// ---------------------------------------------------------------------------
// Global attention, split-K over NSPLIT partitions of 256 keys.
// ---------------------------------------------------------------------------
__global__ __launch_bounds__(256) void gattn_part_kernel()
{
    const int sp = blockIdx.x, h = blockIdx.y, b = blockIdx.z;
    const int t = threadIdx.x;
    const int g = t >> 3;
    const int li = t & 7;
    const int bh = b * H_ + h;

    const float* __restrict__ Kg = d_bufs[3];
    const float* __restrict__ Vg = d_bufs[4];

    float q_r[8];
    const float* qp = &d_qg[(b * G_ + g) * D_ + h * HD_ + li * 8];
    *(float4*)&q_r[0] = *(const float4*)&qp[0];
    *(float4*)&q_r[4] = *(const float4*)&qp[4];

    float acc[8];
    #pragma unroll
    for (int i = 0; i < 8; i++) acc[i] = 0.f;
    float lsum = 0.f;

    __shared__ float ks[64][64];
    __shared__ float vs[64][64];

    const float* Kb = &Kg[((size_t)bh * S_ + sp * 256) * HD_];
    const float* Vb = &Vg[((size_t)bh * S_ + sp * 256) * HD_];

    for (int ch = 0; ch < 4; ch++) {
        __syncthreads();
        #pragma unroll
        for (int r = 0; r < 4; r++) {
            int idx = t + r * 256;
            int key = idx >> 4;
            int c4  = (idx & 15) * 4;
            *(float4*)&ks[key][c4] = *(const float4*)&Kb[(ch * 64 + key) * HD_ + c4];
            *(float4*)&vs[key][c4] = *(const float4*)&Vb[(ch * 64 + key) * HD_ + c4];
        }
        __syncthreads();

        #pragma unroll 2
        for (int j = 0; j < 64; j++) {
            float4 k0 = *(float4*)&ks[j][li * 8];
            float4 k1 = *(float4*)&ks[j][li * 8 + 4];
            float partial = q_r[0] * k0.x + q_r[1] * k0.y + q_r[2] * k0.z + q_r[3] * k0.w
                          + q_r[4] * k1.x + q_r[5] * k1.y + q_r[6] * k1.z + q_r[7] * k1.w;
            partial += __shfl_xor_sync(0xffffffffu, partial, 1);
            partial += __shfl_xor_sync(0xffffffffu, partial, 2);
            partial += __shfl_xor_sync(0xffffffffu, partial, 4);
            float p = __expf(partial);
            lsum += p;
            float4 v0 = *(float4*)&vs[j][li * 8];
            float4 v1 = *(float4*)&vs[j][li * 8 + 4];
            acc[0] += p * v0.x; acc[1] += p * v0.y; acc[2] += p * v0.z; acc[3] += p * v0.w;
            acc[4] += p * v1.x; acc[5] += p * v1.y; acc[6] += p * v1.z; acc[7] += p * v1.w;
        }
    }

    if (li == 0)
        d_lpart[(bh * NSPLIT + sp) * G_ + g] = lsum;
    float* ap = &d_accpart[((bh * NSPLIT + sp) * G_ + g) * HD_ + li * 8];
    float4 a0, a1;
    a0.x = acc[0]; a0.y = acc[1]; a0.z = acc[2]; a0.w = acc[3];
    a1.x = acc[4]; a1.y = acc[5]; a1.z = acc[6]; a1.w = acc[7];
    *(float4*)&ap[0] = a0;
    *(float4*)&ap[4] = a1;
}

__global__ __launch_bounds__(64) void gattn_combine_kernel(float* __restrict__ out)
{
    const int idx = blockIdx.x;
    const int bh = idx >> 5;
    const int g = idx & 31;
    const int b = bh / H_, h = bh % H_;
    const int d = threadIdx.x;
    float l = 0.f, a = 0.f;
    #pragma unroll
    for (int sp = 0; sp < NSPLIT; sp++) {
        l += d_lpart[(bh * NSPLIT + sp) * G_ + g];
        a += d_accpart[((bh * NSPLIT + sp) * G_ + g) * HD_ + d];
    }
    out[(b * S_ + g) * D_ + h * HD_ + d] = a / l;
}

// ---------------------------------------------------------------------------
extern "C" void kernel_launch(void* const* d_in, const int* in_sizes, int n_in,
                              void* d_out, int out_size)
{
    const float* hidden = (const float*)d_in[0];
    const float* Wq  = (const float*)d_in[1];
    const float* bq  = (const float*)d_in[2];
    const float* Wk  = (const float*)d_in[3];
    const float* bk  = (const float*)d_in[4];
    const float* Wv  = (const float*)d_in[5];
    const float* bv  = (const float*)d_in[6];
    const float* Wqg = (const float*)d_in[7];
    const float* bqg = (const float*)d_in[8];
    const float* Wkg = (const float*)d_in[9];
    const float* bkg = (const float*)d_in[10];
    const float* Wvg = (const float*)d_in[11];
    const float* bvg = (const float*)d_in[12];
    float* out = (float*)d_out;

    static int configured = 0;
    if (!configured) {
        cudaFuncSetAttribute(gemm_kernel, cudaFuncAttributeMaxDynamicSharedMemorySize, GEMM_DYN);
        configured = 1;
    }

    convA_kernel<<<(B_*S_*D_)/1024, 256>>>(hidden);                               // 1
    convW_kernel<<<dim3(24, 24, 6), dim3(32, 8)>>>(Wq, Wk, Wv, Wkg, Wvg, Wqg);    // 2

    dim3 ggrid(D_ / 128, (B_ * S_) / 128, 6);                                     // 3 (all 6 proj)
    gemm_kernel<<<ggrid, 256, GEMM_DYN>>>(bq, bk, bv, bkg, bvg, bqg);

    band_mma_kernel<<<dim3(NC_ * 2, H_, B_), 256>>>(out);                         // 4 <- profiled
    gattn_part_kernel<<<dim3(NSPLIT, H_, B_), 256>>>();                           // 5
    gattn_combine_kernel<<<B_ * H_ * G_, 64>>>(out);                              // 6
}

// round 10
// speedup vs baseline: 4.4255x; 1.1445x over previous
#include <cuda_runtime.h>
#include <cuda_bf16.h>
#include <cstdint>

// Problem constants
#define B_  2
#define S_  4096
#define D_  768
#define H_  12
#define HD_ 64
#define W_  256
#define NC_ 16
#define G_  32
#define SCALE_ 0.125f

#define BHSD (B_*H_*S_*HD_)   // 6291456
#define NSPLITG 32            // gattn split-K partials (8 sp x 4 kw)

// ---------------------------------------------------------------------------
__device__ __forceinline__ uint32_t smem_u32(const void* p) {
    uint32_t a;
    asm("{ .reg .u64 t; cvta.to.shared.u64 t, %1; cvt.u32.u64 %0, t; }" : "=r"(a) : "l"(p));
    return a;
}
#define CPA16(sa, g) asm volatile("cp.async.cg.shared.global [%0], [%1], 16;" :: "r"(sa), "l"(g))
#define CPA_COMMIT() asm volatile("cp.async.commit_group;" ::: "memory")
#define CPA_WAIT1()  asm volatile("cp.async.wait_group 1;" ::: "memory")
#define CPA_WAIT0()  asm volatile("cp.async.wait_group 0;" ::: "memory")
#define LDM4(r, addr) \
  asm volatile("ldmatrix.sync.aligned.m8n8.x4.shared.b16 {%0,%1,%2,%3}, [%4];" \
    : "=r"((r)[0]), "=r"((r)[1]), "=r"((r)[2]), "=r"((r)[3]) : "r"(addr))
#define LDM4T(r, addr) \
  asm volatile("ldmatrix.sync.aligned.m8n8.x4.trans.shared.b16 {%0,%1,%2,%3}, [%4];" \
    : "=r"((r)[0]), "=r"((r)[1]), "=r"((r)[2]), "=r"((r)[3]) : "r"(addr))
#define MMA16816(d, a, b0, b1) \
  asm volatile("mma.sync.aligned.m16n8k16.row.col.f32.bf16.bf16.f32 " \
    "{%0,%1,%2,%3}, {%4,%5,%6,%7}, {%8,%9}, {%0,%1,%2,%3};" \
    : "+f"((d)[0]), "+f"((d)[1]), "+f"((d)[2]), "+f"((d)[3]) \
    : "r"((a)[0]), "r"((a)[1]), "r"((a)[2]), "r"((a)[3]), "r"(b0), "r"(b1))

// ---------------------------------------------------------------------------
// Device scratch (bf16 hi/lo everywhere the tensor cores touch)
__device__ __nv_bfloat16 d_Qhi[BHSD], d_Qlo[BHSD];
__device__ __nv_bfloat16 d_Khi[BHSD], d_Klo[BHSD];
__device__ __nv_bfloat16 d_Vhi[BHSD], d_Vlo[BHSD];
__device__ __nv_bfloat16 d_Kghi[BHSD], d_Kglo[BHSD];
__device__ __nv_bfloat16 d_Vghi[BHSD], d_Vglo[BHSD];
__device__ __nv_bfloat16 d_qghi[B_*H_*G_*HD_], d_qglo[B_*H_*G_*HD_];
__device__ __nv_bfloat16 d_Ahi[B_*S_*D_];
__device__ __nv_bfloat16 d_Alo[B_*S_*D_];
__device__ __nv_bfloat16 d_Whi[6][D_*D_];   // transposed [n][k]
__device__ __nv_bfloat16 d_Wlo[6][D_*D_];
__device__ float d_lpart[B_*H_*NSPLITG*G_];
__device__ float d_accpart[B_*H_*NSPLITG*G_*HD_];

// ---------------------------------------------------------------------------
// Prepass: hidden -> bf16 hi/lo
__global__ __launch_bounds__(256) void convA_kernel(const float* __restrict__ A)
{
    int i = (blockIdx.x * 256 + threadIdx.x) * 4;
    float4 a = *(const float4*)&A[i];
    float av[4] = {a.x, a.y, a.z, a.w};
    __nv_bfloat16 h[4], l[4];
    #pragma unroll
    for (int j = 0; j < 4; j++) {
        h[j] = __float2bfloat16(av[j]);
        l[j] = __float2bfloat16(av[j] - __bfloat162float(h[j]));
    }
    *(uint2*)&d_Ahi[i] = *(uint2*)h;
    *(uint2*)&d_Alo[i] = *(uint2*)l;
}

// Prepass (fused over 6 weights): W[k][n] -> Wt_hi/lo[n][k] bf16
__global__ __launch_bounds__(256) void convW_kernel(
    const float* __restrict__ W0, const float* __restrict__ W1,
    const float* __restrict__ W2, const float* __restrict__ W3,
    const float* __restrict__ W4, const float* __restrict__ W5)
{
    __shared__ float t[32][33];
    const int which = blockIdx.z;
    const float* __restrict__ W = (which == 0) ? W0 : (which == 1) ? W1
                                : (which == 2) ? W2 : (which == 3) ? W3
                                : (which == 4) ? W4 : W5;
    const int n0 = blockIdx.x * 32, k0 = blockIdx.y * 32;
    const int tx = threadIdx.x, ty = threadIdx.y;   // (32, 8)
    #pragma unroll
    for (int r = 0; r < 32; r += 8)
        t[ty + r][tx] = W[(k0 + ty + r) * D_ + n0 + tx];
    __syncthreads();
    #pragma unroll
    for (int r = 0; r < 32; r += 8) {
        float v = t[tx][ty + r];
        __nv_bfloat16 hh = __float2bfloat16(v);
        __nv_bfloat16 ll = __float2bfloat16(v - __bfloat162float(hh));
        d_Whi[which][(n0 + ty + r) * D_ + k0 + tx] = hh;
        d_Wlo[which][(n0 + ty + r) * D_ + k0 + tx] = ll;
    }
}

// ---------------------------------------------------------------------------
// Fused projection GEMMs on mma.sync (HMMA bf16, fp32 acc), hi/lo 3-term.
// grid = (6, 64, 6). z = which; z==5 (qg) only runs y==0 / y==32.
// Epilogue: 0/1/2 -> Q/K/V hi/lo (Q scaled); 3/4 -> Kg/Vg hi/lo; 5 -> qg hi/lo.
// ---------------------------------------------------------------------------
#define TILE_B 10240
#define GEMM_DYN (2*4*TILE_B)   // 81920

__global__ __launch_bounds__(256, 2) void gemm_kernel(
    const float* __restrict__ bq,  const float* __restrict__ bk,
    const float* __restrict__ bv,  const float* __restrict__ bkg,
    const float* __restrict__ bvg, const float* __restrict__ bqg)
{
    const int which = blockIdx.z;
    if (which == 5 && blockIdx.y != 0 && blockIdx.y != 32) return;
    extern __shared__ char smraw[];
    const uint32_t sb = smem_u32(smraw);
    const int tid = threadIdx.x, wid = tid >> 5, lane = tid & 31;
    const int mw = wid & 3, nw = wid >> 2;
    const int n0 = blockIdx.x * 128;
    const int m0 = blockIdx.y * 128;
    const float* bias = (which == 0) ? bq : (which == 1) ? bk : (which == 2) ? bv
                       : (which == 3) ? bkg : (which == 4) ? bvg : bqg;
    const __nv_bfloat16* __restrict__ Ahi = d_Ahi;
    const __nv_bfloat16* __restrict__ Alo = d_Alo;
    const __nv_bfloat16* __restrict__ Whi = d_Whi[which];
    const __nv_bfloat16* __restrict__ Wlo = d_Wlo[which];

    float acc[2][8][4];
    #pragma unroll
    for (int mt = 0; mt < 2; mt++)
        #pragma unroll
        for (int nt = 0; nt < 8; nt++)
            #pragma unroll
            for (int r = 0; r < 4; r++) acc[mt][nt][r] = 0.f;

    const int lrow = tid >> 2, lch = tid & 3;
    const int lrow2 = (tid + 256) >> 2;

    auto load_chunk = [&](int buf, int k0) {
        uint32_t base = sb + buf * 4 * TILE_B;
        CPA16(base + lrow * 80 + lch * 16, &Ahi[(m0 + lrow) * D_ + k0 + lch * 8]);
        CPA16(base + lrow2 * 80 + lch * 16, &Ahi[(m0 + lrow2) * D_ + k0 + lch * 8]);
        base += TILE_B;
        CPA16(base + lrow * 80 + lch * 16, &Alo[(m0 + lrow) * D_ + k0 + lch * 8]);
        CPA16(base + lrow2 * 80 + lch * 16, &Alo[(m0 + lrow2) * D_ + k0 + lch * 8]);
        base += TILE_B;
        CPA16(base + lrow * 80 + lch * 16, &Whi[(n0 + lrow) * D_ + k0 + lch * 8]);
        CPA16(base + lrow2 * 80 + lch * 16, &Whi[(n0 + lrow2) * D_ + k0 + lch * 8]);
        base += TILE_B;
        CPA16(base + lrow * 80 + lch * 16, &Wlo[(n0 + lrow) * D_ + k0 + lch * 8]);
        CPA16(base + lrow2 * 80 + lch * 16, &Wlo[(n0 + lrow2) * D_ + k0 + lch * 8]);
        CPA_COMMIT();
    };

    load_chunk(0, 0);

    #pragma unroll 1
    for (int c = 0; c < 24; c++) {
        if (c + 1 < 24) { load_chunk((c + 1) & 1, (c + 1) * 32); CPA_WAIT1(); }
        else CPA_WAIT0();
        __syncthreads();

        const uint32_t aBase  = sb + ((c & 1) * 4 + 0) * TILE_B;
        const uint32_t alBase = sb + ((c & 1) * 4 + 1) * TILE_B;
        const uint32_t bBase  = sb + ((c & 1) * 4 + 2) * TILE_B;
        const uint32_t blBase = sb + ((c & 1) * 4 + 3) * TILE_B;

        #pragma unroll
        for (int ks = 0; ks < 2; ks++) {
            uint32_t ahi[2][4], alo[2][4];
            const uint32_t acoff = ks * 32 + ((lane >> 4) & 1) * 16;
            #pragma unroll
            for (int mt = 0; mt < 2; mt++) {
                int row = mw * 32 + mt * 16 + (lane & 15);
                LDM4(ahi[mt], aBase + row * 80 + acoff);
                LDM4(alo[mt], alBase + row * 80 + acoff);
            }
            const uint32_t bcoff = ks * 32 + ((lane >> 3) & 1) * 16;
            #pragma unroll
            for (int nh = 0; nh < 2; nh++) {
                uint32_t bhi[2][4], blo[2][4];
                #pragma unroll
                for (int q = 0; q < 2; q++) {
                    int row = nw * 64 + nh * 32 + q * 16 + (lane & 7) + ((lane >> 4) << 3);
                    LDM4(bhi[q], bBase + row * 80 + bcoff);
                    LDM4(blo[q], blBase + row * 80 + bcoff);
                }
                #pragma unroll
                for (int mt = 0; mt < 2; mt++)
                    #pragma unroll
                    for (int q = 0; q < 2; q++)
                        #pragma unroll
                        for (int p = 0; p < 2; p++) {
                            int nt = nh * 4 + q * 2 + p;
                            MMA16816(acc[mt][nt], ahi[mt], bhi[q][p*2], bhi[q][p*2+1]);
                            MMA16816(acc[mt][nt], ahi[mt], blo[q][p*2], blo[q][p*2+1]);
                            MMA16816(acc[mt][nt], alo[mt], bhi[q][p*2], bhi[q][p*2+1]);
                        }
            }
        }
        __syncthreads();
    }

    // Epilogue: bf16 hi/lo split stores
    const int g = lane >> 2, tg = lane & 3;
    #pragma unroll
    for (int mt = 0; mt < 2; mt++)
        #pragma unroll
        for (int half = 0; half < 2; half++) {
            int m = m0 + mw * 32 + mt * 16 + g + half * 8;
            int b = m >> 12, s = m & 4095;
            #pragma unroll
            for (int nt = 0; nt < 8; nt++) {
                int n = n0 + nw * 64 + nt * 8 + tg * 2;
                float v0 = acc[mt][nt][half * 2 + 0] + bias[n];
                float v1 = acc[mt][nt][half * 2 + 1] + bias[n + 1];
                int h = n >> 6, hd = n & 63;
                if (which == 0 || which == 5) { v0 *= SCALE_; v1 *= SCALE_; }
                if (which == 5 && s >= G_) continue;
                __nv_bfloat16 h0 = __float2bfloat16(v0);
                __nv_bfloat16 h1 = __float2bfloat16(v1);
                __nv_bfloat16 l0 = __float2bfloat16(v0 - __bfloat162float(h0));
                __nv_bfloat16 l1 = __float2bfloat16(v1 - __bfloat162float(h1));
                __nv_bfloat162 hp; hp.x = h0; hp.y = h1;
                __nv_bfloat162 lp; lp.x = l0; lp.y = l1;
                size_t bidx = ((size_t)(b * H_ + h) * S_ + s) * HD_ + hd;
                switch (which) {
                    case 0:
                        *(__nv_bfloat162*)&d_Qhi[bidx] = hp;
                        *(__nv_bfloat162*)&d_Qlo[bidx] = lp; break;
                    case 1:
                        *(__nv_bfloat162*)&d_Khi[bidx] = hp;
                        *(__nv_bfloat162*)&d_Klo[bidx] = lp; break;
                    case 2:
                        *(__nv_bfloat162*)&d_Vhi[bidx] = hp;
                        *(__nv_bfloat162*)&d_Vlo[bidx] = lp; break;
                    case 3:
                        *(__nv_bfloat162*)&d_Kghi[bidx] = hp;
                        *(__nv_bfloat162*)&d_Kglo[bidx] = lp; break;
                    case 4:
                        *(__nv_bfloat162*)&d_Vghi[bidx] = hp;
                        *(__nv_bfloat162*)&d_Vglo[bidx] = lp; break;
                    default: {
                        size_t qidx = ((size_t)(b * H_ + h) * G_ + s) * HD_ + hd;
                        *(__nv_bfloat162*)&d_qghi[qidx] = hp;
                        *(__nv_bfloat162*)&d_qglo[qidx] = lp; break;
                    }
                }
            }
        }
}

// ---------------------------------------------------------------------------
// Global attention on mma.sync. grid = (8, H, B); 512 keys per CTA, 4 chunks
// of 128 keys in smem. 8 warps = 2 m-halves (mw) x 4 key-subchunks (kw).
// 3-term hi/lo QK and PV; no masking (softmax over all S). 32 split-K parts.
// ---------------------------------------------------------------------------
__global__ __launch_bounds__(256, 2) void gattn_mma_kernel()
{
    __shared__ __align__(16) char kh_sm[16384];
    __shared__ __align__(16) char kl_sm[16384];
    __shared__ __align__(16) char vh_sm[16384];
    __shared__ __align__(16) char vl_sm[16384];
    const uint32_t sKhi = smem_u32(kh_sm), sKlo = smem_u32(kl_sm);
    const uint32_t sVhi = smem_u32(vh_sm), sVlo = smem_u32(vl_sm);
    const int tid = threadIdx.x, wid = tid >> 5, lane = tid & 31;
    const int sp = blockIdx.x, h = blockIdx.y, b = blockIdx.z;
    const int bh = b * H_ + h;
    const int mw = wid & 1, kw = wid >> 1;
    const int g = lane >> 2, tg = lane & 3;

    // Q fragments: rows mw*16 + {g, g+8}, k = 64 dims
    uint32_t qhi[4][4], qlo[4][4];
    {
        const __nv_bfloat16* Qh = &d_qghi[((size_t)bh * G_ + mw * 16) * 64];
        const __nv_bfloat16* Ql = &d_qglo[((size_t)bh * G_ + mw * 16) * 64];
        #pragma unroll
        for (int ks = 0; ks < 4; ks++) {
            int c0 = ks * 16 + tg * 2;
            qhi[ks][0] = *(const uint32_t*)&Qh[g * 64 + c0];
            qhi[ks][1] = *(const uint32_t*)&Qh[(g + 8) * 64 + c0];
            qhi[ks][2] = *(const uint32_t*)&Qh[g * 64 + c0 + 8];
            qhi[ks][3] = *(const uint32_t*)&Qh[(g + 8) * 64 + c0 + 8];
            qlo[ks][0] = *(const uint32_t*)&Ql[g * 64 + c0];
            qlo[ks][1] = *(const uint32_t*)&Ql[(g + 8) * 64 + c0];
            qlo[ks][2] = *(const uint32_t*)&Ql[g * 64 + c0 + 8];
            qlo[ks][3] = *(const uint32_t*)&Ql[(g + 8) * 64 + c0 + 8];
        }
    }

    float oacc[8][4];
    #pragma unroll
    for (int i = 0; i < 8; i++)
        #pragma unroll
        for (int r = 0; r < 4; r++) oacc[i][r] = 0.f;
    float lsum0 = 0.f, lsum1 = 0.f;

    #pragma unroll 1
    for (int ch = 0; ch < 4; ch++) {
        __syncthreads();
        #pragma unroll
        for (int r = 0; r < 4; r++) {
            int idx = tid + r * 256;       // 0..1023: 128 rows x 8 segs
            int row = idx >> 3, seg = idx & 7;
            uint32_t off = row * 128 + ((seg ^ (row & 7)) * 16);
            size_t src = ((size_t)bh * S_ + sp * 512 + ch * 128 + row) * 64 + seg * 8;
            CPA16(sKhi + off, &d_Kghi[src]);
            CPA16(sKlo + off, &d_Kglo[src]);
            CPA16(sVhi + off, &d_Vghi[src]);
            CPA16(sVlo + off, &d_Vglo[src]);
        }
        CPA_COMMIT(); CPA_WAIT0();
        __syncthreads();

        const int kb = kw * 32;
        float sc[4][4];
        #pragma unroll
        for (int i = 0; i < 4; i++)
            #pragma unroll
            for (int r = 0; r < 4; r++) sc[i][r] = 0.f;

        // QK^T (3-term hi/lo)
        #pragma unroll
        for (int ks = 0; ks < 4; ks++) {
            uint32_t kh[2][4], kl[2][4];
            #pragma unroll
            for (int q2 = 0; q2 < 2; q2++) {
                int row = kb + q2 * 16 + (lane & 7) + ((lane >> 4) << 3);
                int seg = ks * 2 + ((lane >> 3) & 1);
                uint32_t addr = row * 128 + ((seg ^ (row & 7)) * 16);
                LDM4(kh[q2], sKhi + addr);
                LDM4(kl[q2], sKlo + addr);
            }
            #pragma unroll
            for (int q2 = 0; q2 < 2; q2++)
                #pragma unroll
                for (int p = 0; p < 2; p++) {
                    int nt = q2 * 2 + p;
                    MMA16816(sc[nt], qhi[ks], kh[q2][p*2], kh[q2][p*2+1]);
                    MMA16816(sc[nt], qhi[ks], kl[q2][p*2], kl[q2][p*2+1]);
                    MMA16816(sc[nt], qlo[ks], kh[q2][p*2], kh[q2][p*2+1]);
                }
        }

        // exp + pack P hi/lo (no mask)
        uint32_t pah[2][4], pal[2][4];
        #pragma unroll
        for (int nt = 0; nt < 4; nt++) {
            float p00 = __expf(sc[nt][0]), p01 = __expf(sc[nt][1]);
            float p10 = __expf(sc[nt][2]), p11 = __expf(sc[nt][3]);
            lsum0 += p00 + p01;
            lsum1 += p10 + p11;
            __nv_bfloat16 h00 = __float2bfloat16(p00);
            __nv_bfloat16 h01 = __float2bfloat16(p01);
            __nv_bfloat16 h10 = __float2bfloat16(p10);
            __nv_bfloat16 h11 = __float2bfloat16(p11);
            __nv_bfloat162 hp0; hp0.x = h00; hp0.y = h01;
            __nv_bfloat162 hp1; hp1.x = h10; hp1.y = h11;
            __nv_bfloat162 lp0;
            lp0.x = __float2bfloat16(p00 - __bfloat162float(h00));
            lp0.y = __float2bfloat16(p01 - __bfloat162float(h01));
            __nv_bfloat162 lp1;
            lp1.x = __float2bfloat16(p10 - __bfloat162float(h10));
            lp1.y = __float2bfloat16(p11 - __bfloat162float(h11));
            pah[nt >> 1][(nt & 1) * 2 + 0] = *(uint32_t*)&hp0;
            pah[nt >> 1][(nt & 1) * 2 + 1] = *(uint32_t*)&hp1;
            pal[nt >> 1][(nt & 1) * 2 + 0] = *(uint32_t*)&lp0;
            pal[nt >> 1][(nt & 1) * 2 + 1] = *(uint32_t*)&lp1;
        }

        // P @ V (3-term hi/lo)
        #pragma unroll
        for (int ksp = 0; ksp < 2; ksp++) {
            #pragma unroll
            for (int dg = 0; dg < 4; dg++) {
                uint32_t vh[4], vl[4];
                int row = kb + ksp * 16 + (lane & 15);
                int seg = dg * 2 + (lane >> 4);
                uint32_t addr = row * 128 + ((seg ^ (row & 7)) * 16);
                LDM4T(vh, sVhi + addr);
                LDM4T(vl, sVlo + addr);
                MMA16816(oacc[dg * 2 + 0], pah[ksp], vh[0], vh[1]);
                MMA16816(oacc[dg * 2 + 0], pal[ksp], vh[0], vh[1]);
                MMA16816(oacc[dg * 2 + 0], pah[ksp], vl[0], vl[1]);
                MMA16816(oacc[dg * 2 + 1], pah[ksp], vh[2], vh[3]);
                MMA16816(oacc[dg * 2 + 1], pal[ksp], vh[2], vh[3]);
                MMA16816(oacc[dg * 2 + 1], pah[ksp], vl[2], vl[3]);
            }
        }
    }

    // write split-K partials: part = sp*4 + kw
    lsum0 += __shfl_xor_sync(0xffffffffu, lsum0, 1);
    lsum0 += __shfl_xor_sync(0xffffffffu, lsum0, 2);
    lsum1 += __shfl_xor_sync(0xffffffffu, lsum1, 1);
    lsum1 += __shfl_xor_sync(0xffffffffu, lsum1, 2);
    const int part = sp * 4 + kw;
    const int r0 = mw * 16 + g, r1 = r0 + 8;
    if (tg == 0) {
        d_lpart[((size_t)bh * NSPLITG + part) * G_ + r0] = lsum0;
        d_lpart[((size_t)bh * NSPLITG + part) * G_ + r1] = lsum1;
    }
    float* a0 = &d_accpart[(((size_t)bh * NSPLITG + part) * G_ + r0) * HD_];
    float* a1 = &d_accpart[(((size_t)bh * NSPLITG + part) * G_ + r1) * HD_];
    #pragma unroll
    for (int nt = 0; nt < 8; nt++) {
        float2 w0; w0.x = oacc[nt][0]; w0.y = oacc[nt][1];
        float2 w1; w1.x = oacc[nt][2]; w1.y = oacc[nt][3];
        *(float2*)&a0[nt * 8 + tg * 2] = w0;
        *(float2*)&a1[nt * 8 + tg * 2] = w1;
    }
}

__global__ __launch_bounds__(64) void gattn_combine_kernel(float* __restrict__ out)
{
    const int idx = blockIdx.x;
    const int bh = idx >> 5;
    const int g = idx & 31;
    const int b = bh / H_, h = bh % H_;
    const int d = threadIdx.x;
    float l = 0.f, a = 0.f;
    #pragma unroll
    for (int sp = 0; sp < NSPLITG; sp++) {
        l += d_lpart[((size_t)bh * NSPLITG + sp) * G_ + g];
        a += d_accpart[(((size_t)bh * NSPLITG + sp) * G_ + g) * HD_ + d];
    }
    out[(b * S_ + g) * D_ + h * HD_ + d] = a / l;
}

// ---------------------------------------------------------------------------
// Band + global-key attention on mma.sync, flash-style, hi/lo QK and PV,
// double-buffered cp.async pipeline over the active key-tile list.
// ---------------------------------------------------------------------------
__global__ __launch_bounds__(256, 2) void band_mma_kernel(float* __restrict__ out)
{
    __shared__ __align__(16) char ksm_hi[2][8192];
    __shared__ __align__(16) char ksm_lo[2][8192];
    __shared__ __align__(16) char vsm_hi[2][8192];
    __shared__ __align__(16) char vsm_lo[2][8192];
    const int tid = threadIdx.x, wid = tid >> 5, lane = tid & 31;
    const int c = blockIdx.x >> 1, qh = blockIdx.x & 1;
    const int h = blockIdx.y, b = blockIdx.z;
    const int bh = b * H_ + h;
    const int row0 = c * W_ + qh * 128;
    const int wr = wid * 16;
    const int g = lane >> 2, tg = lane & 3;
    const int pqr0 = qh * 128 + wr + g;

    int tlist[11], ntl = 0;
    tlist[ntl++] = 0;
    #pragma unroll
    for (int t = 1; t < 11; t++) {
        int ebase = qh * 128 + (t - 1) * 64;
        int kl = c * W_ + ebase - W_;
        if (kl + 63 >= 0 && kl < S_) tlist[ntl++] = t;
    }

    uint32_t qhi[4][4], qlo[4][4];
    {
        const __nv_bfloat16* Qh = &d_Qhi[((size_t)bh * S_ + row0 + wr) * 64];
        const __nv_bfloat16* Ql = &d_Qlo[((size_t)bh * S_ + row0 + wr) * 64];
        #pragma unroll
        for (int ks = 0; ks < 4; ks++) {
            int c0 = ks * 16 + tg * 2;
            qhi[ks][0] = *(const uint32_t*)&Qh[g * 64 + c0];
            qhi[ks][1] = *(const uint32_t*)&Qh[(g + 8) * 64 + c0];
            qhi[ks][2] = *(const uint32_t*)&Qh[g * 64 + c0 + 8];
            qhi[ks][3] = *(const uint32_t*)&Qh[(g + 8) * 64 + c0 + 8];
            qlo[ks][0] = *(const uint32_t*)&Ql[g * 64 + c0];
            qlo[ks][1] = *(const uint32_t*)&Ql[(g + 8) * 64 + c0];
            qlo[ks][2] = *(const uint32_t*)&Ql[g * 64 + c0 + 8];
            qlo[ks][3] = *(const uint32_t*)&Ql[(g + 8) * 64 + c0 + 8];
        }
    }

    float oacc[8][4];
    #pragma unroll
    for (int i = 0; i < 8; i++)
        #pragma unroll
        for (int r = 0; r < 4; r++) oacc[i][r] = 0.f;
    float lsum0 = 0.f, lsum1 = 0.f;

    const int lrowA = tid >> 3, lseg = tid & 7;
    const int lrowB = lrowA + 32;

    auto load_tile = [&](int stg, int t) {
        #pragma unroll
        for (int r = 0; r < 2; r++) {
            int row = r ? lrowB : lrowA;
            int ka = (t == 0) ? row
                              : (c * W_ + qh * 128 + (t - 1) * 64 + row - W_);
            int kr = min(max(ka, 0), S_ - 1);
            uint32_t off = row * 128 + ((lseg ^ (row & 7)) * 16);
            size_t src = ((size_t)bh * S_ + kr) * 64 + lseg * 8;
            CPA16(smem_u32(&ksm_hi[stg][0]) + off, &d_Khi[src]);
            CPA16(smem_u32(&ksm_lo[stg][0]) + off, &d_Klo[src]);
            CPA16(smem_u32(&vsm_hi[stg][0]) + off, &d_Vhi[src]);
            CPA16(smem_u32(&vsm_lo[stg][0]) + off, &d_Vlo[src]);
        }
        CPA_COMMIT();
    };

    load_tile(0, tlist[0]);

    #pragma unroll 1
    for (int it = 0; it < ntl; it++) {
        const int t = tlist[it];
        const int stg = it & 1;
        if (it + 1 < ntl) { load_tile((it + 1) & 1, tlist[it + 1]); CPA_WAIT1(); }
        else CPA_WAIT0();
        __syncthreads();

        const uint32_t sKhi = smem_u32(&ksm_hi[stg][0]);
        const uint32_t sKlo = smem_u32(&ksm_lo[stg][0]);
        const uint32_t sVhi = smem_u32(&vsm_hi[stg][0]);
        const uint32_t sVlo = smem_u32(&vsm_lo[stg][0]);
        const int ebase = qh * 128 + (t - 1) * 64;

        const int nhalf = (t == 0) ? 1 : 2;
        for (int hf = 0; hf < nhalf; hf++) {
            const int kb = hf * 32;
            float sc[4][4];
            #pragma unroll
            for (int i = 0; i < 4; i++)
                #pragma unroll
                for (int r = 0; r < 4; r++) sc[i][r] = 0.f;

            #pragma unroll
            for (int ks = 0; ks < 4; ks++) {
                uint32_t kh[2][4], kl[2][4];
                #pragma unroll
                for (int q2 = 0; q2 < 2; q2++) {
                    int row = kb + q2 * 16 + (lane & 7) + ((lane >> 4) << 3);
                    int seg = ks * 2 + ((lane >> 3) & 1);
                    uint32_t addr = row * 128 + ((seg ^ (row & 7)) * 16);
                    LDM4(kh[q2], sKhi + addr);
                    LDM4(kl[q2], sKlo + addr);
                }
                #pragma unroll
                for (int q2 = 0; q2 < 2; q2++)
                    #pragma unroll
                    for (int p = 0; p < 2; p++) {
                        int nt = q2 * 2 + p;
                        MMA16816(sc[nt], qhi[ks], kh[q2][p*2], kh[q2][p*2+1]);
                        MMA16816(sc[nt], qhi[ks], kl[q2][p*2], kl[q2][p*2+1]);
                        MMA16816(sc[nt], qlo[ks], kh[q2][p*2], kh[q2][p*2+1]);
                    }
            }

            uint32_t pah[2][4], pal[2][4];
            #pragma unroll
            for (int nt = 0; nt < 4; nt++) {
                float p00, p01, p10, p11;
                if (t == 0) {
                    p00 = __expf(sc[nt][0]); p01 = __expf(sc[nt][1]);
                    p10 = __expf(sc[nt][2]); p11 = __expf(sc[nt][3]);
                } else {
                    int e0 = ebase + kb + nt * 8 + tg * 2;
                    int e1 = e0 + 1;
                    int ka0 = c * W_ + e0 - W_;
                    int ka1 = ka0 + 1;
                    int pr1 = pqr0 + 8;
                    bool in0 = (ka0 >= 0) && (ka0 < S_);
                    bool in1 = (ka1 >= 0) && (ka1 < S_);
                    p00 = (in0 && e0 >= pqr0 && e0 <= pqr0 + 2*W_) ? __expf(sc[nt][0]) : 0.f;
                    p01 = (in1 && e1 >= pqr0 && e1 <= pqr0 + 2*W_) ? __expf(sc[nt][1]) : 0.f;
                    p10 = (in0 && e0 >= pr1  && e0 <= pr1  + 2*W_) ? __expf(sc[nt][2]) : 0.f;
                    p11 = (in1 && e1 >= pr1  && e1 <= pr1  + 2*W_) ? __expf(sc[nt][3]) : 0.f;
                }
                lsum0 += p00 + p01;
                lsum1 += p10 + p11;
                __nv_bfloat16 h00 = __float2bfloat16(p00);
                __nv_bfloat16 h01 = __float2bfloat16(p01);
                __nv_bfloat16 h10 = __float2bfloat16(p10);
                __nv_bfloat16 h11 = __float2bfloat16(p11);
                __nv_bfloat162 hp0; hp0.x = h00; hp0.y = h01;
                __nv_bfloat162 hp1; hp1.x = h10; hp1.y = h11;
                __nv_bfloat162 lp0;
                lp0.x = __float2bfloat16(p00 - __bfloat162float(h00));
                lp0.y = __float2bfloat16(p01 - __bfloat162float(h01));
                __nv_bfloat162 lp1;
                lp1.x = __float2bfloat16(p10 - __bfloat162float(h10));
                lp1.y = __float2bfloat16(p11 - __bfloat162float(h11));
                pah[nt >> 1][(nt & 1) * 2 + 0] = *(uint32_t*)&hp0;
                pah[nt >> 1][(nt & 1) * 2 + 1] = *(uint32_t*)&hp1;
                pal[nt >> 1][(nt & 1) * 2 + 0] = *(uint32_t*)&lp0;
                pal[nt >> 1][(nt & 1) * 2 + 1] = *(uint32_t*)&lp1;
            }

            #pragma unroll
            for (int ksp = 0; ksp < 2; ksp++) {
                #pragma unroll
                for (int dg = 0; dg < 4; dg++) {
                    uint32_t vh[4], vl[4];
                    int row = kb + ksp * 16 + (lane & 15);
                    int seg = dg * 2 + (lane >> 4);
                    uint32_t addr = row * 128 + ((seg ^ (row & 7)) * 16);
                    LDM4T(vh, sVhi + addr);
                    LDM4T(vl, sVlo + addr);
                    MMA16816(oacc[dg * 2 + 0], pah[ksp], vh[0], vh[1]);
                    MMA16816(oacc[dg * 2 + 0], pal[ksp], vh[0], vh[1]);
                    MMA16816(oacc[dg * 2 + 0], pah[ksp], vl[0], vl[1]);
                    MMA16816(oacc[dg * 2 + 1], pah[ksp], vh[2], vh[3]);
                    MMA16816(oacc[dg * 2 + 1], pal[ksp], vh[2], vh[3]);
                    MMA16816(oacc[dg * 2 + 1], pah[ksp], vl[2], vl[3]);
                }
            }
        }
        __syncthreads();
    }

    lsum0 += __shfl_xor_sync(0xffffffffu, lsum0, 1);
    lsum0 += __shfl_xor_sync(0xffffffffu, lsum0, 2);
    lsum1 += __shfl_xor_sync(0xffffffffu, lsum1, 1);
    lsum1 += __shfl_xor_sync(0xffffffffu, lsum1, 2);
    float inv0 = 1.f / lsum0, inv1 = 1.f / lsum1;
    float* o0 = &out[(size_t)(b * S_ + row0 + wr + g) * D_ + h * 64];
    float* o1 = o0 + 8 * D_;
    #pragma unroll
    for (int nt = 0; nt < 8; nt++) {
        float2 w0; w0.x = oacc[nt][0] * inv0; w0.y = oacc[nt][1] * inv0;
        float2 w1; w1.x = oacc[nt][2] * inv1; w1.y = oacc[nt][3] * inv1;
        *(float2*)&o0[nt * 8 + tg * 2] = w0;
        *(float2*)&o1[nt * 8 + tg * 2] = w1;
    }
}

// ---------------------------------------------------------------------------
extern "C" void kernel_launch(void* const* d_in, const int* in_sizes, int n_in,
                              void* d_out, int out_size)
{
    const float* hidden = (const float*)d_in[0];
    const float* Wq  = (const float*)d_in[1];
    const float* bq  = (const float*)d_in[2];
    const float* Wk  = (const float*)d_in[3];
    const float* bk  = (const float*)d_in[4];
    const float* Wv  = (const float*)d_in[5];
    const float* bv  = (const float*)d_in[6];
    const float* Wqg = (const float*)d_in[7];
    const float* bqg = (const float*)d_in[8];
    const float* Wkg = (const float*)d_in[9];
    const float* bkg = (const float*)d_in[10];
    const float* Wvg = (const float*)d_in[11];
    const float* bvg = (const float*)d_in[12];
    float* out = (float*)d_out;

    static int configured = 0;
    if (!configured) {
        cudaFuncSetAttribute(gemm_kernel, cudaFuncAttributeMaxDynamicSharedMemorySize, GEMM_DYN);
        configured = 1;
    }

    convA_kernel<<<(B_*S_*D_)/1024, 256>>>(hidden);                               // 1
    convW_kernel<<<dim3(24, 24, 6), dim3(32, 8)>>>(Wq, Wk, Wv, Wkg, Wvg, Wqg);    // 2

    dim3 ggrid(D_ / 128, (B_ * S_) / 128, 6);
    gemm_kernel<<<ggrid, 256, GEMM_DYN>>>(bq, bk, bv, bkg, bvg, bqg);             // 3

    gattn_mma_kernel<<<dim3(8, H_, B_), 256>>>();                                 // 4 <- profiled
    band_mma_kernel<<<dim3(NC_ * 2, H_, B_), 256>>>(out);                         // 5
    gattn_combine_kernel<<<B_ * H_ * G_, 64>>>(out);                              // 6
}

// round 11
// speedup vs baseline: 5.1230x; 1.1576x over previous
#include <cuda_runtime.h>
#include <cuda_bf16.h>
#include <cstdint>

// Problem constants
#define B_  2
#define S_  4096
#define D_  768
#define H_  12
#define HD_ 64
#define W_  256
#define NC_ 16
#define G_  32
#define SCALE_ 0.125f

#define BHSD (B_*H_*S_*HD_)   // 6291456
#define NSPLITG 32            // gattn split-K partials (8 sp x 4 kw)

// ---------------------------------------------------------------------------
__device__ __forceinline__ uint32_t smem_u32(const void* p) {
    uint32_t a;
    asm("{ .reg .u64 t; cvta.to.shared.u64 t, %1; cvt.u32.u64 %0, t; }" : "=r"(a) : "l"(p));
    return a;
}
#define CPA16(sa, g) asm volatile("cp.async.cg.shared.global [%0], [%1], 16;" :: "r"(sa), "l"(g))
#define CPA_COMMIT() asm volatile("cp.async.commit_group;" ::: "memory")
#define CPA_WAIT1()  asm volatile("cp.async.wait_group 1;" ::: "memory")
#define CPA_WAIT0()  asm volatile("cp.async.wait_group 0;" ::: "memory")
#define LDM4(r, addr) \
  asm volatile("ldmatrix.sync.aligned.m8n8.x4.shared.b16 {%0,%1,%2,%3}, [%4];" \
    : "=r"((r)[0]), "=r"((r)[1]), "=r"((r)[2]), "=r"((r)[3]) : "r"(addr))
#define LDM4T(r, addr) \
  asm volatile("ldmatrix.sync.aligned.m8n8.x4.trans.shared.b16 {%0,%1,%2,%3}, [%4];" \
    : "=r"((r)[0]), "=r"((r)[1]), "=r"((r)[2]), "=r"((r)[3]) : "r"(addr))
#define MMA16816(d, a, b0, b1) \
  asm volatile("mma.sync.aligned.m16n8k16.row.col.f32.bf16.bf16.f32 " \
    "{%0,%1,%2,%3}, {%4,%5,%6,%7}, {%8,%9}, {%0,%1,%2,%3};" \
    : "+f"((d)[0]), "+f"((d)[1]), "+f"((d)[2]), "+f"((d)[3]) \
    : "r"((a)[0]), "r"((a)[1]), "r"((a)[2]), "r"((a)[3]), "r"(b0), "r"(b1))

// 64B-row swizzle: seg' = seg ^ ((row>>1)&3)  (conflict-free for ldmatrix + cp.async)
#define SWZ64(row, seg) ((uint32_t)((row) * 64 + ((((seg) ^ ((row) >> 1)) & 3) * 16)))

// ---------------------------------------------------------------------------
// Device scratch (bf16 hi/lo everywhere the tensor cores touch)
__device__ __nv_bfloat16 d_Qhi[BHSD], d_Qlo[BHSD];
__device__ __nv_bfloat16 d_Khi[BHSD], d_Klo[BHSD];
__device__ __nv_bfloat16 d_Vhi[BHSD], d_Vlo[BHSD];
__device__ __nv_bfloat16 d_Kghi[BHSD], d_Kglo[BHSD];
__device__ __nv_bfloat16 d_Vghi[BHSD], d_Vglo[BHSD];
__device__ __nv_bfloat16 d_qghi[B_*H_*G_*HD_], d_qglo[B_*H_*G_*HD_];
__device__ __nv_bfloat16 d_Ahi[B_*S_*D_];
__device__ __nv_bfloat16 d_Alo[B_*S_*D_];
__device__ __nv_bfloat16 d_Whi[6][D_*D_];   // transposed [n][k]
__device__ __nv_bfloat16 d_Wlo[6][D_*D_];
__device__ float d_lpart[B_*H_*NSPLITG*G_];
__device__ float d_accpart[B_*H_*NSPLITG*G_*HD_];

// ---------------------------------------------------------------------------
// Prepass: hidden -> bf16 hi/lo
__global__ __launch_bounds__(256) void convA_kernel(const float* __restrict__ A)
{
    int i = (blockIdx.x * 256 + threadIdx.x) * 4;
    float4 a = *(const float4*)&A[i];
    float av[4] = {a.x, a.y, a.z, a.w};
    __nv_bfloat16 h[4], l[4];
    #pragma unroll
    for (int j = 0; j < 4; j++) {
        h[j] = __float2bfloat16(av[j]);
        l[j] = __float2bfloat16(av[j] - __bfloat162float(h[j]));
    }
    *(uint2*)&d_Ahi[i] = *(uint2*)h;
    *(uint2*)&d_Alo[i] = *(uint2*)l;
}

// Prepass (fused over 6 weights): W[k][n] -> Wt_hi/lo[n][k] bf16
__global__ __launch_bounds__(256) void convW_kernel(
    const float* __restrict__ W0, const float* __restrict__ W1,
    const float* __restrict__ W2, const float* __restrict__ W3,
    const float* __restrict__ W4, const float* __restrict__ W5)
{
    __shared__ float t[32][33];
    const int which = blockIdx.z;
    const float* __restrict__ W = (which == 0) ? W0 : (which == 1) ? W1
                                : (which == 2) ? W2 : (which == 3) ? W3
                                : (which == 4) ? W4 : W5;
    const int n0 = blockIdx.x * 32, k0 = blockIdx.y * 32;
    const int tx = threadIdx.x, ty = threadIdx.y;   // (32, 8)
    #pragma unroll
    for (int r = 0; r < 32; r += 8)
        t[ty + r][tx] = W[(k0 + ty + r) * D_ + n0 + tx];
    __syncthreads();
    #pragma unroll
    for (int r = 0; r < 32; r += 8) {
        float v = t[tx][ty + r];
        __nv_bfloat16 hh = __float2bfloat16(v);
        __nv_bfloat16 ll = __float2bfloat16(v - __bfloat162float(hh));
        d_Whi[which][(n0 + ty + r) * D_ + k0 + tx] = hh;
        d_Wlo[which][(n0 + ty + r) * D_ + k0 + tx] = ll;
    }
}

// ---------------------------------------------------------------------------
// Fused projection GEMMs on mma.sync, hi/lo 3-term, 3-stage cp.async pipeline,
// swizzled 64B smem rows, ONE barrier per K-chunk.
// grid = (6, 64, 6). z = which; z==5 (qg) only runs y==0 / y==32.
// ---------------------------------------------------------------------------
#define GTILE 8192                 // 128 rows x 64B, swizzled
#define GSTAGE (4 * GTILE)         // 4 operands per stage
#define GEMM_DYN (3 * GSTAGE)      // 98304

__global__ __launch_bounds__(256, 2) void gemm_kernel(
    const float* __restrict__ bq,  const float* __restrict__ bk,
    const float* __restrict__ bv,  const float* __restrict__ bkg,
    const float* __restrict__ bvg, const float* __restrict__ bqg)
{
    const int which = blockIdx.z;
    if (which == 5 && blockIdx.y != 0 && blockIdx.y != 32) return;
    extern __shared__ char smraw[];
    const uint32_t sb = smem_u32(smraw);
    const int tid = threadIdx.x, wid = tid >> 5, lane = tid & 31;
    const int mw = wid & 3, nw = wid >> 2;
    const int n0 = blockIdx.x * 128;
    const int m0 = blockIdx.y * 128;
    const float* bias = (which == 0) ? bq : (which == 1) ? bk : (which == 2) ? bv
                       : (which == 3) ? bkg : (which == 4) ? bvg : bqg;
    const __nv_bfloat16* __restrict__ Ahi = d_Ahi;
    const __nv_bfloat16* __restrict__ Alo = d_Alo;
    const __nv_bfloat16* __restrict__ Whi = d_Whi[which];
    const __nv_bfloat16* __restrict__ Wlo = d_Wlo[which];

    float acc[2][8][4];
    #pragma unroll
    for (int mt = 0; mt < 2; mt++)
        #pragma unroll
        for (int nt = 0; nt < 8; nt++)
            #pragma unroll
            for (int r = 0; r < 4; r++) acc[mt][nt][r] = 0.f;

    const int lrow = tid >> 2, lch = tid & 3;     // 64 rows x 4 segs
    const int lrow2 = lrow + 64;
    const uint32_t o1 = SWZ64(lrow, lch), o2 = SWZ64(lrow2, lch);

    auto load_chunk = [&](int buf, int k0) {
        uint32_t base = sb + buf * GSTAGE;
        CPA16(base + o1, &Ahi[(m0 + lrow) * D_ + k0 + lch * 8]);
        CPA16(base + o2, &Ahi[(m0 + lrow2) * D_ + k0 + lch * 8]);
        base += GTILE;
        CPA16(base + o1, &Alo[(m0 + lrow) * D_ + k0 + lch * 8]);
        CPA16(base + o2, &Alo[(m0 + lrow2) * D_ + k0 + lch * 8]);
        base += GTILE;
        CPA16(base + o1, &Whi[(n0 + lrow) * D_ + k0 + lch * 8]);
        CPA16(base + o2, &Whi[(n0 + lrow2) * D_ + k0 + lch * 8]);
        base += GTILE;
        CPA16(base + o1, &Wlo[(n0 + lrow) * D_ + k0 + lch * 8]);
        CPA16(base + o2, &Wlo[(n0 + lrow2) * D_ + k0 + lch * 8]);
        CPA_COMMIT();
    };

    load_chunk(0, 0);
    load_chunk(1, 32);

    int cur = 0;
    #pragma unroll 1
    for (int c = 0; c < 24; c++) {
        if (c == 23) CPA_WAIT0(); else CPA_WAIT1();
        __syncthreads();
        if (c + 2 < 24) {
            int nxt = cur + 2; if (nxt >= 3) nxt -= 3;
            load_chunk(nxt, (c + 2) * 32);
        }

        const uint32_t aBase  = sb + cur * GSTAGE;
        const uint32_t alBase = aBase + GTILE;
        const uint32_t bBase  = aBase + 2 * GTILE;
        const uint32_t blBase = aBase + 3 * GTILE;

        #pragma unroll
        for (int ks = 0; ks < 2; ks++) {
            uint32_t ahi[2][4], alo[2][4];
            const int aseg = ks * 2 + ((lane >> 4) & 1);
            #pragma unroll
            for (int mt = 0; mt < 2; mt++) {
                int row = mw * 32 + mt * 16 + (lane & 15);
                LDM4(ahi[mt], aBase + SWZ64(row, aseg));
                LDM4(alo[mt], alBase + SWZ64(row, aseg));
            }
            const int bseg = ks * 2 + ((lane >> 3) & 1);
            #pragma unroll
            for (int nh = 0; nh < 2; nh++) {
                uint32_t bhi[2][4], blo[2][4];
                #pragma unroll
                for (int q = 0; q < 2; q++) {
                    int row = nw * 64 + nh * 32 + q * 16 + (lane & 7) + ((lane >> 4) << 3);
                    LDM4(bhi[q], bBase + SWZ64(row, bseg));
                    LDM4(blo[q], blBase + SWZ64(row, bseg));
                }
                #pragma unroll
                for (int mt = 0; mt < 2; mt++)
                    #pragma unroll
                    for (int q = 0; q < 2; q++)
                        #pragma unroll
                        for (int p = 0; p < 2; p++) {
                            int nt = nh * 4 + q * 2 + p;
                            MMA16816(acc[mt][nt], ahi[mt], bhi[q][p*2], bhi[q][p*2+1]);
                            MMA16816(acc[mt][nt], ahi[mt], blo[q][p*2], blo[q][p*2+1]);
                            MMA16816(acc[mt][nt], alo[mt], bhi[q][p*2], bhi[q][p*2+1]);
                        }
            }
        }
        cur++; if (cur >= 3) cur -= 3;
    }

    // Epilogue: bf16 hi/lo split stores
    const int g = lane >> 2, tg = lane & 3;
    #pragma unroll
    for (int mt = 0; mt < 2; mt++)
        #pragma unroll
        for (int half = 0; half < 2; half++) {
            int m = m0 + mw * 32 + mt * 16 + g + half * 8;
            int b = m >> 12, s = m & 4095;
            #pragma unroll
            for (int nt = 0; nt < 8; nt++) {
                int n = n0 + nw * 64 + nt * 8 + tg * 2;
                float v0 = acc[mt][nt][half * 2 + 0] + bias[n];
                float v1 = acc[mt][nt][half * 2 + 1] + bias[n + 1];
                int h = n >> 6, hd = n & 63;
                if (which == 0 || which == 5) { v0 *= SCALE_; v1 *= SCALE_; }
                if (which == 5 && s >= G_) continue;
                __nv_bfloat16 h0 = __float2bfloat16(v0);
                __nv_bfloat16 h1 = __float2bfloat16(v1);
                __nv_bfloat16 l0 = __float2bfloat16(v0 - __bfloat162float(h0));
                __nv_bfloat16 l1 = __float2bfloat16(v1 - __bfloat162float(h1));
                __nv_bfloat162 hp; hp.x = h0; hp.y = h1;
                __nv_bfloat162 lp; lp.x = l0; lp.y = l1;
                size_t bidx = ((size_t)(b * H_ + h) * S_ + s) * HD_ + hd;
                switch (which) {
                    case 0:
                        *(__nv_bfloat162*)&d_Qhi[bidx] = hp;
                        *(__nv_bfloat162*)&d_Qlo[bidx] = lp; break;
                    case 1:
                        *(__nv_bfloat162*)&d_Khi[bidx] = hp;
                        *(__nv_bfloat162*)&d_Klo[bidx] = lp; break;
                    case 2:
                        *(__nv_bfloat162*)&d_Vhi[bidx] = hp;
                        *(__nv_bfloat162*)&d_Vlo[bidx] = lp; break;
                    case 3:
                        *(__nv_bfloat162*)&d_Kghi[bidx] = hp;
                        *(__nv_bfloat162*)&d_Kglo[bidx] = lp; break;
                    case 4:
                        *(__nv_bfloat162*)&d_Vghi[bidx] = hp;
                        *(__nv_bfloat162*)&d_Vglo[bidx] = lp; break;
                    default: {
                        size_t qidx = ((size_t)(b * H_ + h) * G_ + s) * HD_ + hd;
                        *(__nv_bfloat162*)&d_qghi[qidx] = hp;
                        *(__nv_bfloat162*)&d_qglo[qidx] = lp; break;
                    }
                }
            }
        }
}

// ---------------------------------------------------------------------------
// Global attention on mma.sync (unchanged; 21 us).
// ---------------------------------------------------------------------------
__global__ __launch_bounds__(256, 2) void gattn_mma_kernel()
{
    __shared__ __align__(16) char kh_sm[16384];
    __shared__ __align__(16) char kl_sm[16384];
    __shared__ __align__(16) char vh_sm[16384];
    __shared__ __align__(16) char vl_sm[16384];
    const uint32_t sKhi = smem_u32(kh_sm), sKlo = smem_u32(kl_sm);
    const uint32_t sVhi = smem_u32(vh_sm), sVlo = smem_u32(vl_sm);
    const int tid = threadIdx.x, wid = tid >> 5, lane = tid & 31;
    const int sp = blockIdx.x, h = blockIdx.y, b = blockIdx.z;
    const int bh = b * H_ + h;
    const int mw = wid & 1, kw = wid >> 1;
    const int g = lane >> 2, tg = lane & 3;

    uint32_t qhi[4][4], qlo[4][4];
    {
        const __nv_bfloat16* Qh = &d_qghi[((size_t)bh * G_ + mw * 16) * 64];
        const __nv_bfloat16* Ql = &d_qglo[((size_t)bh * G_ + mw * 16) * 64];
        #pragma unroll
        for (int ks = 0; ks < 4; ks++) {
            int c0 = ks * 16 + tg * 2;
            qhi[ks][0] = *(const uint32_t*)&Qh[g * 64 + c0];
            qhi[ks][1] = *(const uint32_t*)&Qh[(g + 8) * 64 + c0];
            qhi[ks][2] = *(const uint32_t*)&Qh[g * 64 + c0 + 8];
            qhi[ks][3] = *(const uint32_t*)&Qh[(g + 8) * 64 + c0 + 8];
            qlo[ks][0] = *(const uint32_t*)&Ql[g * 64 + c0];
            qlo[ks][1] = *(const uint32_t*)&Ql[(g + 8) * 64 + c0];
            qlo[ks][2] = *(const uint32_t*)&Ql[g * 64 + c0 + 8];
            qlo[ks][3] = *(const uint32_t*)&Ql[(g + 8) * 64 + c0 + 8];
        }
    }

    float oacc[8][4];
    #pragma unroll
    for (int i = 0; i < 8; i++)
        #pragma unroll
        for (int r = 0; r < 4; r++) oacc[i][r] = 0.f;
    float lsum0 = 0.f, lsum1 = 0.f;

    #pragma unroll 1
    for (int ch = 0; ch < 4; ch++) {
        __syncthreads();
        #pragma unroll
        for (int r = 0; r < 4; r++) {
            int idx = tid + r * 256;
            int row = idx >> 3, seg = idx & 7;
            uint32_t off = row * 128 + ((seg ^ (row & 7)) * 16);
            size_t src = ((size_t)bh * S_ + sp * 512 + ch * 128 + row) * 64 + seg * 8;
            CPA16(sKhi + off, &d_Kghi[src]);
            CPA16(sKlo + off, &d_Kglo[src]);
            CPA16(sVhi + off, &d_Vghi[src]);
            CPA16(sVlo + off, &d_Vglo[src]);
        }
        CPA_COMMIT(); CPA_WAIT0();
        __syncthreads();

        const int kb = kw * 32;
        float sc[4][4];
        #pragma unroll
        for (int i = 0; i < 4; i++)
            #pragma unroll
            for (int r = 0; r < 4; r++) sc[i][r] = 0.f;

        #pragma unroll
        for (int ks = 0; ks < 4; ks++) {
            uint32_t kh[2][4], kl[2][4];
            #pragma unroll
            for (int q2 = 0; q2 < 2; q2++) {
                int row = kb + q2 * 16 + (lane & 7) + ((lane >> 4) << 3);
                int seg = ks * 2 + ((lane >> 3) & 1);
                uint32_t addr = row * 128 + ((seg ^ (row & 7)) * 16);
                LDM4(kh[q2], sKhi + addr);
                LDM4(kl[q2], sKlo + addr);
            }
            #pragma unroll
            for (int q2 = 0; q2 < 2; q2++)
                #pragma unroll
                for (int p = 0; p < 2; p++) {
                    int nt = q2 * 2 + p;
                    MMA16816(sc[nt], qhi[ks], kh[q2][p*2], kh[q2][p*2+1]);
                    MMA16816(sc[nt], qhi[ks], kl[q2][p*2], kl[q2][p*2+1]);
                    MMA16816(sc[nt], qlo[ks], kh[q2][p*2], kh[q2][p*2+1]);
                }
        }

        uint32_t pah[2][4], pal[2][4];
        #pragma unroll
        for (int nt = 0; nt < 4; nt++) {
            float p00 = __expf(sc[nt][0]), p01 = __expf(sc[nt][1]);
            float p10 = __expf(sc[nt][2]), p11 = __expf(sc[nt][3]);
            lsum0 += p00 + p01;
            lsum1 += p10 + p11;
            __nv_bfloat16 h00 = __float2bfloat16(p00);
            __nv_bfloat16 h01 = __float2bfloat16(p01);
            __nv_bfloat16 h10 = __float2bfloat16(p10);
            __nv_bfloat16 h11 = __float2bfloat16(p11);
            __nv_bfloat162 hp0; hp0.x = h00; hp0.y = h01;
            __nv_bfloat162 hp1; hp1.x = h10; hp1.y = h11;
            __nv_bfloat162 lp0;
            lp0.x = __float2bfloat16(p00 - __bfloat162float(h00));
            lp0.y = __float2bfloat16(p01 - __bfloat162float(h01));
            __nv_bfloat162 lp1;
            lp1.x = __float2bfloat16(p10 - __bfloat162float(h10));
            lp1.y = __float2bfloat16(p11 - __bfloat162float(h11));
            pah[nt >> 1][(nt & 1) * 2 + 0] = *(uint32_t*)&hp0;
            pah[nt >> 1][(nt & 1) * 2 + 1] = *(uint32_t*)&hp1;
            pal[nt >> 1][(nt & 1) * 2 + 0] = *(uint32_t*)&lp0;
            pal[nt >> 1][(nt & 1) * 2 + 1] = *(uint32_t*)&lp1;
        }

        #pragma unroll
        for (int ksp = 0; ksp < 2; ksp++) {
            #pragma unroll
            for (int dg = 0; dg < 4; dg++) {
                uint32_t vh[4], vl[4];
                int row = kb + ksp * 16 + (lane & 15);
                int seg = dg * 2 + (lane >> 4);
                uint32_t addr = row * 128 + ((seg ^ (row & 7)) * 16);
                LDM4T(vh, sVhi + addr);
                LDM4T(vl, sVlo + addr);
                MMA16816(oacc[dg * 2 + 0], pah[ksp], vh[0], vh[1]);
                MMA16816(oacc[dg * 2 + 0], pal[ksp], vh[0], vh[1]);
                MMA16816(oacc[dg * 2 + 0], pah[ksp], vl[0], vl[1]);
                MMA16816(oacc[dg * 2 + 1], pah[ksp], vh[2], vh[3]);
                MMA16816(oacc[dg * 2 + 1], pal[ksp], vh[2], vh[3]);
                MMA16816(oacc[dg * 2 + 1], pah[ksp], vl[2], vl[3]);
            }
        }
    }

    lsum0 += __shfl_xor_sync(0xffffffffu, lsum0, 1);
    lsum0 += __shfl_xor_sync(0xffffffffu, lsum0, 2);
    lsum1 += __shfl_xor_sync(0xffffffffu, lsum1, 1);
    lsum1 += __shfl_xor_sync(0xffffffffu, lsum1, 2);
    const int part = sp * 4 + kw;
    const int r0 = mw * 16 + g, r1 = r0 + 8;
    if (tg == 0) {
        d_lpart[((size_t)bh * NSPLITG + part) * G_ + r0] = lsum0;
        d_lpart[((size_t)bh * NSPLITG + part) * G_ + r1] = lsum1;
    }
    float* a0 = &d_accpart[(((size_t)bh * NSPLITG + part) * G_ + r0) * HD_];
    float* a1 = &d_accpart[(((size_t)bh * NSPLITG + part) * G_ + r1) * HD_];
    #pragma unroll
    for (int nt = 0; nt < 8; nt++) {
        float2 w0; w0.x = oacc[nt][0]; w0.y = oacc[nt][1];
        float2 w1; w1.x = oacc[nt][2]; w1.y = oacc[nt][3];
        *(float2*)&a0[nt * 8 + tg * 2] = w0;
        *(float2*)&a1[nt * 8 + tg * 2] = w1;
    }
}

__global__ __launch_bounds__(64) void gattn_combine_kernel(float* __restrict__ out)
{
    const int idx = blockIdx.x;
    const int bh = idx >> 5;
    const int g = idx & 31;
    const int b = bh / H_, h = bh % H_;
    const int d = threadIdx.x;
    float l = 0.f, a = 0.f;
    #pragma unroll
    for (int sp = 0; sp < NSPLITG; sp++) {
        l += d_lpart[((size_t)bh * NSPLITG + sp) * G_ + g];
        a += d_accpart[(((size_t)bh * NSPLITG + sp) * G_ + g) * HD_ + d];
    }
    out[(b * S_ + g) * D_ + h * HD_ + d] = a / l;
}

// ---------------------------------------------------------------------------
// Band + global-key attention: 3-stage cp.async pipeline, one barrier/tile.
// grid = (NC*2, H, B); dynamic smem 3 stages x 4 tiles x 8KB.
// ---------------------------------------------------------------------------
#define BTILE 8192
#define BSTAGE (4 * BTILE)
#define BAND_DYN (3 * BSTAGE)     // 98304

__global__ __launch_bounds__(256, 2) void band_mma_kernel(float* __restrict__ out)
{
    extern __shared__ char bsm[];
    const uint32_t sb = smem_u32(bsm);
    const int tid = threadIdx.x, wid = tid >> 5, lane = tid & 31;
    const int c = blockIdx.x >> 1, qh = blockIdx.x & 1;
    const int h = blockIdx.y, b = blockIdx.z;
    const int bh = b * H_ + h;
    const int row0 = c * W_ + qh * 128;
    const int wr = wid * 16;
    const int g = lane >> 2, tg = lane & 3;
    const int pqr0 = qh * 128 + wr + g;

    int tlist[11], ntl = 0;
    tlist[ntl++] = 0;
    #pragma unroll
    for (int t = 1; t < 11; t++) {
        int ebase = qh * 128 + (t - 1) * 64;
        int kl = c * W_ + ebase - W_;
        if (kl + 63 >= 0 && kl < S_) tlist[ntl++] = t;
    }

    uint32_t qhi[4][4], qlo[4][4];
    {
        const __nv_bfloat16* Qh = &d_Qhi[((size_t)bh * S_ + row0 + wr) * 64];
        const __nv_bfloat16* Ql = &d_Qlo[((size_t)bh * S_ + row0 + wr) * 64];
        #pragma unroll
        for (int ks = 0; ks < 4; ks++) {
            int c0 = ks * 16 + tg * 2;
            qhi[ks][0] = *(const uint32_t*)&Qh[g * 64 + c0];
            qhi[ks][1] = *(const uint32_t*)&Qh[(g + 8) * 64 + c0];
            qhi[ks][2] = *(const uint32_t*)&Qh[g * 64 + c0 + 8];
            qhi[ks][3] = *(const uint32_t*)&Qh[(g + 8) * 64 + c0 + 8];
            qlo[ks][0] = *(const uint32_t*)&Ql[g * 64 + c0];
            qlo[ks][1] = *(const uint32_t*)&Ql[(g + 8) * 64 + c0];
            qlo[ks][2] = *(const uint32_t*)&Ql[g * 64 + c0 + 8];
            qlo[ks][3] = *(const uint32_t*)&Ql[(g + 8) * 64 + c0 + 8];
        }
    }

    float oacc[8][4];
    #pragma unroll
    for (int i = 0; i < 8; i++)
        #pragma unroll
        for (int r = 0; r < 4; r++) oacc[i][r] = 0.f;
    float lsum0 = 0.f, lsum1 = 0.f;

    const int lrowA = tid >> 3, lseg = tid & 7;
    const int lrowB = lrowA + 32;

    auto load_tile = [&](int stg, int t) {
        uint32_t base = sb + stg * BSTAGE;
        #pragma unroll
        for (int r = 0; r < 2; r++) {
            int row = r ? lrowB : lrowA;
            int ka = (t == 0) ? row
                              : (c * W_ + qh * 128 + (t - 1) * 64 + row - W_);
            int kr = min(max(ka, 0), S_ - 1);
            uint32_t off = row * 128 + ((lseg ^ (row & 7)) * 16);
            size_t src = ((size_t)bh * S_ + kr) * 64 + lseg * 8;
            CPA16(base + off, &d_Khi[src]);
            CPA16(base + BTILE + off, &d_Klo[src]);
            CPA16(base + 2 * BTILE + off, &d_Vhi[src]);
            CPA16(base + 3 * BTILE + off, &d_Vlo[src]);
        }
        CPA_COMMIT();
    };

    load_tile(0, tlist[0]);
    if (ntl > 1) load_tile(1, tlist[1]);

    int cur = 0;
    #pragma unroll 1
    for (int it = 0; it < ntl; it++) {
        const int t = tlist[it];
        if (it == ntl - 1) CPA_WAIT0(); else CPA_WAIT1();
        __syncthreads();
        if (it + 2 < ntl) {
            int nxt = cur + 2; if (nxt >= 3) nxt -= 3;
            load_tile(nxt, tlist[it + 2]);
        }

        const uint32_t sKhi = sb + cur * BSTAGE;
        const uint32_t sKlo = sKhi + BTILE;
        const uint32_t sVhi = sKhi + 2 * BTILE;
        const uint32_t sVlo = sKhi + 3 * BTILE;
        const int ebase = qh * 128 + (t - 1) * 64;

        const int nhalf = (t == 0) ? 1 : 2;
        for (int hf = 0; hf < nhalf; hf++) {
            const int kb = hf * 32;
            float sc[4][4];
            #pragma unroll
            for (int i = 0; i < 4; i++)
                #pragma unroll
                for (int r = 0; r < 4; r++) sc[i][r] = 0.f;

            #pragma unroll
            for (int ks = 0; ks < 4; ks++) {
                uint32_t kh[2][4], kl[2][4];
                #pragma unroll
                for (int q2 = 0; q2 < 2; q2++) {
                    int row = kb + q2 * 16 + (lane & 7) + ((lane >> 4) << 3);
                    int seg = ks * 2 + ((lane >> 3) & 1);
                    uint32_t addr = row * 128 + ((seg ^ (row & 7)) * 16);
                    LDM4(kh[q2], sKhi + addr);
                    LDM4(kl[q2], sKlo + addr);
                }
                #pragma unroll
                for (int q2 = 0; q2 < 2; q2++)
                    #pragma unroll
                    for (int p = 0; p < 2; p++) {
                        int nt = q2 * 2 + p;
                        MMA16816(sc[nt], qhi[ks], kh[q2][p*2], kh[q2][p*2+1]);
                        MMA16816(sc[nt], qhi[ks], kl[q2][p*2], kl[q2][p*2+1]);
                        MMA16816(sc[nt], qlo[ks], kh[q2][p*2], kh[q2][p*2+1]);
                    }
            }

            uint32_t pah[2][4], pal[2][4];
            #pragma unroll
            for (int nt = 0; nt < 4; nt++) {
                float p00, p01, p10, p11;
                if (t == 0) {
                    p00 = __expf(sc[nt][0]); p01 = __expf(sc[nt][1]);
                    p10 = __expf(sc[nt][2]); p11 = __expf(sc[nt][3]);
                } else {
                    int e0 = ebase + kb + nt * 8 + tg * 2;
                    int e1 = e0 + 1;
                    int ka0 = c * W_ + e0 - W_;
                    int ka1 = ka0 + 1;
                    int pr1 = pqr0 + 8;
                    bool in0 = (ka0 >= 0) && (ka0 < S_);
                    bool in1 = (ka1 >= 0) && (ka1 < S_);
                    p00 = (in0 && e0 >= pqr0 && e0 <= pqr0 + 2*W_) ? __expf(sc[nt][0]) : 0.f;
                    p01 = (in1 && e1 >= pqr0 && e1 <= pqr0 + 2*W_) ? __expf(sc[nt][1]) : 0.f;
                    p10 = (in0 && e0 >= pr1  && e0 <= pr1  + 2*W_) ? __expf(sc[nt][2]) : 0.f;
                    p11 = (in1 && e1 >= pr1  && e1 <= pr1  + 2*W_) ? __expf(sc[nt][3]) : 0.f;
                }
                lsum0 += p00 + p01;
                lsum1 += p10 + p11;
                __nv_bfloat16 h00 = __float2bfloat16(p00);
                __nv_bfloat16 h01 = __float2bfloat16(p01);
                __nv_bfloat16 h10 = __float2bfloat16(p10);
                __nv_bfloat16 h11 = __float2bfloat16(p11);
                __nv_bfloat162 hp0; hp0.x = h00; hp0.y = h01;
                __nv_bfloat162 hp1; hp1.x = h10; hp1.y = h11;
                __nv_bfloat162 lp0;
                lp0.x = __float2bfloat16(p00 - __bfloat162float(h00));
                lp0.y = __float2bfloat16(p01 - __bfloat162float(h01));
                __nv_bfloat162 lp1;
                lp1.x = __float2bfloat16(p10 - __bfloat162float(h10));
                lp1.y = __float2bfloat16(p11 - __bfloat162float(h11));
                pah[nt >> 1][(nt & 1) * 2 + 0] = *(uint32_t*)&hp0;
                pah[nt >> 1][(nt & 1) * 2 + 1] = *(uint32_t*)&hp1;
                pal[nt >> 1][(nt & 1) * 2 + 0] = *(uint32_t*)&lp0;
                pal[nt >> 1][(nt & 1) * 2 + 1] = *(uint32_t*)&lp1;
            }

            #pragma unroll
            for (int ksp = 0; ksp < 2; ksp++) {
                #pragma unroll
                for (int dg = 0; dg < 4; dg++) {
                    uint32_t vh[4], vl[4];
                    int row = kb + ksp * 16 + (lane & 15);
                    int seg = dg * 2 + (lane >> 4);
                    uint32_t addr = row * 128 + ((seg ^ (row & 7)) * 16);
                    LDM4T(vh, sVhi + addr);
                    LDM4T(vl, sVlo + addr);
                    MMA16816(oacc[dg * 2 + 0], pah[ksp], vh[0], vh[1]);
                    MMA16816(oacc[dg * 2 + 0], pal[ksp], vh[0], vh[1]);
                    MMA16816(oacc[dg * 2 + 0], pah[ksp], vl[0], vl[1]);
                    MMA16816(oacc[dg * 2 + 1], pah[ksp], vh[2], vh[3]);
                    MMA16816(oacc[dg * 2 + 1], pal[ksp], vh[2], vh[3]);
                    MMA16816(oacc[dg * 2 + 1], pah[ksp], vl[2], vl[3]);
                }
            }
        }
        cur++; if (cur >= 3) cur -= 3;
    }

    lsum0 += __shfl_xor_sync(0xffffffffu, lsum0, 1);
    lsum0 += __shfl_xor_sync(0xffffffffu, lsum0, 2);
    lsum1 += __shfl_xor_sync(0xffffffffu, lsum1, 1);
    lsum1 += __shfl_xor_sync(0xffffffffu, lsum1, 2);
    float inv0 = 1.f / lsum0, inv1 = 1.f / lsum1;
    float* o0 = &out[(size_t)(b * S_ + row0 + wr + g) * D_ + h * 64];
    float* o1 = o0 + 8 * D_;
    #pragma unroll
    for (int nt = 0; nt < 8; nt++) {
        float2 w0; w0.x = oacc[nt][0] * inv0; w0.y = oacc[nt][1] * inv0;
        float2 w1; w1.x = oacc[nt][2] * inv1; w1.y = oacc[nt][3] * inv1;
        *(float2*)&o0[nt * 8 + tg * 2] = w0;
        *(float2*)&o1[nt * 8 + tg * 2] = w1;
    }
}

// ---------------------------------------------------------------------------
extern "C" void kernel_launch(void* const* d_in, const int* in_sizes, int n_in,
                              void* d_out, int out_size)
{
    const float* hidden = (const float*)d_in[0];
    const float* Wq  = (const float*)d_in[1];
    const float* bq  = (const float*)d_in[2];
    const float* Wk  = (const float*)d_in[3];
    const float* bk  = (const float*)d_in[4];
    const float* Wv  = (const float*)d_in[5];
    const float* bv  = (const float*)d_in[6];
    const float* Wqg = (const float*)d_in[7];
    const float* bqg = (const float*)d_in[8];
    const float* Wkg = (const float*)d_in[9];
    const float* bkg = (const float*)d_in[10];
    const float* Wvg = (const float*)d_in[11];
    const float* bvg = (const float*)d_in[12];
    float* out = (float*)d_out;

    static int configured = 0;
    if (!configured) {
        cudaFuncSetAttribute(gemm_kernel, cudaFuncAttributeMaxDynamicSharedMemorySize, GEMM_DYN);
        cudaFuncSetAttribute(band_mma_kernel, cudaFuncAttributeMaxDynamicSharedMemorySize, BAND_DYN);
        configured = 1;
    }

    convA_kernel<<<(B_*S_*D_)/1024, 256>>>(hidden);                               // 1
    convW_kernel<<<dim3(24, 24, 6), dim3(32, 8)>>>(Wq, Wk, Wv, Wkg, Wvg, Wqg);    // 2

    dim3 ggrid(D_ / 128, (B_ * S_) / 128, 6);
    gemm_kernel<<<ggrid, 256, GEMM_DYN>>>(bq, bk, bv, bkg, bvg, bqg);             // 3

    band_mma_kernel<<<dim3(NC_ * 2, H_, B_), 256, BAND_DYN>>>(out);               // 4
    gattn_mma_kernel<<<dim3(8, H_, B_), 256>>>();                                 // 5
    gattn_combine_kernel<<<B_ * H_ * G_, 64>>>(out);                              // 6
}

// round 12
// speedup vs baseline: 5.2498x; 1.0247x over previous
#include <cuda_runtime.h>
#include <cuda_bf16.h>
#include <cstdint>

// Problem constants
#define B_  2
#define S_  4096
#define D_  768
#define H_  12
#define HD_ 64
#define W_  256
#define NC_ 16
#define G_  32
#define SCALE_ 0.125f

#define BHSD (B_*H_*S_*HD_)   // 6291456
#define NSPLITG 32            // gattn split-K partials (8 sp x 4 kw)

// ---------------------------------------------------------------------------
__device__ __forceinline__ uint32_t smem_u32(const void* p) {
    uint32_t a;
    asm("{ .reg .u64 t; cvta.to.shared.u64 t, %1; cvt.u32.u64 %0, t; }" : "=r"(a) : "l"(p));
    return a;
}
#define CPA16(sa, g) asm volatile("cp.async.cg.shared.global [%0], [%1], 16;" :: "r"(sa), "l"(g))
#define CPA_COMMIT() asm volatile("cp.async.commit_group;" ::: "memory")
#define CPA_WAIT1()  asm volatile("cp.async.wait_group 1;" ::: "memory")
#define CPA_WAIT0()  asm volatile("cp.async.wait_group 0;" ::: "memory")
#define LDM4(r, addr) \
  asm volatile("ldmatrix.sync.aligned.m8n8.x4.shared.b16 {%0,%1,%2,%3}, [%4];" \
    : "=r"((r)[0]), "=r"((r)[1]), "=r"((r)[2]), "=r"((r)[3]) : "r"(addr))
#define LDM4T(r, addr) \
  asm volatile("ldmatrix.sync.aligned.m8n8.x4.trans.shared.b16 {%0,%1,%2,%3}, [%4];" \
    : "=r"((r)[0]), "=r"((r)[1]), "=r"((r)[2]), "=r"((r)[3]) : "r"(addr))
#define MMA16816(d, a, b0, b1) \
  asm volatile("mma.sync.aligned.m16n8k16.row.col.f32.bf16.bf16.f32 " \
    "{%0,%1,%2,%3}, {%4,%5,%6,%7}, {%8,%9}, {%0,%1,%2,%3};" \
    : "+f"((d)[0]), "+f"((d)[1]), "+f"((d)[2]), "+f"((d)[3]) \
    : "r"((a)[0]), "r"((a)[1]), "r"((a)[2]), "r"((a)[3]), "r"(b0), "r"(b1))

// 64B-row swizzle: seg' = seg ^ ((row>>1)&3)  (conflict-free for ldmatrix + cp.async)
#define SWZ64(row, seg) ((uint32_t)((row) * 64 + ((((seg) ^ ((row) >> 1)) & 3) * 16)))

// ---------------------------------------------------------------------------
// Device scratch (bf16 hi/lo everywhere the tensor cores touch)
__device__ __nv_bfloat16 d_Qhi[BHSD], d_Qlo[BHSD];
__device__ __nv_bfloat16 d_Khi[BHSD], d_Klo[BHSD];
__device__ __nv_bfloat16 d_Vhi[BHSD], d_Vlo[BHSD];
__device__ __nv_bfloat16 d_Kghi[BHSD], d_Kglo[BHSD];
__device__ __nv_bfloat16 d_Vghi[BHSD], d_Vglo[BHSD];
__device__ __nv_bfloat16 d_qghi[B_*H_*G_*HD_], d_qglo[B_*H_*G_*HD_];
__device__ __nv_bfloat16 d_Ahi[B_*S_*D_];
__device__ __nv_bfloat16 d_Alo[B_*S_*D_];
__device__ __nv_bfloat16 d_Whi[6][D_*D_];   // transposed [n][k]
__device__ __nv_bfloat16 d_Wlo[6][D_*D_];
__device__ float d_lpart[B_*H_*NSPLITG*G_];
__device__ float d_accpart[B_*H_*NSPLITG*G_*HD_];

// ---------------------------------------------------------------------------
// Prepass: hidden -> bf16 hi/lo
__global__ __launch_bounds__(256) void convA_kernel(const float* __restrict__ A)
{
    int i = (blockIdx.x * 256 + threadIdx.x) * 4;
    float4 a = *(const float4*)&A[i];
    float av[4] = {a.x, a.y, a.z, a.w};
    __nv_bfloat16 h[4], l[4];
    #pragma unroll
    for (int j = 0; j < 4; j++) {
        h[j] = __float2bfloat16(av[j]);
        l[j] = __float2bfloat16(av[j] - __bfloat162float(h[j]));
    }
    *(uint2*)&d_Ahi[i] = *(uint2*)h;
    *(uint2*)&d_Alo[i] = *(uint2*)l;
}

// Prepass (fused over 6 weights): W[k][n] -> Wt_hi/lo[n][k] bf16
__global__ __launch_bounds__(256) void convW_kernel(
    const float* __restrict__ W0, const float* __restrict__ W1,
    const float* __restrict__ W2, const float* __restrict__ W3,
    const float* __restrict__ W4, const float* __restrict__ W5)
{
    __shared__ float t[32][33];
    const int which = blockIdx.z;
    const float* __restrict__ W = (which == 0) ? W0 : (which == 1) ? W1
                                : (which == 2) ? W2 : (which == 3) ? W3
                                : (which == 4) ? W4 : W5;
    const int n0 = blockIdx.x * 32, k0 = blockIdx.y * 32;
    const int tx = threadIdx.x, ty = threadIdx.y;   // (32, 8)
    #pragma unroll
    for (int r = 0; r < 32; r += 8)
        t[ty + r][tx] = W[(k0 + ty + r) * D_ + n0 + tx];
    __syncthreads();
    #pragma unroll
    for (int r = 0; r < 32; r += 8) {
        float v = t[tx][ty + r];
        __nv_bfloat16 hh = __float2bfloat16(v);
        __nv_bfloat16 ll = __float2bfloat16(v - __bfloat162float(hh));
        d_Whi[which][(n0 + ty + r) * D_ + k0 + tx] = hh;
        d_Wlo[which][(n0 + ty + r) * D_ + k0 + tx] = ll;
    }
}

// ---------------------------------------------------------------------------
// Fused projection GEMMs on mma.sync, hi/lo 3-term, 3-stage cp.async pipeline,
// swizzled 64B smem rows, ONE barrier per K-chunk.
// grid = (6, 64, 6). z = which; z==5 (qg) only runs y==0 / y==32.
// ---------------------------------------------------------------------------
#define GTILE 8192                 // 128 rows x 64B, swizzled
#define GSTAGE (4 * GTILE)         // 4 operands per stage
#define GEMM_DYN (3 * GSTAGE)      // 98304

__global__ __launch_bounds__(256, 2) void gemm_kernel(
    const float* __restrict__ bq,  const float* __restrict__ bk,
    const float* __restrict__ bv,  const float* __restrict__ bkg,
    const float* __restrict__ bvg, const float* __restrict__ bqg)
{
    const int which = blockIdx.z;
    if (which == 5 && blockIdx.y != 0 && blockIdx.y != 32) return;
    extern __shared__ char smraw[];
    const uint32_t sb = smem_u32(smraw);
    const int tid = threadIdx.x, wid = tid >> 5, lane = tid & 31;
    const int mw = wid & 3, nw = wid >> 2;
    const int n0 = blockIdx.x * 128;
    const int m0 = blockIdx.y * 128;
    const float* bias = (which == 0) ? bq : (which == 1) ? bk : (which == 2) ? bv
                       : (which == 3) ? bkg : (which == 4) ? bvg : bqg;
    const __nv_bfloat16* __restrict__ Ahi = d_Ahi;
    const __nv_bfloat16* __restrict__ Alo = d_Alo;
    const __nv_bfloat16* __restrict__ Whi = d_Whi[which];
    const __nv_bfloat16* __restrict__ Wlo = d_Wlo[which];

    float acc[2][8][4];
    #pragma unroll
    for (int mt = 0; mt < 2; mt++)
        #pragma unroll
        for (int nt = 0; nt < 8; nt++)
            #pragma unroll
            for (int r = 0; r < 4; r++) acc[mt][nt][r] = 0.f;

    const int lrow = tid >> 2, lch = tid & 3;     // 64 rows x 4 segs
    const int lrow2 = lrow + 64;
    const uint32_t o1 = SWZ64(lrow, lch), o2 = SWZ64(lrow2, lch);

    auto load_chunk = [&](int buf, int k0) {
        uint32_t base = sb + buf * GSTAGE;
        CPA16(base + o1, &Ahi[(m0 + lrow) * D_ + k0 + lch * 8]);
        CPA16(base + o2, &Ahi[(m0 + lrow2) * D_ + k0 + lch * 8]);
        base += GTILE;
        CPA16(base + o1, &Alo[(m0 + lrow) * D_ + k0 + lch * 8]);
        CPA16(base + o2, &Alo[(m0 + lrow2) * D_ + k0 + lch * 8]);
        base += GTILE;
        CPA16(base + o1, &Whi[(n0 + lrow) * D_ + k0 + lch * 8]);
        CPA16(base + o2, &Whi[(n0 + lrow2) * D_ + k0 + lch * 8]);
        base += GTILE;
        CPA16(base + o1, &Wlo[(n0 + lrow) * D_ + k0 + lch * 8]);
        CPA16(base + o2, &Wlo[(n0 + lrow2) * D_ + k0 + lch * 8]);
        CPA_COMMIT();
    };

    load_chunk(0, 0);
    load_chunk(1, 32);

    int cur = 0;
    #pragma unroll 1
    for (int c = 0; c < 24; c++) {
        if (c == 23) CPA_WAIT0(); else CPA_WAIT1();
        __syncthreads();
        if (c + 2 < 24) {
            int nxt = cur + 2; if (nxt >= 3) nxt -= 3;
            load_chunk(nxt, (c + 2) * 32);
        }

        const uint32_t aBase  = sb + cur * GSTAGE;
        const uint32_t alBase = aBase + GTILE;
        const uint32_t bBase  = aBase + 2 * GTILE;
        const uint32_t blBase = aBase + 3 * GTILE;

        #pragma unroll
        for (int ks = 0; ks < 2; ks++) {
            uint32_t ahi[2][4], alo[2][4];
            const int aseg = ks * 2 + ((lane >> 4) & 1);
            #pragma unroll
            for (int mt = 0; mt < 2; mt++) {
                int row = mw * 32 + mt * 16 + (lane & 15);
                LDM4(ahi[mt], aBase + SWZ64(row, aseg));
                LDM4(alo[mt], alBase + SWZ64(row, aseg));
            }
            const int bseg = ks * 2 + ((lane >> 3) & 1);
            #pragma unroll
            for (int nh = 0; nh < 2; nh++) {
                uint32_t bhi[2][4], blo[2][4];
                #pragma unroll
                for (int q = 0; q < 2; q++) {
                    int row = nw * 64 + nh * 32 + q * 16 + (lane & 7) + ((lane >> 4) << 3);
                    LDM4(bhi[q], bBase + SWZ64(row, bseg));
                    LDM4(blo[q], blBase + SWZ64(row, bseg));
                }
                #pragma unroll
                for (int mt = 0; mt < 2; mt++)
                    #pragma unroll
                    for (int q = 0; q < 2; q++)
                        #pragma unroll
                        for (int p = 0; p < 2; p++) {
                            int nt = nh * 4 + q * 2 + p;
                            MMA16816(acc[mt][nt], ahi[mt], bhi[q][p*2], bhi[q][p*2+1]);
                            MMA16816(acc[mt][nt], ahi[mt], blo[q][p*2], blo[q][p*2+1]);
                            MMA16816(acc[mt][nt], alo[mt], bhi[q][p*2], bhi[q][p*2+1]);
                        }
            }
        }
        cur++; if (cur >= 3) cur -= 3;
    }

    // Epilogue: bf16 hi/lo split stores
    const int g = lane >> 2, tg = lane & 3;
    #pragma unroll
    for (int mt = 0; mt < 2; mt++)
        #pragma unroll
        for (int half = 0; half < 2; half++) {
            int m = m0 + mw * 32 + mt * 16 + g + half * 8;
            int b = m >> 12, s = m & 4095;
            #pragma unroll
            for (int nt = 0; nt < 8; nt++) {
                int n = n0 + nw * 64 + nt * 8 + tg * 2;
                float v0 = acc[mt][nt][half * 2 + 0] + bias[n];
                float v1 = acc[mt][nt][half * 2 + 1] + bias[n + 1];
                int h = n >> 6, hd = n & 63;
                if (which == 0 || which == 5) { v0 *= SCALE_; v1 *= SCALE_; }
                if (which == 5 && s >= G_) continue;
                __nv_bfloat16 h0 = __float2bfloat16(v0);
                __nv_bfloat16 h1 = __float2bfloat16(v1);
                __nv_bfloat16 l0 = __float2bfloat16(v0 - __bfloat162float(h0));
                __nv_bfloat16 l1 = __float2bfloat16(v1 - __bfloat162float(h1));
                __nv_bfloat162 hp; hp.x = h0; hp.y = h1;
                __nv_bfloat162 lp; lp.x = l0; lp.y = l1;
                size_t bidx = ((size_t)(b * H_ + h) * S_ + s) * HD_ + hd;
                switch (which) {
                    case 0:
                        *(__nv_bfloat162*)&d_Qhi[bidx] = hp;
                        *(__nv_bfloat162*)&d_Qlo[bidx] = lp; break;
                    case 1:
                        *(__nv_bfloat162*)&d_Khi[bidx] = hp;
                        *(__nv_bfloat162*)&d_Klo[bidx] = lp; break;
                    case 2:
                        *(__nv_bfloat162*)&d_Vhi[bidx] = hp;
                        *(__nv_bfloat162*)&d_Vlo[bidx] = lp; break;
                    case 3:
                        *(__nv_bfloat162*)&d_Kghi[bidx] = hp;
                        *(__nv_bfloat162*)&d_Kglo[bidx] = lp; break;
                    case 4:
                        *(__nv_bfloat162*)&d_Vghi[bidx] = hp;
                        *(__nv_bfloat162*)&d_Vglo[bidx] = lp; break;
                    default: {
                        size_t qidx = ((size_t)(b * H_ + h) * G_ + s) * HD_ + hd;
                        *(__nv_bfloat162*)&d_qghi[qidx] = hp;
                        *(__nv_bfloat162*)&d_qglo[qidx] = lp; break;
                    }
                }
            }
        }
}

// ---------------------------------------------------------------------------
// Global attention on mma.sync (unchanged; 21 us).
// ---------------------------------------------------------------------------
__global__ __launch_bounds__(256, 2) void gattn_mma_kernel()
{
    __shared__ __align__(16) char kh_sm[16384];
    __shared__ __align__(16) char kl_sm[16384];
    __shared__ __align__(16) char vh_sm[16384];
    __shared__ __align__(16) char vl_sm[16384];
    const uint32_t sKhi = smem_u32(kh_sm), sKlo = smem_u32(kl_sm);
    const uint32_t sVhi = smem_u32(vh_sm), sVlo = smem_u32(vl_sm);
    const int tid = threadIdx.x, wid = tid >> 5, lane = tid & 31;
    const int sp = blockIdx.x, h = blockIdx.y, b = blockIdx.z;
    const int bh = b * H_ + h;
    const int mw = wid & 1, kw = wid >> 1;
    const int g = lane >> 2, tg = lane & 3;

    uint32_t qhi[4][4], qlo[4][4];
    {
        const __nv_bfloat16* Qh = &d_qghi[((size_t)bh * G_ + mw * 16) * 64];
        const __nv_bfloat16* Ql = &d_qglo[((size_t)bh * G_ + mw * 16) * 64];
        #pragma unroll
        for (int ks = 0; ks < 4; ks++) {
            int c0 = ks * 16 + tg * 2;
            qhi[ks][0] = *(const uint32_t*)&Qh[g * 64 + c0];
            qhi[ks][1] = *(const uint32_t*)&Qh[(g + 8) * 64 + c0];
            qhi[ks][2] = *(const uint32_t*)&Qh[g * 64 + c0 + 8];
            qhi[ks][3] = *(const uint32_t*)&Qh[(g + 8) * 64 + c0 + 8];
            qlo[ks][0] = *(const uint32_t*)&Ql[g * 64 + c0];
            qlo[ks][1] = *(const uint32_t*)&Ql[(g + 8) * 64 + c0];
            qlo[ks][2] = *(const uint32_t*)&Ql[g * 64 + c0 + 8];
            qlo[ks][3] = *(const uint32_t*)&Ql[(g + 8) * 64 + c0 + 8];
        }
    }

    float oacc[8][4];
    #pragma unroll
    for (int i = 0; i < 8; i++)
        #pragma unroll
        for (int r = 0; r < 4; r++) oacc[i][r] = 0.f;
    float lsum0 = 0.f, lsum1 = 0.f;

    #pragma unroll 1
    for (int ch = 0; ch < 4; ch++) {
        __syncthreads();
        #pragma unroll
        for (int r = 0; r < 4; r++) {
            int idx = tid + r * 256;
            int row = idx >> 3, seg = idx & 7;
            uint32_t off = row * 128 + ((seg ^ (row & 7)) * 16);
            size_t src = ((size_t)bh * S_ + sp * 512 + ch * 128 + row) * 64 + seg * 8;
            CPA16(sKhi + off, &d_Kghi[src]);
            CPA16(sKlo + off, &d_Kglo[src]);
            CPA16(sVhi + off, &d_Vghi[src]);
            CPA16(sVlo + off, &d_Vglo[src]);
        }
        CPA_COMMIT(); CPA_WAIT0();
        __syncthreads();

        const int kb = kw * 32;
        float sc[4][4];
        #pragma unroll
        for (int i = 0; i < 4; i++)
            #pragma unroll
            for (int r = 0; r < 4; r++) sc[i][r] = 0.f;

        #pragma unroll
        for (int ks = 0; ks < 4; ks++) {
            uint32_t kh[2][4], kl[2][4];
            #pragma unroll
            for (int q2 = 0; q2 < 2; q2++) {
                int row = kb + q2 * 16 + (lane & 7) + ((lane >> 4) << 3);
                int seg = ks * 2 + ((lane >> 3) & 1);
                uint32_t addr = row * 128 + ((seg ^ (row & 7)) * 16);
                LDM4(kh[q2], sKhi + addr);
                LDM4(kl[q2], sKlo + addr);
            }
            #pragma unroll
            for (int q2 = 0; q2 < 2; q2++)
                #pragma unroll
                for (int p = 0; p < 2; p++) {
                    int nt = q2 * 2 + p;
                    MMA16816(sc[nt], qhi[ks], kh[q2][p*2], kh[q2][p*2+1]);
                    MMA16816(sc[nt], qhi[ks], kl[q2][p*2], kl[q2][p*2+1]);
                    MMA16816(sc[nt], qlo[ks], kh[q2][p*2], kh[q2][p*2+1]);
                }
        }

        uint32_t pah[2][4], pal[2][4];
        #pragma unroll
        for (int nt = 0; nt < 4; nt++) {
            float p00 = __expf(sc[nt][0]), p01 = __expf(sc[nt][1]);
            float p10 = __expf(sc[nt][2]), p11 = __expf(sc[nt][3]);
            lsum0 += p00 + p01;
            lsum1 += p10 + p11;
            __nv_bfloat16 h00 = __float2bfloat16(p00);
            __nv_bfloat16 h01 = __float2bfloat16(p01);
            __nv_bfloat16 h10 = __float2bfloat16(p10);
            __nv_bfloat16 h11 = __float2bfloat16(p11);
            __nv_bfloat162 hp0; hp0.x = h00; hp0.y = h01;
            __nv_bfloat162 hp1; hp1.x = h10; hp1.y = h11;
            __nv_bfloat162 lp0;
            lp0.x = __float2bfloat16(p00 - __bfloat162float(h00));
            lp0.y = __float2bfloat16(p01 - __bfloat162float(h01));
            __nv_bfloat162 lp1;
            lp1.x = __float2bfloat16(p10 - __bfloat162float(h10));
            lp1.y = __float2bfloat16(p11 - __bfloat162float(h11));
            pah[nt >> 1][(nt & 1) * 2 + 0] = *(uint32_t*)&hp0;
            pah[nt >> 1][(nt & 1) * 2 + 1] = *(uint32_t*)&hp1;
            pal[nt >> 1][(nt & 1) * 2 + 0] = *(uint32_t*)&lp0;
            pal[nt >> 1][(nt & 1) * 2 + 1] = *(uint32_t*)&lp1;
        }

        #pragma unroll
        for (int ksp = 0; ksp < 2; ksp++) {
            #pragma unroll
            for (int dg = 0; dg < 4; dg++) {
                uint32_t vh[4], vl[4];
                int row = kb + ksp * 16 + (lane & 15);
                int seg = dg * 2 + (lane >> 4);
                uint32_t addr = row * 128 + ((seg ^ (row & 7)) * 16);
                LDM4T(vh, sVhi + addr);
                LDM4T(vl, sVlo + addr);
                MMA16816(oacc[dg * 2 + 0], pah[ksp], vh[0], vh[1]);
                MMA16816(oacc[dg * 2 + 0], pal[ksp], vh[0], vh[1]);
                MMA16816(oacc[dg * 2 + 0], pah[ksp], vl[0], vl[1]);
                MMA16816(oacc[dg * 2 + 1], pah[ksp], vh[2], vh[3]);
                MMA16816(oacc[dg * 2 + 1], pal[ksp], vh[2], vh[3]);
                MMA16816(oacc[dg * 2 + 1], pah[ksp], vl[2], vl[3]);
            }
        }
    }

    lsum0 += __shfl_xor_sync(0xffffffffu, lsum0, 1);
    lsum0 += __shfl_xor_sync(0xffffffffu, lsum0, 2);
    lsum1 += __shfl_xor_sync(0xffffffffu, lsum1, 1);
    lsum1 += __shfl_xor_sync(0xffffffffu, lsum1, 2);
    const int part = sp * 4 + kw;
    const int r0 = mw * 16 + g, r1 = r0 + 8;
    if (tg == 0) {
        d_lpart[((size_t)bh * NSPLITG + part) * G_ + r0] = lsum0;
        d_lpart[((size_t)bh * NSPLITG + part) * G_ + r1] = lsum1;
    }
    float* a0 = &d_accpart[(((size_t)bh * NSPLITG + part) * G_ + r0) * HD_];
    float* a1 = &d_accpart[(((size_t)bh * NSPLITG + part) * G_ + r1) * HD_];
    #pragma unroll
    for (int nt = 0; nt < 8; nt++) {
        float2 w0; w0.x = oacc[nt][0]; w0.y = oacc[nt][1];
        float2 w1; w1.x = oacc[nt][2]; w1.y = oacc[nt][3];
        *(float2*)&a0[nt * 8 + tg * 2] = w0;
        *(float2*)&a1[nt * 8 + tg * 2] = w1;
    }
}

__global__ __launch_bounds__(64) void gattn_combine_kernel(float* __restrict__ out)
{
    const int idx = blockIdx.x;
    const int bh = idx >> 5;
    const int g = idx & 31;
    const int b = bh / H_, h = bh % H_;
    const int d = threadIdx.x;
    float l = 0.f, a = 0.f;
    #pragma unroll
    for (int sp = 0; sp < NSPLITG; sp++) {
        l += d_lpart[((size_t)bh * NSPLITG + sp) * G_ + g];
        a += d_accpart[(((size_t)bh * NSPLITG + sp) * G_ + g) * HD_ + d];
    }
    out[(b * S_ + g) * D_ + h * HD_ + d] = a / l;
}

// ---------------------------------------------------------------------------
// Band + global-key attention: 3-stage cp.async pipeline, one barrier/tile,
// warp-uniform unmasked fast path + hoisted per-thread mask bounds.
// grid = (NC*2, H, B); dynamic smem 3 stages x 4 tiles x 8KB.
// ---------------------------------------------------------------------------
#define BTILE 8192
#define BSTAGE (4 * BTILE)
#define BAND_DYN (3 * BSTAGE)     // 98304

__global__ __launch_bounds__(256, 2) void band_mma_kernel(float* __restrict__ out)
{
    extern __shared__ char bsm[];
    const uint32_t sb = smem_u32(bsm);
    const int tid = threadIdx.x, wid = tid >> 5, lane = tid & 31;
    const int c = blockIdx.x >> 1, qh = blockIdx.x & 1;
    const int h = blockIdx.y, b = blockIdx.z;
    const int bh = b * H_ + h;
    const int row0 = c * W_ + qh * 128;
    const int wr = wid * 16;
    const int g = lane >> 2, tg = lane & 3;
    const int pqr0 = qh * 128 + wr + g;
    const int pqr1 = pqr0 + 8;
    const int wbase = qh * 128 + wr;            // warp min pq

    // per-thread e-bounds (t-invariant): valid <=> lo <= e <= hi
    const int eklo = W_ - c * W_;               // kabs >= 0
    const int ekhi = S_ - 1 + W_ - c * W_;      // kabs <= S-1
    const int lo0 = max(pqr0, eklo), hi0 = min(pqr0 + 2 * W_, ekhi);
    const int lo1 = max(pqr1, eklo), hi1 = min(pqr1 + 2 * W_, ekhi);

    int tlist[11], ntl = 0;
    tlist[ntl++] = 0;
    #pragma unroll
    for (int t = 1; t < 11; t++) {
        int ebase = qh * 128 + (t - 1) * 64;
        int kl = c * W_ + ebase - W_;
        if (kl + 63 >= 0 && kl < S_) tlist[ntl++] = t;
    }

    uint32_t qhi[4][4], qlo[4][4];
    {
        const __nv_bfloat16* Qh = &d_Qhi[((size_t)bh * S_ + row0 + wr) * 64];
        const __nv_bfloat16* Ql = &d_Qlo[((size_t)bh * S_ + row0 + wr) * 64];
        #pragma unroll
        for (int ks = 0; ks < 4; ks++) {
            int c0 = ks * 16 + tg * 2;
            qhi[ks][0] = *(const uint32_t*)&Qh[g * 64 + c0];
            qhi[ks][1] = *(const uint32_t*)&Qh[(g + 8) * 64 + c0];
            qhi[ks][2] = *(const uint32_t*)&Qh[g * 64 + c0 + 8];
            qhi[ks][3] = *(const uint32_t*)&Qh[(g + 8) * 64 + c0 + 8];
            qlo[ks][0] = *(const uint32_t*)&Ql[g * 64 + c0];
            qlo[ks][1] = *(const uint32_t*)&Ql[(g + 8) * 64 + c0];
            qlo[ks][2] = *(const uint32_t*)&Ql[g * 64 + c0 + 8];
            qlo[ks][3] = *(const uint32_t*)&Ql[(g + 8) * 64 + c0 + 8];
        }
    }

    float oacc[8][4];
    #pragma unroll
    for (int i = 0; i < 8; i++)
        #pragma unroll
        for (int r = 0; r < 4; r++) oacc[i][r] = 0.f;
    float lsum0 = 0.f, lsum1 = 0.f;

    const int lrowA = tid >> 3, lseg = tid & 7;
    const int lrowB = lrowA + 32;

    auto load_tile = [&](int stg, int t) {
        uint32_t base = sb + stg * BSTAGE;
        #pragma unroll
        for (int r = 0; r < 2; r++) {
            int row = r ? lrowB : lrowA;
            int ka = (t == 0) ? row
                              : (c * W_ + qh * 128 + (t - 1) * 64 + row - W_);
            int kr = min(max(ka, 0), S_ - 1);
            uint32_t off = row * 128 + ((lseg ^ (row & 7)) * 16);
            size_t src = ((size_t)bh * S_ + kr) * 64 + lseg * 8;
            CPA16(base + off, &d_Khi[src]);
            CPA16(base + BTILE + off, &d_Klo[src]);
            CPA16(base + 2 * BTILE + off, &d_Vhi[src]);
            CPA16(base + 3 * BTILE + off, &d_Vlo[src]);
        }
        CPA_COMMIT();
    };

    load_tile(0, tlist[0]);
    if (ntl > 1) load_tile(1, tlist[1]);

    int cur = 0;
    #pragma unroll 1
    for (int it = 0; it < ntl; it++) {
        const int t = tlist[it];
        if (it == ntl - 1) CPA_WAIT0(); else CPA_WAIT1();
        __syncthreads();
        if (it + 2 < ntl) {
            int nxt = cur + 2; if (nxt >= 3) nxt -= 3;
            load_tile(nxt, tlist[it + 2]);
        }

        const uint32_t sKhi = sb + cur * BSTAGE;
        const uint32_t sKlo = sKhi + BTILE;
        const uint32_t sVhi = sKhi + 2 * BTILE;
        const uint32_t sVlo = sKhi + 3 * BTILE;
        const int ebase = qh * 128 + (t - 1) * 64;

        const int nhalf = (t == 0) ? 1 : 2;
        for (int hf = 0; hf < nhalf; hf++) {
            const int kb = hf * 32;
            float sc[4][4];
            #pragma unroll
            for (int i = 0; i < 4; i++)
                #pragma unroll
                for (int r = 0; r < 4; r++) sc[i][r] = 0.f;

            #pragma unroll
            for (int ks = 0; ks < 4; ks++) {
                uint32_t kh[2][4], kl[2][4];
                #pragma unroll
                for (int q2 = 0; q2 < 2; q2++) {
                    int row = kb + q2 * 16 + (lane & 7) + ((lane >> 4) << 3);
                    int seg = ks * 2 + ((lane >> 3) & 1);
                    uint32_t addr = row * 128 + ((seg ^ (row & 7)) * 16);
                    LDM4(kh[q2], sKhi + addr);
                    LDM4(kl[q2], sKlo + addr);
                }
                #pragma unroll
                for (int q2 = 0; q2 < 2; q2++)
                    #pragma unroll
                    for (int p = 0; p < 2; p++) {
                        int nt = q2 * 2 + p;
                        MMA16816(sc[nt], qhi[ks], kh[q2][p*2], kh[q2][p*2+1]);
                        MMA16816(sc[nt], qhi[ks], kl[q2][p*2], kl[q2][p*2+1]);
                        MMA16816(sc[nt], qlo[ks], kh[q2][p*2], kh[q2][p*2+1]);
                    }
            }

            // warp-uniform: is this 32-key segment fully valid for every
            // (q-row, e) pair this warp owns?
            const int minE = ebase + kb, maxE = minE + 31;
            const bool full = (t != 0) &&
                (minE >= wbase + 15) && (maxE <= wbase + 2 * W_) &&
                (minE >= eklo) && (maxE <= ekhi);

            uint32_t pah[2][4], pal[2][4];
            if (t == 0 || full) {
                // fast path: no masking at all
                #pragma unroll
                for (int nt = 0; nt < 4; nt++) {
                    float p00 = __expf(sc[nt][0]), p01 = __expf(sc[nt][1]);
                    float p10 = __expf(sc[nt][2]), p11 = __expf(sc[nt][3]);
                    lsum0 += p00 + p01;
                    lsum1 += p10 + p11;
                    __nv_bfloat16 h00 = __float2bfloat16(p00);
                    __nv_bfloat16 h01 = __float2bfloat16(p01);
                    __nv_bfloat16 h10 = __float2bfloat16(p10);
                    __nv_bfloat16 h11 = __float2bfloat16(p11);
                    __nv_bfloat162 hp0; hp0.x = h00; hp0.y = h01;
                    __nv_bfloat162 hp1; hp1.x = h10; hp1.y = h11;
                    __nv_bfloat162 lp0;
                    lp0.x = __float2bfloat16(p00 - __bfloat162float(h00));
                    lp0.y = __float2bfloat16(p01 - __bfloat162float(h01));
                    __nv_bfloat162 lp1;
                    lp1.x = __float2bfloat16(p10 - __bfloat162float(h10));
                    lp1.y = __float2bfloat16(p11 - __bfloat162float(h11));
                    pah[nt >> 1][(nt & 1) * 2 + 0] = *(uint32_t*)&hp0;
                    pah[nt >> 1][(nt & 1) * 2 + 1] = *(uint32_t*)&hp1;
                    pal[nt >> 1][(nt & 1) * 2 + 0] = *(uint32_t*)&lp0;
                    pal[nt >> 1][(nt & 1) * 2 + 1] = *(uint32_t*)&lp1;
                }
            } else {
                // masked path: 2 compares per element against hoisted bounds
                #pragma unroll
                for (int nt = 0; nt < 4; nt++) {
                    int e0 = ebase + kb + nt * 8 + tg * 2;
                    int e1 = e0 + 1;
                    float p00 = (e0 >= lo0 && e0 <= hi0) ? __expf(sc[nt][0]) : 0.f;
                    float p01 = (e1 >= lo0 && e1 <= hi0) ? __expf(sc[nt][1]) : 0.f;
                    float p10 = (e0 >= lo1 && e0 <= hi1) ? __expf(sc[nt][2]) : 0.f;
                    float p11 = (e1 >= lo1 && e1 <= hi1) ? __expf(sc[nt][3]) : 0.f;
                    lsum0 += p00 + p01;
                    lsum1 += p10 + p11;
                    __nv_bfloat16 h00 = __float2bfloat16(p00);
                    __nv_bfloat16 h01 = __float2bfloat16(p01);
                    __nv_bfloat16 h10 = __float2bfloat16(p10);
                    __nv_bfloat16 h11 = __float2bfloat16(p11);
                    __nv_bfloat162 hp0; hp0.x = h00; hp0.y = h01;
                    __nv_bfloat162 hp1; hp1.x = h10; hp1.y = h11;
                    __nv_bfloat162 lp0;
                    lp0.x = __float2bfloat16(p00 - __bfloat162float(h00));
                    lp0.y = __float2bfloat16(p01 - __bfloat162float(h01));
                    __nv_bfloat162 lp1;
                    lp1.x = __float2bfloat16(p10 - __bfloat162float(h10));
                    lp1.y = __float2bfloat16(p11 - __bfloat162float(h11));
                    pah[nt >> 1][(nt & 1) * 2 + 0] = *(uint32_t*)&hp0;
                    pah[nt >> 1][(nt & 1) * 2 + 1] = *(uint32_t*)&hp1;
                    pal[nt >> 1][(nt & 1) * 2 + 0] = *(uint32_t*)&lp0;
                    pal[nt >> 1][(nt & 1) * 2 + 1] = *(uint32_t*)&lp1;
                }
            }

            #pragma unroll
            for (int ksp = 0; ksp < 2; ksp++) {
                #pragma unroll
                for (int dg = 0; dg < 4; dg++) {
                    uint32_t vh[4], vl[4];
                    int row = kb + ksp * 16 + (lane & 15);
                    int seg = dg * 2 + (lane >> 4);
                    uint32_t addr = row * 128 + ((seg ^ (row & 7)) * 16);
                    LDM4T(vh, sVhi + addr);
                    LDM4T(vl, sVlo + addr);
                    MMA16816(oacc[dg * 2 + 0], pah[ksp], vh[0], vh[1]);
                    MMA16816(oacc[dg * 2 + 0], pal[ksp], vh[0], vh[1]);
                    MMA16816(oacc[dg * 2 + 0], pah[ksp], vl[0], vl[1]);
                    MMA16816(oacc[dg * 2 + 1], pah[ksp], vh[2], vh[3]);
                    MMA16816(oacc[dg * 2 + 1], pal[ksp], vh[2], vh[3]);
                    MMA16816(oacc[dg * 2 + 1], pah[ksp], vl[2], vl[3]);
                }
            }
        }
        cur++; if (cur >= 3) cur -= 3;
    }

    lsum0 += __shfl_xor_sync(0xffffffffu, lsum0, 1);
    lsum0 += __shfl_xor_sync(0xffffffffu, lsum0, 2);
    lsum1 += __shfl_xor_sync(0xffffffffu, lsum1, 1);
    lsum1 += __shfl_xor_sync(0xffffffffu, lsum1, 2);
    float inv0 = 1.f / lsum0, inv1 = 1.f / lsum1;
    float* o0 = &out[(size_t)(b * S_ + row0 + wr + g) * D_ + h * 64];
    float* o1 = o0 + 8 * D_;
    #pragma unroll
    for (int nt = 0; nt < 8; nt++) {
        float2 w0; w0.x = oacc[nt][0] * inv0; w0.y = oacc[nt][1] * inv0;
        float2 w1; w1.x = oacc[nt][2] * inv1; w1.y = oacc[nt][3] * inv1;
        *(float2*)&o0[nt * 8 + tg * 2] = w0;
        *(float2*)&o1[nt * 8 + tg * 2] = w1;
    }
}

// ---------------------------------------------------------------------------
extern "C" void kernel_launch(void* const* d_in, const int* in_sizes, int n_in,
                              void* d_out, int out_size)
{
    const float* hidden = (const float*)d_in[0];
    const float* Wq  = (const float*)d_in[1];
    const float* bq  = (const float*)d_in[2];
    const float* Wk  = (const float*)d_in[3];
    const float* bk  = (const float*)d_in[4];
    const float* Wv  = (const float*)d_in[5];
    const float* bv  = (const float*)d_in[6];
    const float* Wqg = (const float*)d_in[7];
    const float* bqg = (const float*)d_in[8];
    const float* Wkg = (const float*)d_in[9];
    const float* bkg = (const float*)d_in[10];
    const float* Wvg = (const float*)d_in[11];
    const float* bvg = (const float*)d_in[12];
    float* out = (float*)d_out;

    static int configured = 0;
    if (!configured) {
        cudaFuncSetAttribute(gemm_kernel, cudaFuncAttributeMaxDynamicSharedMemorySize, GEMM_DYN);
        cudaFuncSetAttribute(band_mma_kernel, cudaFuncAttributeMaxDynamicSharedMemorySize, BAND_DYN);
        configured = 1;
    }

    convA_kernel<<<(B_*S_*D_)/1024, 256>>>(hidden);                               // 1
    convW_kernel<<<dim3(24, 24, 6), dim3(32, 8)>>>(Wq, Wk, Wv, Wkg, Wvg, Wqg);    // 2

    dim3 ggrid(D_ / 128, (B_ * S_) / 128, 6);
    gemm_kernel<<<ggrid, 256, GEMM_DYN>>>(bq, bk, bv, bkg, bvg, bqg);             // 3

    band_mma_kernel<<<dim3(NC_ * 2, H_, B_), 256, BAND_DYN>>>(out);               // 4 <- profiled
    gattn_mma_kernel<<<dim3(8, H_, B_), 256>>>();                                 // 5
    gattn_combine_kernel<<<B_ * H_ * G_, 64>>>(out);                              // 6
}

// round 13
// speedup vs baseline: 5.3313x; 1.0155x over previous
#include <cuda_runtime.h>
#include <cuda_bf16.h>
#include <cstdint>

// Problem constants
#define B_  2
#define S_  4096
#define D_  768
#define H_  12
#define HD_ 64
#define W_  256
#define NC_ 16
#define G_  32
#define SCALE_ 0.125f

#define BHSD (B_*H_*S_*HD_)   // 6291456
#define NSPLITG 32            // gattn split-K partials (8 sp x 4 kw)

// ---------------------------------------------------------------------------
__device__ __forceinline__ uint32_t smem_u32(const void* p) {
    uint32_t a;
    asm("{ .reg .u64 t; cvta.to.shared.u64 t, %1; cvt.u32.u64 %0, t; }" : "=r"(a) : "l"(p));
    return a;
}
#define CPA16(sa, g) asm volatile("cp.async.cg.shared.global [%0], [%1], 16;" :: "r"(sa), "l"(g))
#define CPA_COMMIT() asm volatile("cp.async.commit_group;" ::: "memory")
#define CPA_WAIT1()  asm volatile("cp.async.wait_group 1;" ::: "memory")
#define CPA_WAIT0()  asm volatile("cp.async.wait_group 0;" ::: "memory")
#define LDM4(r, addr) \
  asm volatile("ldmatrix.sync.aligned.m8n8.x4.shared.b16 {%0,%1,%2,%3}, [%4];" \
    : "=r"((r)[0]), "=r"((r)[1]), "=r"((r)[2]), "=r"((r)[3]) : "r"(addr))
#define LDM4T(r, addr) \
  asm volatile("ldmatrix.sync.aligned.m8n8.x4.trans.shared.b16 {%0,%1,%2,%3}, [%4];" \
    : "=r"((r)[0]), "=r"((r)[1]), "=r"((r)[2]), "=r"((r)[3]) : "r"(addr))
#define MMA16816(d, a, b0, b1) \
  asm volatile("mma.sync.aligned.m16n8k16.row.col.f32.bf16.bf16.f32 " \
    "{%0,%1,%2,%3}, {%4,%5,%6,%7}, {%8,%9}, {%0,%1,%2,%3};" \
    : "+f"((d)[0]), "+f"((d)[1]), "+f"((d)[2]), "+f"((d)[3]) \
    : "r"((a)[0]), "r"((a)[1]), "r"((a)[2]), "r"((a)[3]), "r"(b0), "r"(b1))

// 64B-row swizzle: seg' = seg ^ ((row>>1)&3)  (conflict-free for ldmatrix + cp.async)
#define SWZ64(row, seg) ((uint32_t)((row) * 64 + ((((seg) ^ ((row) >> 1)) & 3) * 16)))

// ---------------------------------------------------------------------------
// Device scratch (bf16 hi/lo everywhere the tensor cores touch)
__device__ __nv_bfloat16 d_Qhi[BHSD], d_Qlo[BHSD];
__device__ __nv_bfloat16 d_Khi[BHSD], d_Klo[BHSD];
__device__ __nv_bfloat16 d_Vhi[BHSD], d_Vlo[BHSD];
__device__ __nv_bfloat16 d_Kghi[BHSD], d_Kglo[BHSD];
__device__ __nv_bfloat16 d_Vghi[BHSD], d_Vglo[BHSD];
__device__ __nv_bfloat16 d_qghi[B_*H_*G_*HD_], d_qglo[B_*H_*G_*HD_];
__device__ __nv_bfloat16 d_Ahi[B_*S_*D_];
__device__ __nv_bfloat16 d_Alo[B_*S_*D_];
__device__ __nv_bfloat16 d_Whi[6][D_*D_];   // transposed [n][k]
__device__ __nv_bfloat16 d_Wlo[6][D_*D_];
__device__ float d_lpart[B_*H_*NSPLITG*G_];
__device__ float d_accpart[B_*H_*NSPLITG*G_*HD_];

// ---------------------------------------------------------------------------
// Prepass: hidden -> bf16 hi/lo
__global__ __launch_bounds__(256) void convA_kernel(const float* __restrict__ A)
{
    int i = (blockIdx.x * 256 + threadIdx.x) * 4;
    float4 a = *(const float4*)&A[i];
    float av[4] = {a.x, a.y, a.z, a.w};
    __nv_bfloat16 h[4], l[4];
    #pragma unroll
    for (int j = 0; j < 4; j++) {
        h[j] = __float2bfloat16(av[j]);
        l[j] = __float2bfloat16(av[j] - __bfloat162float(h[j]));
    }
    *(uint2*)&d_Ahi[i] = *(uint2*)h;
    *(uint2*)&d_Alo[i] = *(uint2*)l;
}

// Prepass (fused over 6 weights): W[k][n] -> Wt_hi/lo[n][k] bf16
__global__ __launch_bounds__(256) void convW_kernel(
    const float* __restrict__ W0, const float* __restrict__ W1,
    const float* __restrict__ W2, const float* __restrict__ W3,
    const float* __restrict__ W4, const float* __restrict__ W5)
{
    __shared__ float t[32][33];
    const int which = blockIdx.z;
    const float* __restrict__ W = (which == 0) ? W0 : (which == 1) ? W1
                                : (which == 2) ? W2 : (which == 3) ? W3
                                : (which == 4) ? W4 : W5;
    const int n0 = blockIdx.x * 32, k0 = blockIdx.y * 32;
    const int tx = threadIdx.x, ty = threadIdx.y;   // (32, 8)
    #pragma unroll
    for (int r = 0; r < 32; r += 8)
        t[ty + r][tx] = W[(k0 + ty + r) * D_ + n0 + tx];
    __syncthreads();
    #pragma unroll
    for (int r = 0; r < 32; r += 8) {
        float v = t[tx][ty + r];
        __nv_bfloat16 hh = __float2bfloat16(v);
        __nv_bfloat16 ll = __float2bfloat16(v - __bfloat162float(hh));
        d_Whi[which][(n0 + ty + r) * D_ + k0 + tx] = hh;
        d_Wlo[which][(n0 + ty + r) * D_ + k0 + tx] = ll;
    }
}

// ---------------------------------------------------------------------------
// Fused projection GEMMs on mma.sync, hi/lo 3-term, 3-stage cp.async pipeline,
// swizzled 64B smem rows, ONE barrier per K-chunk.
// grid = (6, 64, 6). z = which; z==5 (qg) only runs y==0 / y==32.
// ---------------------------------------------------------------------------
#define GTILE 8192                 // 128 rows x 64B, swizzled
#define GSTAGE (4 * GTILE)         // 4 operands per stage
#define GEMM_DYN (3 * GSTAGE)      // 98304

__global__ __launch_bounds__(256, 2) void gemm_kernel(
    const float* __restrict__ bq,  const float* __restrict__ bk,
    const float* __restrict__ bv,  const float* __restrict__ bkg,
    const float* __restrict__ bvg, const float* __restrict__ bqg)
{
    const int which = blockIdx.z;
    if (which == 5 && blockIdx.y != 0 && blockIdx.y != 32) return;
    extern __shared__ char smraw[];
    const uint32_t sb = smem_u32(smraw);
    const int tid = threadIdx.x, wid = tid >> 5, lane = tid & 31;
    const int mw = wid & 3, nw = wid >> 2;
    const int n0 = blockIdx.x * 128;
    const int m0 = blockIdx.y * 128;
    const float* bias = (which == 0) ? bq : (which == 1) ? bk : (which == 2) ? bv
                       : (which == 3) ? bkg : (which == 4) ? bvg : bqg;
    const __nv_bfloat16* __restrict__ Ahi = d_Ahi;
    const __nv_bfloat16* __restrict__ Alo = d_Alo;
    const __nv_bfloat16* __restrict__ Whi = d_Whi[which];
    const __nv_bfloat16* __restrict__ Wlo = d_Wlo[which];

    float acc[2][8][4];
    #pragma unroll
    for (int mt = 0; mt < 2; mt++)
        #pragma unroll
        for (int nt = 0; nt < 8; nt++)
            #pragma unroll
            for (int r = 0; r < 4; r++) acc[mt][nt][r] = 0.f;

    const int lrow = tid >> 2, lch = tid & 3;     // 64 rows x 4 segs
    const int lrow2 = lrow + 64;
    const uint32_t o1 = SWZ64(lrow, lch), o2 = SWZ64(lrow2, lch);

    auto load_chunk = [&](int buf, int k0) {
        uint32_t base = sb + buf * GSTAGE;
        CPA16(base + o1, &Ahi[(m0 + lrow) * D_ + k0 + lch * 8]);
        CPA16(base + o2, &Ahi[(m0 + lrow2) * D_ + k0 + lch * 8]);
        base += GTILE;
        CPA16(base + o1, &Alo[(m0 + lrow) * D_ + k0 + lch * 8]);
        CPA16(base + o2, &Alo[(m0 + lrow2) * D_ + k0 + lch * 8]);
        base += GTILE;
        CPA16(base + o1, &Whi[(n0 + lrow) * D_ + k0 + lch * 8]);
        CPA16(base + o2, &Whi[(n0 + lrow2) * D_ + k0 + lch * 8]);
        base += GTILE;
        CPA16(base + o1, &Wlo[(n0 + lrow) * D_ + k0 + lch * 8]);
        CPA16(base + o2, &Wlo[(n0 + lrow2) * D_ + k0 + lch * 8]);
        CPA_COMMIT();
    };

    load_chunk(0, 0);
    load_chunk(1, 32);

    int cur = 0;
    #pragma unroll 1
    for (int c = 0; c < 24; c++) {
        if (c == 23) CPA_WAIT0(); else CPA_WAIT1();
        __syncthreads();
        if (c + 2 < 24) {
            int nxt = cur + 2; if (nxt >= 3) nxt -= 3;
            load_chunk(nxt, (c + 2) * 32);
        }

        const uint32_t aBase  = sb + cur * GSTAGE;
        const uint32_t alBase = aBase + GTILE;
        const uint32_t bBase  = aBase + 2 * GTILE;
        const uint32_t blBase = aBase + 3 * GTILE;

        #pragma unroll
        for (int ks = 0; ks < 2; ks++) {
            uint32_t ahi[2][4], alo[2][4];
            const int aseg = ks * 2 + ((lane >> 4) & 1);
            #pragma unroll
            for (int mt = 0; mt < 2; mt++) {
                int row = mw * 32 + mt * 16 + (lane & 15);
                LDM4(ahi[mt], aBase + SWZ64(row, aseg));
                LDM4(alo[mt], alBase + SWZ64(row, aseg));
            }
            const int bseg = ks * 2 + ((lane >> 3) & 1);
            #pragma unroll
            for (int nh = 0; nh < 2; nh++) {
                uint32_t bhi[2][4], blo[2][4];
                #pragma unroll
                for (int q = 0; q < 2; q++) {
                    int row = nw * 64 + nh * 32 + q * 16 + (lane & 7) + ((lane >> 4) << 3);
                    LDM4(bhi[q], bBase + SWZ64(row, bseg));
                    LDM4(blo[q], blBase + SWZ64(row, bseg));
                }
                #pragma unroll
                for (int mt = 0; mt < 2; mt++)
                    #pragma unroll
                    for (int q = 0; q < 2; q++)
                        #pragma unroll
                        for (int p = 0; p < 2; p++) {
                            int nt = nh * 4 + q * 2 + p;
                            MMA16816(acc[mt][nt], ahi[mt], bhi[q][p*2], bhi[q][p*2+1]);
                            MMA16816(acc[mt][nt], ahi[mt], blo[q][p*2], blo[q][p*2+1]);
                            MMA16816(acc[mt][nt], alo[mt], bhi[q][p*2], bhi[q][p*2+1]);
                        }
            }
        }
        cur++; if (cur >= 3) cur -= 3;
    }

    // Epilogue: bf16 hi/lo split stores
    const int g = lane >> 2, tg = lane & 3;
    #pragma unroll
    for (int mt = 0; mt < 2; mt++)
        #pragma unroll
        for (int half = 0; half < 2; half++) {
            int m = m0 + mw * 32 + mt * 16 + g + half * 8;
            int b = m >> 12, s = m & 4095;
            #pragma unroll
            for (int nt = 0; nt < 8; nt++) {
                int n = n0 + nw * 64 + nt * 8 + tg * 2;
                float v0 = acc[mt][nt][half * 2 + 0] + bias[n];
                float v1 = acc[mt][nt][half * 2 + 1] + bias[n + 1];
                int h = n >> 6, hd = n & 63;
                if (which == 0 || which == 5) { v0 *= SCALE_; v1 *= SCALE_; }
                if (which == 5 && s >= G_) continue;
                __nv_bfloat16 h0 = __float2bfloat16(v0);
                __nv_bfloat16 h1 = __float2bfloat16(v1);
                __nv_bfloat16 l0 = __float2bfloat16(v0 - __bfloat162float(h0));
                __nv_bfloat16 l1 = __float2bfloat16(v1 - __bfloat162float(h1));
                __nv_bfloat162 hp; hp.x = h0; hp.y = h1;
                __nv_bfloat162 lp; lp.x = l0; lp.y = l1;
                size_t bidx = ((size_t)(b * H_ + h) * S_ + s) * HD_ + hd;
                switch (which) {
                    case 0:
                        *(__nv_bfloat162*)&d_Qhi[bidx] = hp;
                        *(__nv_bfloat162*)&d_Qlo[bidx] = lp; break;
                    case 1:
                        *(__nv_bfloat162*)&d_Khi[bidx] = hp;
                        *(__nv_bfloat162*)&d_Klo[bidx] = lp; break;
                    case 2:
                        *(__nv_bfloat162*)&d_Vhi[bidx] = hp;
                        *(__nv_bfloat162*)&d_Vlo[bidx] = lp; break;
                    case 3:
                        *(__nv_bfloat162*)&d_Kghi[bidx] = hp;
                        *(__nv_bfloat162*)&d_Kglo[bidx] = lp; break;
                    case 4:
                        *(__nv_bfloat162*)&d_Vghi[bidx] = hp;
                        *(__nv_bfloat162*)&d_Vglo[bidx] = lp; break;
                    default: {
                        size_t qidx = ((size_t)(b * H_ + h) * G_ + s) * HD_ + hd;
                        *(__nv_bfloat162*)&d_qghi[qidx] = hp;
                        *(__nv_bfloat162*)&d_qglo[qidx] = lp; break;
                    }
                }
            }
        }
}

// ---------------------------------------------------------------------------
// Global attention on mma.sync (unchanged; 21 us).
// ---------------------------------------------------------------------------
__global__ __launch_bounds__(256, 2) void gattn_mma_kernel()
{
    __shared__ __align__(16) char kh_sm[16384];
    __shared__ __align__(16) char kl_sm[16384];
    __shared__ __align__(16) char vh_sm[16384];
    __shared__ __align__(16) char vl_sm[16384];
    const uint32_t sKhi = smem_u32(kh_sm), sKlo = smem_u32(kl_sm);
    const uint32_t sVhi = smem_u32(vh_sm), sVlo = smem_u32(vl_sm);
    const int tid = threadIdx.x, wid = tid >> 5, lane = tid & 31;
    const int sp = blockIdx.x, h = blockIdx.y, b = blockIdx.z;
    const int bh = b * H_ + h;
    const int mw = wid & 1, kw = wid >> 1;
    const int g = lane >> 2, tg = lane & 3;

    uint32_t qhi[4][4], qlo[4][4];
    {
        const __nv_bfloat16* Qh = &d_qghi[((size_t)bh * G_ + mw * 16) * 64];
        const __nv_bfloat16* Ql = &d_qglo[((size_t)bh * G_ + mw * 16) * 64];
        #pragma unroll
        for (int ks = 0; ks < 4; ks++) {
            int c0 = ks * 16 + tg * 2;
            qhi[ks][0] = *(const uint32_t*)&Qh[g * 64 + c0];
            qhi[ks][1] = *(const uint32_t*)&Qh[(g + 8) * 64 + c0];
            qhi[ks][2] = *(const uint32_t*)&Qh[g * 64 + c0 + 8];
            qhi[ks][3] = *(const uint32_t*)&Qh[(g + 8) * 64 + c0 + 8];
            qlo[ks][0] = *(const uint32_t*)&Ql[g * 64 + c0];
            qlo[ks][1] = *(const uint32_t*)&Ql[(g + 8) * 64 + c0];
            qlo[ks][2] = *(const uint32_t*)&Ql[g * 64 + c0 + 8];
            qlo[ks][3] = *(const uint32_t*)&Ql[(g + 8) * 64 + c0 + 8];
        }
    }

    float oacc[8][4];
    #pragma unroll
    for (int i = 0; i < 8; i++)
        #pragma unroll
        for (int r = 0; r < 4; r++) oacc[i][r] = 0.f;
    float lsum0 = 0.f, lsum1 = 0.f;

    #pragma unroll 1
    for (int ch = 0; ch < 4; ch++) {
        __syncthreads();
        #pragma unroll
        for (int r = 0; r < 4; r++) {
            int idx = tid + r * 256;
            int row = idx >> 3, seg = idx & 7;
            uint32_t off = row * 128 + ((seg ^ (row & 7)) * 16);
            size_t src = ((size_t)bh * S_ + sp * 512 + ch * 128 + row) * 64 + seg * 8;
            CPA16(sKhi + off, &d_Kghi[src]);
            CPA16(sKlo + off, &d_Kglo[src]);
            CPA16(sVhi + off, &d_Vghi[src]);
            CPA16(sVlo + off, &d_Vglo[src]);
        }
        CPA_COMMIT(); CPA_WAIT0();
        __syncthreads();

        const int kb = kw * 32;
        float sc[4][4];
        #pragma unroll
        for (int i = 0; i < 4; i++)
            #pragma unroll
            for (int r = 0; r < 4; r++) sc[i][r] = 0.f;

        #pragma unroll
        for (int ks = 0; ks < 4; ks++) {
            uint32_t kh[2][4], kl[2][4];
            #pragma unroll
            for (int q2 = 0; q2 < 2; q2++) {
                int row = kb + q2 * 16 + (lane & 7) + ((lane >> 4) << 3);
                int seg = ks * 2 + ((lane >> 3) & 1);
                uint32_t addr = row * 128 + ((seg ^ (row & 7)) * 16);
                LDM4(kh[q2], sKhi + addr);
                LDM4(kl[q2], sKlo + addr);
            }
            #pragma unroll
            for (int q2 = 0; q2 < 2; q2++)
                #pragma unroll
                for (int p = 0; p < 2; p++) {
                    int nt = q2 * 2 + p;
                    MMA16816(sc[nt], qhi[ks], kh[q2][p*2], kh[q2][p*2+1]);
                    MMA16816(sc[nt], qhi[ks], kl[q2][p*2], kl[q2][p*2+1]);
                    MMA16816(sc[nt], qlo[ks], kh[q2][p*2], kh[q2][p*2+1]);
                }
        }

        uint32_t pah[2][4], pal[2][4];
        #pragma unroll
        for (int nt = 0; nt < 4; nt++) {
            float p00 = __expf(sc[nt][0]), p01 = __expf(sc[nt][1]);
            float p10 = __expf(sc[nt][2]), p11 = __expf(sc[nt][3]);
            lsum0 += p00 + p01;
            lsum1 += p10 + p11;
            __nv_bfloat16 h00 = __float2bfloat16(p00);
            __nv_bfloat16 h01 = __float2bfloat16(p01);
            __nv_bfloat16 h10 = __float2bfloat16(p10);
            __nv_bfloat16 h11 = __float2bfloat16(p11);
            __nv_bfloat162 hp0; hp0.x = h00; hp0.y = h01;
            __nv_bfloat162 hp1; hp1.x = h10; hp1.y = h11;
            __nv_bfloat162 lp0;
            lp0.x = __float2bfloat16(p00 - __bfloat162float(h00));
            lp0.y = __float2bfloat16(p01 - __bfloat162float(h01));
            __nv_bfloat162 lp1;
            lp1.x = __float2bfloat16(p10 - __bfloat162float(h10));
            lp1.y = __float2bfloat16(p11 - __bfloat162float(h11));
            pah[nt >> 1][(nt & 1) * 2 + 0] = *(uint32_t*)&hp0;
            pah[nt >> 1][(nt & 1) * 2 + 1] = *(uint32_t*)&hp1;
            pal[nt >> 1][(nt & 1) * 2 + 0] = *(uint32_t*)&lp0;
            pal[nt >> 1][(nt & 1) * 2 + 1] = *(uint32_t*)&lp1;
        }

        #pragma unroll
        for (int ksp = 0; ksp < 2; ksp++) {
            #pragma unroll
            for (int dg = 0; dg < 4; dg++) {
                uint32_t vh[4], vl[4];
                int row = kb + ksp * 16 + (lane & 15);
                int seg = dg * 2 + (lane >> 4);
                uint32_t addr = row * 128 + ((seg ^ (row & 7)) * 16);
                LDM4T(vh, sVhi + addr);
                LDM4T(vl, sVlo + addr);
                MMA16816(oacc[dg * 2 + 0], pah[ksp], vh[0], vh[1]);
                MMA16816(oacc[dg * 2 + 0], pal[ksp], vh[0], vh[1]);
                MMA16816(oacc[dg * 2 + 0], pah[ksp], vl[0], vl[1]);
                MMA16816(oacc[dg * 2 + 1], pah[ksp], vh[2], vh[3]);
                MMA16816(oacc[dg * 2 + 1], pal[ksp], vh[2], vh[3]);
                MMA16816(oacc[dg * 2 + 1], pah[ksp], vl[2], vl[3]);
            }
        }
    }

    lsum0 += __shfl_xor_sync(0xffffffffu, lsum0, 1);
    lsum0 += __shfl_xor_sync(0xffffffffu, lsum0, 2);
    lsum1 += __shfl_xor_sync(0xffffffffu, lsum1, 1);
    lsum1 += __shfl_xor_sync(0xffffffffu, lsum1, 2);
    const int part = sp * 4 + kw;
    const int r0 = mw * 16 + g, r1 = r0 + 8;
    if (tg == 0) {
        d_lpart[((size_t)bh * NSPLITG + part) * G_ + r0] = lsum0;
        d_lpart[((size_t)bh * NSPLITG + part) * G_ + r1] = lsum1;
    }
    float* a0 = &d_accpart[(((size_t)bh * NSPLITG + part) * G_ + r0) * HD_];
    float* a1 = &d_accpart[(((size_t)bh * NSPLITG + part) * G_ + r1) * HD_];
    #pragma unroll
    for (int nt = 0; nt < 8; nt++) {
        float2 w0; w0.x = oacc[nt][0]; w0.y = oacc[nt][1];
        float2 w1; w1.x = oacc[nt][2]; w1.y = oacc[nt][3];
        *(float2*)&a0[nt * 8 + tg * 2] = w0;
        *(float2*)&a1[nt * 8 + tg * 2] = w1;
    }
}

__global__ __launch_bounds__(64) void gattn_combine_kernel(float* __restrict__ out)
{
    const int idx = blockIdx.x;
    const int bh = idx >> 5;
    const int g = idx & 31;
    const int b = bh / H_, h = bh % H_;
    const int d = threadIdx.x;
    float l = 0.f, a = 0.f;
    #pragma unroll
    for (int sp = 0; sp < NSPLITG; sp++) {
        l += d_lpart[((size_t)bh * NSPLITG + sp) * G_ + g];
        a += d_accpart[(((size_t)bh * NSPLITG + sp) * G_ + g) * HD_ + d];
    }
    out[(b * S_ + g) * D_ + h * HD_ + d] = a / l;
}

// ---------------------------------------------------------------------------
// Band + global-key attention: 3-stage cp.async pipeline, one barrier/tile,
// warp-uniform SKIP of fully-masked segments, unmasked fast path, hoisted
// per-thread mask bounds.
// grid = (NC*2, H, B); dynamic smem 3 stages x 4 tiles x 8KB.
// ---------------------------------------------------------------------------
#define BTILE 8192
#define BSTAGE (4 * BTILE)
#define BAND_DYN (3 * BSTAGE)     // 98304

__global__ __launch_bounds__(256, 2) void band_mma_kernel(float* __restrict__ out)
{
    extern __shared__ char bsm[];
    const uint32_t sb = smem_u32(bsm);
    const int tid = threadIdx.x, wid = tid >> 5, lane = tid & 31;
    const int c = blockIdx.x >> 1, qh = blockIdx.x & 1;
    const int h = blockIdx.y, b = blockIdx.z;
    const int bh = b * H_ + h;
    const int row0 = c * W_ + qh * 128;
    const int wr = wid * 16;
    const int g = lane >> 2, tg = lane & 3;
    const int pqr0 = qh * 128 + wr + g;
    const int pqr1 = pqr0 + 8;
    const int wbase = qh * 128 + wr;            // warp min pq

    // per-thread e-bounds (t-invariant): valid <=> lo <= e <= hi
    const int eklo = W_ - c * W_;               // kabs >= 0
    const int ekhi = S_ - 1 + W_ - c * W_;      // kabs <= S-1
    const int lo0 = max(pqr0, eklo), hi0 = min(pqr0 + 2 * W_, ekhi);
    const int lo1 = max(pqr1, eklo), hi1 = min(pqr1 + 2 * W_, ekhi);
    // warp-uniform union of valid e over the warp's 16 rows
    const int wlo = max(wbase, eklo);
    const int whi = min(wbase + 15 + 2 * W_, ekhi);

    int tlist[11], ntl = 0;
    tlist[ntl++] = 0;
    #pragma unroll
    for (int t = 1; t < 11; t++) {
        int ebase = qh * 128 + (t - 1) * 64;
        int kl = c * W_ + ebase - W_;
        if (kl + 63 >= 0 && kl < S_) tlist[ntl++] = t;
    }

    uint32_t qhi[4][4], qlo[4][4];
    {
        const __nv_bfloat16* Qh = &d_Qhi[((size_t)bh * S_ + row0 + wr) * 64];
        const __nv_bfloat16* Ql = &d_Qlo[((size_t)bh * S_ + row0 + wr) * 64];
        #pragma unroll
        for (int ks = 0; ks < 4; ks++) {
            int c0 = ks * 16 + tg * 2;
            qhi[ks][0] = *(const uint32_t*)&Qh[g * 64 + c0];
            qhi[ks][1] = *(const uint32_t*)&Qh[(g + 8) * 64 + c0];
            qhi[ks][2] = *(const uint32_t*)&Qh[g * 64 + c0 + 8];
            qhi[ks][3] = *(const uint32_t*)&Qh[(g + 8) * 64 + c0 + 8];
            qlo[ks][0] = *(const uint32_t*)&Ql[g * 64 + c0];
            qlo[ks][1] = *(const uint32_t*)&Ql[(g + 8) * 64 + c0];
            qlo[ks][2] = *(const uint32_t*)&Ql[g * 64 + c0 + 8];
            qlo[ks][3] = *(const uint32_t*)&Ql[(g + 8) * 64 + c0 + 8];
        }
    }

    float oacc[8][4];
    #pragma unroll
    for (int i = 0; i < 8; i++)
        #pragma unroll
        for (int r = 0; r < 4; r++) oacc[i][r] = 0.f;
    float lsum0 = 0.f, lsum1 = 0.f;

    const int lrowA = tid >> 3, lseg = tid & 7;
    const int lrowB = lrowA + 32;

    auto load_tile = [&](int stg, int t) {
        uint32_t base = sb + stg * BSTAGE;
        #pragma unroll
        for (int r = 0; r < 2; r++) {
            int row = r ? lrowB : lrowA;
            int ka = (t == 0) ? row
                              : (c * W_ + qh * 128 + (t - 1) * 64 + row - W_);
            int kr = min(max(ka, 0), S_ - 1);
            uint32_t off = row * 128 + ((lseg ^ (row & 7)) * 16);
            size_t src = ((size_t)bh * S_ + kr) * 64 + lseg * 8;
            CPA16(base + off, &d_Khi[src]);
            CPA16(base + BTILE + off, &d_Klo[src]);
            CPA16(base + 2 * BTILE + off, &d_Vhi[src]);
            CPA16(base + 3 * BTILE + off, &d_Vlo[src]);
        }
        CPA_COMMIT();
    };

    load_tile(0, tlist[0]);
    if (ntl > 1) load_tile(1, tlist[1]);

    int cur = 0;
    #pragma unroll 1
    for (int it = 0; it < ntl; it++) {
        const int t = tlist[it];
        if (it == ntl - 1) CPA_WAIT0(); else CPA_WAIT1();
        __syncthreads();
        if (it + 2 < ntl) {
            int nxt = cur + 2; if (nxt >= 3) nxt -= 3;
            load_tile(nxt, tlist[it + 2]);
        }

        const uint32_t sKhi = sb + cur * BSTAGE;
        const uint32_t sKlo = sKhi + BTILE;
        const uint32_t sVhi = sKhi + 2 * BTILE;
        const uint32_t sVlo = sKhi + 3 * BTILE;
        const int ebase = qh * 128 + (t - 1) * 64;

        const int nhalf = (t == 0) ? 1 : 2;
        for (int hf = 0; hf < nhalf; hf++) {
            const int kb = hf * 32;
            const int minE = ebase + kb, maxE = minE + 31;

            // warp-uniform SKIP: segment entirely outside this warp's window
            if (t != 0 && (maxE < wlo || minE > whi)) continue;

            float sc[4][4];
            #pragma unroll
            for (int i = 0; i < 4; i++)
                #pragma unroll
                for (int r = 0; r < 4; r++) sc[i][r] = 0.f;

            #pragma unroll
            for (int ks = 0; ks < 4; ks++) {
                uint32_t kh[2][4], kl[2][4];
                #pragma unroll
                for (int q2 = 0; q2 < 2; q2++) {
                    int row = kb + q2 * 16 + (lane & 7) + ((lane >> 4) << 3);
                    int seg = ks * 2 + ((lane >> 3) & 1);
                    uint32_t addr = row * 128 + ((seg ^ (row & 7)) * 16);
                    LDM4(kh[q2], sKhi + addr);
                    LDM4(kl[q2], sKlo + addr);
                }
                #pragma unroll
                for (int q2 = 0; q2 < 2; q2++)
                    #pragma unroll
                    for (int p = 0; p < 2; p++) {
                        int nt = q2 * 2 + p;
                        MMA16816(sc[nt], qhi[ks], kh[q2][p*2], kh[q2][p*2+1]);
                        MMA16816(sc[nt], qhi[ks], kl[q2][p*2], kl[q2][p*2+1]);
                        MMA16816(sc[nt], qlo[ks], kh[q2][p*2], kh[q2][p*2+1]);
                    }
            }

            // warp-uniform: fully valid segment?
            const bool full = (t != 0) &&
                (minE >= wbase + 15) && (maxE <= wbase + 2 * W_) &&
                (minE >= eklo) && (maxE <= ekhi);

            uint32_t pah[2][4], pal[2][4];
            if (t == 0 || full) {
                // fast path: no masking at all
                #pragma unroll
                for (int nt = 0; nt < 4; nt++) {
                    float p00 = __expf(sc[nt][0]), p01 = __expf(sc[nt][1]);
                    float p10 = __expf(sc[nt][2]), p11 = __expf(sc[nt][3]);
                    lsum0 += p00 + p01;
                    lsum1 += p10 + p11;
                    __nv_bfloat16 h00 = __float2bfloat16(p00);
                    __nv_bfloat16 h01 = __float2bfloat16(p01);
                    __nv_bfloat16 h10 = __float2bfloat16(p10);
                    __nv_bfloat16 h11 = __float2bfloat16(p11);
                    __nv_bfloat162 hp0; hp0.x = h00; hp0.y = h01;
                    __nv_bfloat162 hp1; hp1.x = h10; hp1.y = h11;
                    __nv_bfloat162 lp0;
                    lp0.x = __float2bfloat16(p00 - __bfloat162float(h00));
                    lp0.y = __float2bfloat16(p01 - __bfloat162float(h01));
                    __nv_bfloat162 lp1;
                    lp1.x = __float2bfloat16(p10 - __bfloat162float(h10));
                    lp1.y = __float2bfloat16(p11 - __bfloat162float(h11));
                    pah[nt >> 1][(nt & 1) * 2 + 0] = *(uint32_t*)&hp0;
                    pah[nt >> 1][(nt & 1) * 2 + 1] = *(uint32_t*)&hp1;
                    pal[nt >> 1][(nt & 1) * 2 + 0] = *(uint32_t*)&lp0;
                    pal[nt >> 1][(nt & 1) * 2 + 1] = *(uint32_t*)&lp1;
                }
            } else {
                // masked path: 2 compares per element against hoisted bounds
                #pragma unroll
                for (int nt = 0; nt < 4; nt++) {
                    int e0 = ebase + kb + nt * 8 + tg * 2;
                    int e1 = e0 + 1;
                    float p00 = (e0 >= lo0 && e0 <= hi0) ? __expf(sc[nt][0]) : 0.f;
                    float p01 = (e1 >= lo0 && e1 <= hi0) ? __expf(sc[nt][1]) : 0.f;
                    float p10 = (e0 >= lo1 && e0 <= hi1) ? __expf(sc[nt][2]) : 0.f;
                    float p11 = (e1 >= lo1 && e1 <= hi1) ? __expf(sc[nt][3]) : 0.f;
                    lsum0 += p00 + p01;
                    lsum1 += p10 + p11;
                    __nv_bfloat16 h00 = __float2bfloat16(p00);
                    __nv_bfloat16 h01 = __float2bfloat16(p01);
                    __nv_bfloat16 h10 = __float2bfloat16(p10);
                    __nv_bfloat16 h11 = __float2bfloat16(p11);
                    __nv_bfloat162 hp0; hp0.x = h00; hp0.y = h01;
                    __nv_bfloat162 hp1; hp1.x = h10; hp1.y = h11;
                    __nv_bfloat162 lp0;
                    lp0.x = __float2bfloat16(p00 - __bfloat162float(h00));
                    lp0.y = __float2bfloat16(p01 - __bfloat162float(h01));
                    __nv_bfloat162 lp1;
                    lp1.x = __float2bfloat16(p10 - __bfloat162float(h10));
                    lp1.y = __float2bfloat16(p11 - __bfloat162float(h11));
                    pah[nt >> 1][(nt & 1) * 2 + 0] = *(uint32_t*)&hp0;
                    pah[nt >> 1][(nt & 1) * 2 + 1] = *(uint32_t*)&hp1;
                    pal[nt >> 1][(nt & 1) * 2 + 0] = *(uint32_t*)&lp0;
                    pal[nt >> 1][(nt & 1) * 2 + 1] = *(uint32_t*)&lp1;
                }
            }

            #pragma unroll
            for (int ksp = 0; ksp < 2; ksp++) {
                #pragma unroll
                for (int dg = 0; dg < 4; dg++) {
                    uint32_t vh[4], vl[4];
                    int row = kb + ksp * 16 + (lane & 15);
                    int seg = dg * 2 + (lane >> 4);
                    uint32_t addr = row * 128 + ((seg ^ (row & 7)) * 16);
                    LDM4T(vh, sVhi + addr);
                    LDM4T(vl, sVlo + addr);
                    MMA16816(oacc[dg * 2 + 0], pah[ksp], vh[0], vh[1]);
                    MMA16816(oacc[dg * 2 + 0], pal[ksp], vh[0], vh[1]);
                    MMA16816(oacc[dg * 2 + 0], pah[ksp], vl[0], vl[1]);
                    MMA16816(oacc[dg * 2 + 1], pah[ksp], vh[2], vh[3]);
                    MMA16816(oacc[dg * 2 + 1], pal[ksp], vh[2], vh[3]);
                    MMA16816(oacc[dg * 2 + 1], pah[ksp], vl[2], vl[3]);
                }
            }
        }
        cur++; if (cur >= 3) cur -= 3;
    }

    lsum0 += __shfl_xor_sync(0xffffffffu, lsum0, 1);
    lsum0 += __shfl_xor_sync(0xffffffffu, lsum0, 2);
    lsum1 += __shfl_xor_sync(0xffffffffu, lsum1, 1);
    lsum1 += __shfl_xor_sync(0xffffffffu, lsum1, 2);
    float inv0 = 1.f / lsum0, inv1 = 1.f / lsum1;
    float* o0 = &out[(size_t)(b * S_ + row0 + wr + g) * D_ + h * 64];
    float* o1 = o0 + 8 * D_;
    #pragma unroll
    for (int nt = 0; nt < 8; nt++) {
        float2 w0; w0.x = oacc[nt][0] * inv0; w0.y = oacc[nt][1] * inv0;
        float2 w1; w1.x = oacc[nt][2] * inv1; w1.y = oacc[nt][3] * inv1;
        *(float2*)&o0[nt * 8 + tg * 2] = w0;
        *(float2*)&o1[nt * 8 + tg * 2] = w1;
    }
}

// ---------------------------------------------------------------------------
extern "C" void kernel_launch(void* const* d_in, const int* in_sizes, int n_in,
                              void* d_out, int out_size)
{
    const float* hidden = (const float*)d_in[0];
    const float* Wq  = (const float*)d_in[1];
    const float* bq  = (const float*)d_in[2];
    const float* Wk  = (const float*)d_in[3];
    const float* bk  = (const float*)d_in[4];
    const float* Wv  = (const float*)d_in[5];
    const float* bv  = (const float*)d_in[6];
    const float* Wqg = (const float*)d_in[7];
    const float* bqg = (const float*)d_in[8];
    const float* Wkg = (const float*)d_in[9];
    const float* bkg = (const float*)d_in[10];
    const float* Wvg = (const float*)d_in[11];
    const float* bvg = (const float*)d_in[12];
    float* out = (float*)d_out;

    static int configured = 0;
    if (!configured) {
        cudaFuncSetAttribute(gemm_kernel, cudaFuncAttributeMaxDynamicSharedMemorySize, GEMM_DYN);
        cudaFuncSetAttribute(band_mma_kernel, cudaFuncAttributeMaxDynamicSharedMemorySize, BAND_DYN);
        configured = 1;
    }

    convA_kernel<<<(B_*S_*D_)/1024, 256>>>(hidden);                               // 1
    convW_kernel<<<dim3(24, 24, 6), dim3(32, 8)>>>(Wq, Wk, Wv, Wkg, Wvg, Wqg);    // 2

    dim3 ggrid(D_ / 128, (B_ * S_) / 128, 6);
    gemm_kernel<<<ggrid, 256, GEMM_DYN>>>(bq, bk, bv, bkg, bvg, bqg);             // 3

    band_mma_kernel<<<dim3(NC_ * 2, H_, B_), 256, BAND_DYN>>>(out);               // 4 <- profiled
    gattn_mma_kernel<<<dim3(8, H_, B_), 256>>>();                                 // 5
    gattn_combine_kernel<<<B_ * H_ * G_, 64>>>(out);                              // 6
}

// round 14
// speedup vs baseline: 5.4522x; 1.0227x over previous
#include <cuda_runtime.h>
#include <cuda_bf16.h>
#include <cstdint>

// Problem constants
#define B_  2
#define S_  4096
#define D_  768
#define H_  12
#define HD_ 64
#define W_  256
#define NC_ 16
#define G_  32
#define SCALE_ 0.125f

#define BHSD (B_*H_*S_*HD_)   // 6291456
#define NSPLITG 32            // gattn split-K partials (8 sp x 4 kw)

// ---------------------------------------------------------------------------
__device__ __forceinline__ uint32_t smem_u32(const void* p) {
    uint32_t a;
    asm("{ .reg .u64 t; cvta.to.shared.u64 t, %1; cvt.u32.u64 %0, t; }" : "=r"(a) : "l"(p));
    return a;
}
#define CPA16(sa, g) asm volatile("cp.async.cg.shared.global [%0], [%1], 16;" :: "r"(sa), "l"(g))
#define CPA_COMMIT() asm volatile("cp.async.commit_group;" ::: "memory")
#define CPA_WAIT1()  asm volatile("cp.async.wait_group 1;" ::: "memory")
#define CPA_WAIT0()  asm volatile("cp.async.wait_group 0;" ::: "memory")
#define LDM4(r, addr) \
  asm volatile("ldmatrix.sync.aligned.m8n8.x4.shared.b16 {%0,%1,%2,%3}, [%4];" \
    : "=r"((r)[0]), "=r"((r)[1]), "=r"((r)[2]), "=r"((r)[3]) : "r"(addr))
#define LDM4T(r, addr) \
  asm volatile("ldmatrix.sync.aligned.m8n8.x4.trans.shared.b16 {%0,%1,%2,%3}, [%4];" \
    : "=r"((r)[0]), "=r"((r)[1]), "=r"((r)[2]), "=r"((r)[3]) : "r"(addr))
#define MMA16816(d, a, b0, b1) \
  asm volatile("mma.sync.aligned.m16n8k16.row.col.f32.bf16.bf16.f32 " \
    "{%0,%1,%2,%3}, {%4,%5,%6,%7}, {%8,%9}, {%0,%1,%2,%3};" \
    : "+f"((d)[0]), "+f"((d)[1]), "+f"((d)[2]), "+f"((d)[3]) \
    : "r"((a)[0]), "r"((a)[1]), "r"((a)[2]), "r"((a)[3]), "r"(b0), "r"(b1))

// 64B-row swizzle: seg' = seg ^ ((row>>1)&3)  (conflict-free for ldmatrix + cp.async)
#define SWZ64(row, seg) ((uint32_t)((row) * 64 + ((((seg) ^ ((row) >> 1)) & 3) * 16)))

// ---------------------------------------------------------------------------
// Device scratch (bf16 hi/lo everywhere the tensor cores touch)
__device__ __nv_bfloat16 d_Qhi[BHSD], d_Qlo[BHSD];
__device__ __nv_bfloat16 d_Khi[BHSD], d_Klo[BHSD];
__device__ __nv_bfloat16 d_Vhi[BHSD], d_Vlo[BHSD];
__device__ __nv_bfloat16 d_Kghi[BHSD], d_Kglo[BHSD];
__device__ __nv_bfloat16 d_Vghi[BHSD], d_Vglo[BHSD];
__device__ __nv_bfloat16 d_qghi[B_*H_*G_*HD_], d_qglo[B_*H_*G_*HD_];
__device__ __nv_bfloat16 d_Ahi[B_*S_*D_];
__device__ __nv_bfloat16 d_Alo[B_*S_*D_];
__device__ __nv_bfloat16 d_Whi[6][D_*D_];   // transposed [n][k]
__device__ __nv_bfloat16 d_Wlo[6][D_*D_];
__device__ float d_lpart[B_*H_*NSPLITG*G_];
__device__ float d_accpart[B_*H_*NSPLITG*G_*HD_];

// ---------------------------------------------------------------------------
// Prepass: hidden -> bf16 hi/lo
__global__ __launch_bounds__(256) void convA_kernel(const float* __restrict__ A)
{
    int i = (blockIdx.x * 256 + threadIdx.x) * 4;
    float4 a = *(const float4*)&A[i];
    float av[4] = {a.x, a.y, a.z, a.w};
    __nv_bfloat16 h[4], l[4];
    #pragma unroll
    for (int j = 0; j < 4; j++) {
        h[j] = __float2bfloat16(av[j]);
        l[j] = __float2bfloat16(av[j] - __bfloat162float(h[j]));
    }
    *(uint2*)&d_Ahi[i] = *(uint2*)h;
    *(uint2*)&d_Alo[i] = *(uint2*)l;
}

// Prepass (fused over 6 weights): W[k][n] -> Wt_hi/lo[n][k] bf16
__global__ __launch_bounds__(256) void convW_kernel(
    const float* __restrict__ W0, const float* __restrict__ W1,
    const float* __restrict__ W2, const float* __restrict__ W3,
    const float* __restrict__ W4, const float* __restrict__ W5)
{
    __shared__ float t[32][33];
    const int which = blockIdx.z;
    const float* __restrict__ W = (which == 0) ? W0 : (which == 1) ? W1
                                : (which == 2) ? W2 : (which == 3) ? W3
                                : (which == 4) ? W4 : W5;
    const int n0 = blockIdx.x * 32, k0 = blockIdx.y * 32;
    const int tx = threadIdx.x, ty = threadIdx.y;   // (32, 8)
    #pragma unroll
    for (int r = 0; r < 32; r += 8)
        t[ty + r][tx] = W[(k0 + ty + r) * D_ + n0 + tx];
    __syncthreads();
    #pragma unroll
    for (int r = 0; r < 32; r += 8) {
        float v = t[tx][ty + r];
        __nv_bfloat16 hh = __float2bfloat16(v);
        __nv_bfloat16 ll = __float2bfloat16(v - __bfloat162float(hh));
        d_Whi[which][(n0 + ty + r) * D_ + k0 + tx] = hh;
        d_Wlo[which][(n0 + ty + r) * D_ + k0 + tx] = ll;
    }
}

// ---------------------------------------------------------------------------
// Fused projection GEMMs on mma.sync, hi/lo 3-term, 3-stage cp.async pipeline,
// swizzled 64B smem rows, ONE barrier per K-chunk.
// grid = (6, 64, 3), which = blockIdx.z + zoff. which==5 only y==0/32.
// ---------------------------------------------------------------------------
#define GTILE 8192                 // 128 rows x 64B, swizzled
#define GSTAGE (4 * GTILE)         // 4 operands per stage
#define GEMM_DYN (3 * GSTAGE)      // 98304

__global__ __launch_bounds__(256, 2) void gemm_kernel(
    const float* __restrict__ bq,  const float* __restrict__ bk,
    const float* __restrict__ bv,  const float* __restrict__ bkg,
    const float* __restrict__ bvg, const float* __restrict__ bqg,
    int zoff)
{
    const int which = blockIdx.z + zoff;
    if (which == 5 && blockIdx.y != 0 && blockIdx.y != 32) return;
    extern __shared__ char smraw[];
    const uint32_t sb = smem_u32(smraw);
    const int tid = threadIdx.x, wid = tid >> 5, lane = tid & 31;
    const int mw = wid & 3, nw = wid >> 2;
    const int n0 = blockIdx.x * 128;
    const int m0 = blockIdx.y * 128;
    const float* bias = (which == 0) ? bq : (which == 1) ? bk : (which == 2) ? bv
                       : (which == 3) ? bkg : (which == 4) ? bvg : bqg;
    const __nv_bfloat16* __restrict__ Ahi = d_Ahi;
    const __nv_bfloat16* __restrict__ Alo = d_Alo;
    const __nv_bfloat16* __restrict__ Whi = d_Whi[which];
    const __nv_bfloat16* __restrict__ Wlo = d_Wlo[which];

    float acc[2][8][4];
    #pragma unroll
    for (int mt = 0; mt < 2; mt++)
        #pragma unroll
        for (int nt = 0; nt < 8; nt++)
            #pragma unroll
            for (int r = 0; r < 4; r++) acc[mt][nt][r] = 0.f;

    const int lrow = tid >> 2, lch = tid & 3;     // 64 rows x 4 segs
    const int lrow2 = lrow + 64;
    const uint32_t o1 = SWZ64(lrow, lch), o2 = SWZ64(lrow2, lch);

    auto load_chunk = [&](int buf, int k0) {
        uint32_t base = sb + buf * GSTAGE;
        CPA16(base + o1, &Ahi[(m0 + lrow) * D_ + k0 + lch * 8]);
        CPA16(base + o2, &Ahi[(m0 + lrow2) * D_ + k0 + lch * 8]);
        base += GTILE;
        CPA16(base + o1, &Alo[(m0 + lrow) * D_ + k0 + lch * 8]);
        CPA16(base + o2, &Alo[(m0 + lrow2) * D_ + k0 + lch * 8]);
        base += GTILE;
        CPA16(base + o1, &Whi[(n0 + lrow) * D_ + k0 + lch * 8]);
        CPA16(base + o2, &Whi[(n0 + lrow2) * D_ + k0 + lch * 8]);
        base += GTILE;
        CPA16(base + o1, &Wlo[(n0 + lrow) * D_ + k0 + lch * 8]);
        CPA16(base + o2, &Wlo[(n0 + lrow2) * D_ + k0 + lch * 8]);
        CPA_COMMIT();
    };

    load_chunk(0, 0);
    load_chunk(1, 32);

    int cur = 0;
    #pragma unroll 1
    for (int c = 0; c < 24; c++) {
        if (c == 23) CPA_WAIT0(); else CPA_WAIT1();
        __syncthreads();
        if (c + 2 < 24) {
            int nxt = cur + 2; if (nxt >= 3) nxt -= 3;
            load_chunk(nxt, (c + 2) * 32);
        }

        const uint32_t aBase  = sb + cur * GSTAGE;
        const uint32_t alBase = aBase + GTILE;
        const uint32_t bBase  = aBase + 2 * GTILE;
        const uint32_t blBase = aBase + 3 * GTILE;

        #pragma unroll
        for (int ks = 0; ks < 2; ks++) {
            uint32_t ahi[2][4], alo[2][4];
            const int aseg = ks * 2 + ((lane >> 4) & 1);
            #pragma unroll
            for (int mt = 0; mt < 2; mt++) {
                int row = mw * 32 + mt * 16 + (lane & 15);
                LDM4(ahi[mt], aBase + SWZ64(row, aseg));
                LDM4(alo[mt], alBase + SWZ64(row, aseg));
            }
            const int bseg = ks * 2 + ((lane >> 3) & 1);
            #pragma unroll
            for (int nh = 0; nh < 2; nh++) {
                uint32_t bhi[2][4], blo[2][4];
                #pragma unroll
                for (int q = 0; q < 2; q++) {
                    int row = nw * 64 + nh * 32 + q * 16 + (lane & 7) + ((lane >> 4) << 3);
                    LDM4(bhi[q], bBase + SWZ64(row, bseg));
                    LDM4(blo[q], blBase + SWZ64(row, bseg));
                }
                #pragma unroll
                for (int mt = 0; mt < 2; mt++)
                    #pragma unroll
                    for (int q = 0; q < 2; q++)
                        #pragma unroll
                        for (int p = 0; p < 2; p++) {
                            int nt = nh * 4 + q * 2 + p;
                            MMA16816(acc[mt][nt], ahi[mt], bhi[q][p*2], bhi[q][p*2+1]);
                            MMA16816(acc[mt][nt], ahi[mt], blo[q][p*2], blo[q][p*2+1]);
                            MMA16816(acc[mt][nt], alo[mt], bhi[q][p*2], bhi[q][p*2+1]);
                        }
            }
        }
        cur++; if (cur >= 3) cur -= 3;
    }

    // Epilogue: bf16 hi/lo split stores
    const int g = lane >> 2, tg = lane & 3;
    #pragma unroll
    for (int mt = 0; mt < 2; mt++)
        #pragma unroll
        for (int half = 0; half < 2; half++) {
            int m = m0 + mw * 32 + mt * 16 + g + half * 8;
            int b = m >> 12, s = m & 4095;
            #pragma unroll
            for (int nt = 0; nt < 8; nt++) {
                int n = n0 + nw * 64 + nt * 8 + tg * 2;
                float v0 = acc[mt][nt][half * 2 + 0] + bias[n];
                float v1 = acc[mt][nt][half * 2 + 1] + bias[n + 1];
                int h = n >> 6, hd = n & 63;
                if (which == 0 || which == 5) { v0 *= SCALE_; v1 *= SCALE_; }
                if (which == 5 && s >= G_) continue;
                __nv_bfloat16 h0 = __float2bfloat16(v0);
                __nv_bfloat16 h1 = __float2bfloat16(v1);
                __nv_bfloat16 l0 = __float2bfloat16(v0 - __bfloat162float(h0));
                __nv_bfloat16 l1 = __float2bfloat16(v1 - __bfloat162float(h1));
                __nv_bfloat162 hp; hp.x = h0; hp.y = h1;
                __nv_bfloat162 lp; lp.x = l0; lp.y = l1;
                size_t bidx = ((size_t)(b * H_ + h) * S_ + s) * HD_ + hd;
                switch (which) {
                    case 0:
                        *(__nv_bfloat162*)&d_Qhi[bidx] = hp;
                        *(__nv_bfloat162*)&d_Qlo[bidx] = lp; break;
                    case 1:
                        *(__nv_bfloat162*)&d_Khi[bidx] = hp;
                        *(__nv_bfloat162*)&d_Klo[bidx] = lp; break;
                    case 2:
                        *(__nv_bfloat162*)&d_Vhi[bidx] = hp;
                        *(__nv_bfloat162*)&d_Vlo[bidx] = lp; break;
                    case 3:
                        *(__nv_bfloat162*)&d_Kghi[bidx] = hp;
                        *(__nv_bfloat162*)&d_Kglo[bidx] = lp; break;
                    case 4:
                        *(__nv_bfloat162*)&d_Vghi[bidx] = hp;
                        *(__nv_bfloat162*)&d_Vglo[bidx] = lp; break;
                    default: {
                        size_t qidx = ((size_t)(b * H_ + h) * G_ + s) * HD_ + hd;
                        *(__nv_bfloat162*)&d_qghi[qidx] = hp;
                        *(__nv_bfloat162*)&d_qglo[qidx] = lp; break;
                    }
                }
            }
        }
}

// ---------------------------------------------------------------------------
// Global attention on mma.sync (unchanged; 21 us).
// ---------------------------------------------------------------------------
__global__ __launch_bounds__(256, 2) void gattn_mma_kernel()
{
    __shared__ __align__(16) char kh_sm[16384];
    __shared__ __align__(16) char kl_sm[16384];
    __shared__ __align__(16) char vh_sm[16384];
    __shared__ __align__(16) char vl_sm[16384];
    const uint32_t sKhi = smem_u32(kh_sm), sKlo = smem_u32(kl_sm);
    const uint32_t sVhi = smem_u32(vh_sm), sVlo = smem_u32(vl_sm);
    const int tid = threadIdx.x, wid = tid >> 5, lane = tid & 31;
    const int sp = blockIdx.x, h = blockIdx.y, b = blockIdx.z;
    const int bh = b * H_ + h;
    const int mw = wid & 1, kw = wid >> 1;
    const int g = lane >> 2, tg = lane & 3;

    uint32_t qhi[4][4], qlo[4][4];
    {
        const __nv_bfloat16* Qh = &d_qghi[((size_t)bh * G_ + mw * 16) * 64];
        const __nv_bfloat16* Ql = &d_qglo[((size_t)bh * G_ + mw * 16) * 64];
        #pragma unroll
        for (int ks = 0; ks < 4; ks++) {
            int c0 = ks * 16 + tg * 2;
            qhi[ks][0] = *(const uint32_t*)&Qh[g * 64 + c0];
            qhi[ks][1] = *(const uint32_t*)&Qh[(g + 8) * 64 + c0];
            qhi[ks][2] = *(const uint32_t*)&Qh[g * 64 + c0 + 8];
            qhi[ks][3] = *(const uint32_t*)&Qh[(g + 8) * 64 + c0 + 8];
            qlo[ks][0] = *(const uint32_t*)&Ql[g * 64 + c0];
            qlo[ks][1] = *(const uint32_t*)&Ql[(g + 8) * 64 + c0];
            qlo[ks][2] = *(const uint32_t*)&Ql[g * 64 + c0 + 8];
            qlo[ks][3] = *(const uint32_t*)&Ql[(g + 8) * 64 + c0 + 8];
        }
    }

    float oacc[8][4];
    #pragma unroll
    for (int i = 0; i < 8; i++)
        #pragma unroll
        for (int r = 0; r < 4; r++) oacc[i][r] = 0.f;
    float lsum0 = 0.f, lsum1 = 0.f;

    #pragma unroll 1
    for (int ch = 0; ch < 4; ch++) {
        __syncthreads();
        #pragma unroll
        for (int r = 0; r < 4; r++) {
            int idx = tid + r * 256;
            int row = idx >> 3, seg = idx & 7;
            uint32_t off = row * 128 + ((seg ^ (row & 7)) * 16);
            size_t src = ((size_t)bh * S_ + sp * 512 + ch * 128 + row) * 64 + seg * 8;
            CPA16(sKhi + off, &d_Kghi[src]);
            CPA16(sKlo + off, &d_Kglo[src]);
            CPA16(sVhi + off, &d_Vghi[src]);
            CPA16(sVlo + off, &d_Vglo[src]);
        }
        CPA_COMMIT(); CPA_WAIT0();
        __syncthreads();

        const int kb = kw * 32;
        float sc[4][4];
        #pragma unroll
        for (int i = 0; i < 4; i++)
            #pragma unroll
            for (int r = 0; r < 4; r++) sc[i][r] = 0.f;

        #pragma unroll
        for (int ks = 0; ks < 4; ks++) {
            uint32_t kh[2][4], kl[2][4];
            #pragma unroll
            for (int q2 = 0; q2 < 2; q2++) {
                int row = kb + q2 * 16 + (lane & 7) + ((lane >> 4) << 3);
                int seg = ks * 2 + ((lane >> 3) & 1);
                uint32_t addr = row * 128 + ((seg ^ (row & 7)) * 16);
                LDM4(kh[q2], sKhi + addr);
                LDM4(kl[q2], sKlo + addr);
            }
            #pragma unroll
            for (int q2 = 0; q2 < 2; q2++)
                #pragma unroll
                for (int p = 0; p < 2; p++) {
                    int nt = q2 * 2 + p;
                    MMA16816(sc[nt], qhi[ks], kh[q2][p*2], kh[q2][p*2+1]);
                    MMA16816(sc[nt], qhi[ks], kl[q2][p*2], kl[q2][p*2+1]);
                    MMA16816(sc[nt], qlo[ks], kh[q2][p*2], kh[q2][p*2+1]);
                }
        }

        uint32_t pah[2][4], pal[2][4];
        #pragma unroll
        for (int nt = 0; nt < 4; nt++) {
            float p00 = __expf(sc[nt][0]), p01 = __expf(sc[nt][1]);
            float p10 = __expf(sc[nt][2]), p11 = __expf(sc[nt][3]);
            lsum0 += p00 + p01;
            lsum1 += p10 + p11;
            __nv_bfloat16 h00 = __float2bfloat16(p00);
            __nv_bfloat16 h01 = __float2bfloat16(p01);
            __nv_bfloat16 h10 = __float2bfloat16(p10);
            __nv_bfloat16 h11 = __float2bfloat16(p11);
            __nv_bfloat162 hp0; hp0.x = h00; hp0.y = h01;
            __nv_bfloat162 hp1; hp1.x = h10; hp1.y = h11;
            __nv_bfloat162 lp0;
            lp0.x = __float2bfloat16(p00 - __bfloat162float(h00));
            lp0.y = __float2bfloat16(p01 - __bfloat162float(h01));
            __nv_bfloat162 lp1;
            lp1.x = __float2bfloat16(p10 - __bfloat162float(h10));
            lp1.y = __float2bfloat16(p11 - __bfloat162float(h11));
            pah[nt >> 1][(nt & 1) * 2 + 0] = *(uint32_t*)&hp0;
            pah[nt >> 1][(nt & 1) * 2 + 1] = *(uint32_t*)&hp1;
            pal[nt >> 1][(nt & 1) * 2 + 0] = *(uint32_t*)&lp0;
            pal[nt >> 1][(nt & 1) * 2 + 1] = *(uint32_t*)&lp1;
        }

        #pragma unroll
        for (int ksp = 0; ksp < 2; ksp++) {
            #pragma unroll
            for (int dg = 0; dg < 4; dg++) {
                uint32_t vh[4], vl[4];
                int row = kb + ksp * 16 + (lane & 15);
                int seg = dg * 2 + (lane >> 4);
                uint32_t addr = row * 128 + ((seg ^ (row & 7)) * 16);
                LDM4T(vh, sVhi + addr);
                LDM4T(vl, sVlo + addr);
                MMA16816(oacc[dg * 2 + 0], pah[ksp], vh[0], vh[1]);
                MMA16816(oacc[dg * 2 + 0], pal[ksp], vh[0], vh[1]);
                MMA16816(oacc[dg * 2 + 0], pah[ksp], vl[0], vl[1]);
                MMA16816(oacc[dg * 2 + 1], pah[ksp], vh[2], vh[3]);
                MMA16816(oacc[dg * 2 + 1], pal[ksp], vh[2], vh[3]);
                MMA16816(oacc[dg * 2 + 1], pah[ksp], vl[2], vl[3]);
            }
        }
    }

    lsum0 += __shfl_xor_sync(0xffffffffu, lsum0, 1);
    lsum0 += __shfl_xor_sync(0xffffffffu, lsum0, 2);
    lsum1 += __shfl_xor_sync(0xffffffffu, lsum1, 1);
    lsum1 += __shfl_xor_sync(0xffffffffu, lsum1, 2);
    const int part = sp * 4 + kw;
    const int r0 = mw * 16 + g, r1 = r0 + 8;
    if (tg == 0) {
        d_lpart[((size_t)bh * NSPLITG + part) * G_ + r0] = lsum0;
        d_lpart[((size_t)bh * NSPLITG + part) * G_ + r1] = lsum1;
    }
    float* a0 = &d_accpart[(((size_t)bh * NSPLITG + part) * G_ + r0) * HD_];
    float* a1 = &d_accpart[(((size_t)bh * NSPLITG + part) * G_ + r1) * HD_];
    #pragma unroll
    for (int nt = 0; nt < 8; nt++) {
        float2 w0; w0.x = oacc[nt][0]; w0.y = oacc[nt][1];
        float2 w1; w1.x = oacc[nt][2]; w1.y = oacc[nt][3];
        *(float2*)&a0[nt * 8 + tg * 2] = w0;
        *(float2*)&a1[nt * 8 + tg * 2] = w1;
    }
}

__global__ __launch_bounds__(64) void gattn_combine_kernel(float* __restrict__ out)
{
    const int idx = blockIdx.x;
    const int bh = idx >> 5;
    const int g = idx & 31;
    const int b = bh / H_, h = bh % H_;
    const int d = threadIdx.x;
    float l = 0.f, a = 0.f;
    #pragma unroll
    for (int sp = 0; sp < NSPLITG; sp++) {
        l += d_lpart[((size_t)bh * NSPLITG + sp) * G_ + g];
        a += d_accpart[(((size_t)bh * NSPLITG + sp) * G_ + g) * HD_ + d];
    }
    out[(b * S_ + g) * D_ + h * HD_ + d] = a / l;
}

// ---------------------------------------------------------------------------
// Band + global-key attention: 3-stage cp.async pipeline, one barrier/tile,
// warp-uniform SKIP of fully-masked segments, unmasked fast path, hoisted
// per-thread mask bounds.
// ---------------------------------------------------------------------------
#define BTILE 8192
#define BSTAGE (4 * BTILE)
#define BAND_DYN (3 * BSTAGE)     // 98304

__global__ __launch_bounds__(256, 2) void band_mma_kernel(float* __restrict__ out)
{
    extern __shared__ char bsm[];
    const uint32_t sb = smem_u32(bsm);
    const int tid = threadIdx.x, wid = tid >> 5, lane = tid & 31;
    const int c = blockIdx.x >> 1, qh = blockIdx.x & 1;
    const int h = blockIdx.y, b = blockIdx.z;
    const int bh = b * H_ + h;
    const int row0 = c * W_ + qh * 128;
    const int wr = wid * 16;
    const int g = lane >> 2, tg = lane & 3;
    const int pqr0 = qh * 128 + wr + g;
    const int pqr1 = pqr0 + 8;
    const int wbase = qh * 128 + wr;

    const int eklo = W_ - c * W_;
    const int ekhi = S_ - 1 + W_ - c * W_;
    const int lo0 = max(pqr0, eklo), hi0 = min(pqr0 + 2 * W_, ekhi);
    const int lo1 = max(pqr1, eklo), hi1 = min(pqr1 + 2 * W_, ekhi);
    const int wlo = max(wbase, eklo);
    const int whi = min(wbase + 15 + 2 * W_, ekhi);

    int tlist[11], ntl = 0;
    tlist[ntl++] = 0;
    #pragma unroll
    for (int t = 1; t < 11; t++) {
        int ebase = qh * 128 + (t - 1) * 64;
        int kl = c * W_ + ebase - W_;
        if (kl + 63 >= 0 && kl < S_) tlist[ntl++] = t;
    }

    uint32_t qhi[4][4], qlo[4][4];
    {
        const __nv_bfloat16* Qh = &d_Qhi[((size_t)bh * S_ + row0 + wr) * 64];
        const __nv_bfloat16* Ql = &d_Qlo[((size_t)bh * S_ + row0 + wr) * 64];
        #pragma unroll
        for (int ks = 0; ks < 4; ks++) {
            int c0 = ks * 16 + tg * 2;
            qhi[ks][0] = *(const uint32_t*)&Qh[g * 64 + c0];
            qhi[ks][1] = *(const uint32_t*)&Qh[(g + 8) * 64 + c0];
            qhi[ks][2] = *(const uint32_t*)&Qh[g * 64 + c0 + 8];
            qhi[ks][3] = *(const uint32_t*)&Qh[(g + 8) * 64 + c0 + 8];
            qlo[ks][0] = *(const uint32_t*)&Ql[g * 64 + c0];
            qlo[ks][1] = *(const uint32_t*)&Ql[(g + 8) * 64 + c0];
            qlo[ks][2] = *(const uint32_t*)&Ql[g * 64 + c0 + 8];
            qlo[ks][3] = *(const uint32_t*)&Ql[(g + 8) * 64 + c0 + 8];
        }
    }

    float oacc[8][4];
    #pragma unroll
    for (int i = 0; i < 8; i++)
        #pragma unroll
        for (int r = 0; r < 4; r++) oacc[i][r] = 0.f;
    float lsum0 = 0.f, lsum1 = 0.f;

    const int lrowA = tid >> 3, lseg = tid & 7;
    const int lrowB = lrowA + 32;

    auto load_tile = [&](int stg, int t) {
        uint32_t base = sb + stg * BSTAGE;
        #pragma unroll
        for (int r = 0; r < 2; r++) {
            int row = r ? lrowB : lrowA;
            int ka = (t == 0) ? row
                              : (c * W_ + qh * 128 + (t - 1) * 64 + row - W_);
            int kr = min(max(ka, 0), S_ - 1);
            uint32_t off = row * 128 + ((lseg ^ (row & 7)) * 16);
            size_t src = ((size_t)bh * S_ + kr) * 64 + lseg * 8;
            CPA16(base + off, &d_Khi[src]);
            CPA16(base + BTILE + off, &d_Klo[src]);
            CPA16(base + 2 * BTILE + off, &d_Vhi[src]);
            CPA16(base + 3 * BTILE + off, &d_Vlo[src]);
        }
        CPA_COMMIT();
    };

    load_tile(0, tlist[0]);
    if (ntl > 1) load_tile(1, tlist[1]);

    int cur = 0;
    #pragma unroll 1
    for (int it = 0; it < ntl; it++) {
        const int t = tlist[it];
        if (it == ntl - 1) CPA_WAIT0(); else CPA_WAIT1();
        __syncthreads();
        if (it + 2 < ntl) {
            int nxt = cur + 2; if (nxt >= 3) nxt -= 3;
            load_tile(nxt, tlist[it + 2]);
        }

        const uint32_t sKhi = sb + cur * BSTAGE;
        const uint32_t sKlo = sKhi + BTILE;
        const uint32_t sVhi = sKhi + 2 * BTILE;
        const uint32_t sVlo = sKhi + 3 * BTILE;
        const int ebase = qh * 128 + (t - 1) * 64;

        const int nhalf = (t == 0) ? 1 : 2;
        for (int hf = 0; hf < nhalf; hf++) {
            const int kb = hf * 32;
            const int minE = ebase + kb, maxE = minE + 31;

            if (t != 0 && (maxE < wlo || minE > whi)) continue;

            float sc[4][4];
            #pragma unroll
            for (int i = 0; i < 4; i++)
                #pragma unroll
                for (int r = 0; r < 4; r++) sc[i][r] = 0.f;

            #pragma unroll
            for (int ks = 0; ks < 4; ks++) {
                uint32_t kh[2][4], kl[2][4];
                #pragma unroll
                for (int q2 = 0; q2 < 2; q2++) {
                    int row = kb + q2 * 16 + (lane & 7) + ((lane >> 4) << 3);
                    int seg = ks * 2 + ((lane >> 3) & 1);
                    uint32_t addr = row * 128 + ((seg ^ (row & 7)) * 16);
                    LDM4(kh[q2], sKhi + addr);
                    LDM4(kl[q2], sKlo + addr);
                }
                #pragma unroll
                for (int q2 = 0; q2 < 2; q2++)
                    #pragma unroll
                    for (int p = 0; p < 2; p++) {
                        int nt = q2 * 2 + p;
                        MMA16816(sc[nt], qhi[ks], kh[q2][p*2], kh[q2][p*2+1]);
                        MMA16816(sc[nt], qhi[ks], kl[q2][p*2], kl[q2][p*2+1]);
                        MMA16816(sc[nt], qlo[ks], kh[q2][p*2], kh[q2][p*2+1]);
                    }
            }

            const bool full = (t != 0) &&
                (minE >= wbase + 15) && (maxE <= wbase + 2 * W_) &&
                (minE >= eklo) && (maxE <= ekhi);

            uint32_t pah[2][4], pal[2][4];
            if (t == 0 || full) {
                #pragma unroll
                for (int nt = 0; nt < 4; nt++) {
                    float p00 = __expf(sc[nt][0]), p01 = __expf(sc[nt][1]);
                    float p10 = __expf(sc[nt][2]), p11 = __expf(sc[nt][3]);
                    lsum0 += p00 + p01;
                    lsum1 += p10 + p11;
                    __nv_bfloat16 h00 = __float2bfloat16(p00);
                    __nv_bfloat16 h01 = __float2bfloat16(p01);
                    __nv_bfloat16 h10 = __float2bfloat16(p10);
                    __nv_bfloat16 h11 = __float2bfloat16(p11);
                    __nv_bfloat162 hp0; hp0.x = h00; hp0.y = h01;
                    __nv_bfloat162 hp1; hp1.x = h10; hp1.y = h11;
                    __nv_bfloat162 lp0;
                    lp0.x = __float2bfloat16(p00 - __bfloat162float(h00));
                    lp0.y = __float2bfloat16(p01 - __bfloat162float(h01));
                    __nv_bfloat162 lp1;
                    lp1.x = __float2bfloat16(p10 - __bfloat162float(h10));
                    lp1.y = __float2bfloat16(p11 - __bfloat162float(h11));
                    pah[nt >> 1][(nt & 1) * 2 + 0] = *(uint32_t*)&hp0;
                    pah[nt >> 1][(nt & 1) * 2 + 1] = *(uint32_t*)&hp1;
                    pal[nt >> 1][(nt & 1) * 2 + 0] = *(uint32_t*)&lp0;
                    pal[nt >> 1][(nt & 1) * 2 + 1] = *(uint32_t*)&lp1;
                }
            } else {
                #pragma unroll
                for (int nt = 0; nt < 4; nt++) {
                    int e0 = ebase + kb + nt * 8 + tg * 2;
                    int e1 = e0 + 1;
                    float p00 = (e0 >= lo0 && e0 <= hi0) ? __expf(sc[nt][0]) : 0.f;
                    float p01 = (e1 >= lo0 && e1 <= hi0) ? __expf(sc[nt][1]) : 0.f;
                    float p10 = (e0 >= lo1 && e0 <= hi1) ? __expf(sc[nt][2]) : 0.f;
                    float p11 = (e1 >= lo1 && e1 <= hi1) ? __expf(sc[nt][3]) : 0.f;
                    lsum0 += p00 + p01;
                    lsum1 += p10 + p11;
                    __nv_bfloat16 h00 = __float2bfloat16(p00);
                    __nv_bfloat16 h01 = __float2bfloat16(p01);
                    __nv_bfloat16 h10 = __float2bfloat16(p10);
                    __nv_bfloat16 h11 = __float2bfloat16(p11);
                    __nv_bfloat162 hp0; hp0.x = h00; hp0.y = h01;
                    __nv_bfloat162 hp1; hp1.x = h10; hp1.y = h11;
                    __nv_bfloat162 lp0;
                    lp0.x = __float2bfloat16(p00 - __bfloat162float(h00));
                    lp0.y = __float2bfloat16(p01 - __bfloat162float(h01));
                    __nv_bfloat162 lp1;
                    lp1.x = __float2bfloat16(p10 - __bfloat162float(h10));
                    lp1.y = __float2bfloat16(p11 - __bfloat162float(h11));
                    pah[nt >> 1][(nt & 1) * 2 + 0] = *(uint32_t*)&hp0;
                    pah[nt >> 1][(nt & 1) * 2 + 1] = *(uint32_t*)&hp1;
                    pal[nt >> 1][(nt & 1) * 2 + 0] = *(uint32_t*)&lp0;
                    pal[nt >> 1][(nt & 1) * 2 + 1] = *(uint32_t*)&lp1;
                }
            }

            #pragma unroll
            for (int ksp = 0; ksp < 2; ksp++) {
                #pragma unroll
                for (int dg = 0; dg < 4; dg++) {
                    uint32_t vh[4], vl[4];
                    int row = kb + ksp * 16 + (lane & 15);
                    int seg = dg * 2 + (lane >> 4);
                    uint32_t addr = row * 128 + ((seg ^ (row & 7)) * 16);
                    LDM4T(vh, sVhi + addr);
                    LDM4T(vl, sVlo + addr);
                    MMA16816(oacc[dg * 2 + 0], pah[ksp], vh[0], vh[1]);
                    MMA16816(oacc[dg * 2 + 0], pal[ksp], vh[0], vh[1]);
                    MMA16816(oacc[dg * 2 + 0], pah[ksp], vl[0], vl[1]);
                    MMA16816(oacc[dg * 2 + 1], pah[ksp], vh[2], vh[3]);
                    MMA16816(oacc[dg * 2 + 1], pal[ksp], vh[2], vh[3]);
                    MMA16816(oacc[dg * 2 + 1], pah[ksp], vl[2], vl[3]);
                }
            }
        }
        cur++; if (cur >= 3) cur -= 3;
    }

    lsum0 += __shfl_xor_sync(0xffffffffu, lsum0, 1);
    lsum0 += __shfl_xor_sync(0xffffffffu, lsum0, 2);
    lsum1 += __shfl_xor_sync(0xffffffffu, lsum1, 1);
    lsum1 += __shfl_xor_sync(0xffffffffu, lsum1, 2);
    float inv0 = 1.f / lsum0, inv1 = 1.f / lsum1;
    float* o0 = &out[(size_t)(b * S_ + row0 + wr + g) * D_ + h * 64];
    float* o1 = o0 + 8 * D_;
    #pragma unroll
    for (int nt = 0; nt < 8; nt++) {
        float2 w0; w0.x = oacc[nt][0] * inv0; w0.y = oacc[nt][1] * inv0;
        float2 w1; w1.x = oacc[nt][2] * inv1; w1.y = oacc[nt][3] * inv1;
        *(float2*)&o0[nt * 8 + tg * 2] = w0;
        *(float2*)&o1[nt * 8 + tg * 2] = w1;
    }
}

// ---------------------------------------------------------------------------
extern "C" void kernel_launch(void* const* d_in, const int* in_sizes, int n_in,
                              void* d_out, int out_size)
{
    const float* hidden = (const float*)d_in[0];
    const float* Wq  = (const float*)d_in[1];
    const float* bq  = (const float*)d_in[2];
    const float* Wk  = (const float*)d_in[3];
    const float* bk  = (const float*)d_in[4];
    const float* Wv  = (const float*)d_in[5];
    const float* bv  = (const float*)d_in[6];
    const float* Wqg = (const float*)d_in[7];
    const float* bqg = (const float*)d_in[8];
    const float* Wkg = (const float*)d_in[9];
    const float* bkg = (const float*)d_in[10];
    const float* Wvg = (const float*)d_in[11];
    const float* bvg = (const float*)d_in[12];
    float* out = (float*)d_out;

    static cudaStream_t s2;
    static cudaEvent_t evConv, evS2;
    static int configured = 0;
    if (!configured) {
        cudaFuncSetAttribute(gemm_kernel, cudaFuncAttributeMaxDynamicSharedMemorySize, GEMM_DYN);
        cudaFuncSetAttribute(band_mma_kernel, cudaFuncAttributeMaxDynamicSharedMemorySize, BAND_DYN);
        cudaStreamCreateWithFlags(&s2, cudaStreamNonBlocking);
        cudaEventCreateWithFlags(&evConv, cudaEventDisableTiming);
        cudaEventCreateWithFlags(&evS2, cudaEventDisableTiming);
        configured = 1;
    }

    // stream0: prepasses
    convA_kernel<<<(B_*S_*D_)/1024, 256>>>(hidden);
    convW_kernel<<<dim3(24, 24, 6), dim3(32, 8)>>>(Wq, Wk, Wv, Wkg, Wvg, Wqg);
    cudaEventRecord(evConv, 0);

    // stream2: global-path projections + global attention (forked)
    cudaStreamWaitEvent(s2, evConv, 0);
    gemm_kernel<<<dim3(6, 64, 3), 256, GEMM_DYN, s2>>>(bq, bk, bv, bkg, bvg, bqg, 3);
    gattn_mma_kernel<<<dim3(8, H_, B_), 256, 0, s2>>>();
    cudaEventRecord(evS2, s2);

    // stream0: band-path projections + band attention
    gemm_kernel<<<dim3(6, 64, 3), 256, GEMM_DYN>>>(bq, bk, bv, bkg, bvg, bqg, 0);
    band_mma_kernel<<<dim3(NC_ * 2, H_, B_), 256, BAND_DYN>>>(out);

    // join, then combine (must follow band's writes to out rows < G)
    cudaStreamWaitEvent(0, evS2, 0);
    gattn_combine_kernel<<<B_ * H_ * G_, 64>>>(out);
}